// round 5
// baseline (speedup 1.0000x reference)
#include <cuda_runtime.h>
#include <cstdint>

// Problem constants
#define B_      8
#define D_      512
#define H_      8
#define HD_     64
#define L_NS_   64
#define L_S_    2048
#define L_TOT   2112
#define LS_OUT  512
#define LQ_     576
#define LQPAD   640    // padded q rows (5 tiles of 128); rows 576-639 stay zero

// Scratch (allocation-free: device globals, zero-initialized at module load)
__device__ float g_K[B_ * L_TOT * D_];
__device__ float g_V[B_ * L_TOT * D_];
__device__ float g_Q[B_ * LQPAD * D_];
__device__ float g_A[B_ * LQPAD * D_];
__device__ float g_Part[4 * 64 * B_ * D_];

// ---------------------------------------------------------------------------
// Helpers
// ---------------------------------------------------------------------------
__device__ __forceinline__ uint32_t smem_u32(const void* p) {
    uint32_t a;
    asm("{ .reg .u64 t; cvta.to.shared.u64 t, %1; cvt.u32.u64 %0, t; }" : "=r"(a) : "l"(p));
    return a;
}
__device__ __forceinline__ uint32_t cvt_tf32(float x) {
    uint32_t u; asm("cvt.rna.tf32.f32 %0, %1;" : "=r"(u) : "f"(x)); return u;
}
__device__ __forceinline__ float uf(uint32_t u) { return __uint_as_float(u); }
__device__ __forceinline__ uint32_t fu(float f) { return __float_as_uint(f); }

__device__ __forceinline__ void mma8(float4& d, const uint32_t a[4], uint32_t b0, uint32_t b1) {
    asm volatile(
        "mma.sync.aligned.m16n8k8.row.col.f32.tf32.tf32.f32 "
        "{%0,%1,%2,%3}, {%4,%5,%6,%7}, {%8,%9}, {%0,%1,%2,%3};"
        : "+f"(d.x), "+f"(d.y), "+f"(d.z), "+f"(d.w)
        : "r"(a[0]), "r"(a[1]), "r"(a[2]), "r"(a[3]), "r"(b0), "r"(b1));
}
__device__ __forceinline__ void cp16(uint32_t dst, const void* src) {
    asm volatile("cp.async.cg.shared.global [%0], [%1], 16;" :: "r"(dst), "l"(src));
}
#define CP_COMMIT() asm volatile("cp.async.commit_group;" ::: "memory")
#define CP_WAIT1()  asm volatile("cp.async.wait_group 1;" ::: "memory")

// ---------------------------------------------------------------------------
// Dense projection GEMM, tf32 mma.sync, 3-stage cp.async pipeline.
// C[crow(m)][n] = sum_k A[arow(m)][k] * W[k][n] + bias[n],  K = N = 512.
// 256 threads = 8 warps (2m x 4n), CTA 128x128, BK=16, warp tile 64x32.
// ---------------------------------------------------------------------------
template <int MODE> __device__ __forceinline__ int arow_of(int mi) {
    if (MODE == 0) return (mi >> 11) * L_TOT + (mi & 2047);
    if (MODE == 1) return (mi >> 9) * L_TOT + 1536 + (mi & 511);
    return ((unsigned)mi / 576) * LQPAD + ((unsigned)mi % 576);   // out proj reads padded g_A
}
template <int MODE> __device__ __forceinline__ int crow_of(int mi) {
    if (MODE == 0) return (mi >> 11) * L_TOT + (mi & 2047);
    if (MODE == 1) return (mi >> 9) * LQPAD + (mi & 511);
    return mi;
}

#define PJ_AS 2560            // floats per A stage: 128 rows x stride 20
#define PJ_WS 2176            // floats per W stage: 16 rows x stride 136 (k-major)
#define PJ_SMEM (3 * (PJ_AS + PJ_WS) * 4)

template <int MODE>
__global__ __launch_bounds__(256, 2)
void proj_mma(const float* __restrict__ A, const float* __restrict__ W,
              const float* __restrict__ bias, float* __restrict__ C) {
    extern __shared__ float sm[];
    float* As = sm;
    float* Ws = sm + 3 * PJ_AS;
    const uint32_t as_u = smem_u32(As), ws_u = smem_u32(Ws);

    const int tid = threadIdx.x, lane = tid & 31;
    const int warp = tid >> 5, wm = warp >> 2, wn = warp & 3;
    const int g = lane >> 2, t4 = lane & 3;
    const int m0 = blockIdx.x * 128, n0 = blockIdx.y * 128;

    // Loader indices
    const int lr = tid >> 2, lk = (tid & 3) * 4;       // A: rows lr, lr+64; 16B at lk
    const float* pA0 = A + (size_t)arow_of<MODE>(m0 + lr) * D_ + lk;
    const float* pA1 = A + (size_t)arow_of<MODE>(m0 + 64 + lr) * D_ + lk;
    const int kr0 = tid >> 5, kr1 = kr0 + 8;           // W rows
    const int nn = (tid & 31) * 4;
    const float* pW = W + n0;

    auto issue = [&](int c, int s) {
        const int k0 = c * 16;
        uint32_t ad = as_u + (uint32_t)(s * PJ_AS) * 4;
        cp16(ad + (uint32_t)(lr * 20 + lk) * 4, pA0 + k0);
        cp16(ad + (uint32_t)((lr + 64) * 20 + lk) * 4, pA1 + k0);
        uint32_t wd = ws_u + (uint32_t)(s * PJ_WS) * 4;
        cp16(wd + (uint32_t)(kr0 * 136 + nn) * 4, pW + (size_t)(k0 + kr0) * D_ + nn);
        cp16(wd + (uint32_t)(kr1 * 136 + nn) * 4, pW + (size_t)(k0 + kr1) * D_ + nn);
    };

    float4 acc[4][4];
#pragma unroll
    for (int i = 0; i < 4; ++i)
#pragma unroll
        for (int j = 0; j < 4; ++j) acc[i][j] = make_float4(0.f, 0.f, 0.f, 0.f);

    issue(0, 0); CP_COMMIT();
    issue(1, 1); CP_COMMIT();

#pragma unroll 1
    for (int c = 0; c < 32; ++c) {
        const int s = c % 3;
        CP_WAIT1();
        __syncthreads();
        if (c + 2 < 32) issue(c + 2, (c + 2) % 3);
        CP_COMMIT();

        const float* as_ = As + s * PJ_AS;
        const float* ws_ = Ws + s * PJ_WS;
#pragma unroll
        for (int kc = 0; kc < 2; ++kc) {
            const int kb = kc * 8;
            uint32_t af[4][4], bf[4][2];
#pragma unroll
            for (int mi = 0; mi < 4; ++mi) {
                int row = wm * 64 + mi * 16 + g;
                af[mi][0] = cvt_tf32(as_[row * 20 + kb + t4]);
                af[mi][1] = cvt_tf32(as_[(row + 8) * 20 + kb + t4]);
                af[mi][2] = cvt_tf32(as_[row * 20 + kb + t4 + 4]);
                af[mi][3] = cvt_tf32(as_[(row + 8) * 20 + kb + t4 + 4]);
            }
#pragma unroll
            for (int ni = 0; ni < 4; ++ni) {
                int col = wn * 32 + ni * 8 + g;
                bf[ni][0] = cvt_tf32(ws_[(kb + t4) * 136 + col]);
                bf[ni][1] = cvt_tf32(ws_[(kb + t4 + 4) * 136 + col]);
            }
#pragma unroll
            for (int mi = 0; mi < 4; ++mi)
#pragma unroll
                for (int ni = 0; ni < 4; ++ni)
                    mma8(acc[mi][ni], af[mi], bf[ni][0], bf[ni][1]);
        }
    }

    // Epilogue
#pragma unroll
    for (int ni = 0; ni < 4; ++ni) {
        int col = n0 + wn * 32 + ni * 8 + 2 * t4;
        float2 bv = *(const float2*)(bias + col);
#pragma unroll
        for (int mi = 0; mi < 4; ++mi) {
            int r0 = crow_of<MODE>(m0 + wm * 64 + mi * 16 + g);
            int r1 = crow_of<MODE>(m0 + wm * 64 + mi * 16 + g + 8);
            *(float2*)(C + (size_t)r0 * D_ + col) =
                make_float2(acc[mi][ni].x + bv.x, acc[mi][ni].y + bv.y);
            *(float2*)(C + (size_t)r1 * D_ + col) =
                make_float2(acc[mi][ni].z + bv.x, acc[mi][ni].w + bv.y);
        }
    }
}

// ---------------------------------------------------------------------------
// ns projections: deterministic k-split x4 into g_Part, then reduce (+bias).
// ---------------------------------------------------------------------------
__global__ __launch_bounds__(128)
void proj_ns(const float* __restrict__ x, const float* __restrict__ nw,
             float* __restrict__ part) {
    __shared__ float xs[B_][128];
    const int n = blockIdx.x, ct = blockIdx.y, kz = blockIdx.z;
    const int tid = threadIdx.x;

    for (int t = tid; t < 256; t += 128) {
        int b = t >> 5;
        int k4 = (t & 31) << 2;
        *(float4*)&xs[b][k4] =
            *(const float4*)(x + (size_t)(b * L_TOT + L_S_ + n) * D_ + kz * 128 + k4);
    }
    __syncthreads();

    const int col = ct * 128 + tid;
    float acc[B_];
#pragma unroll
    for (int b = 0; b < B_; ++b) acc[b] = 0.f;

    const float* wp = nw + (size_t)n * D_ * D_ + (size_t)(kz * 128) * D_ + col;
#pragma unroll 8
    for (int k = 0; k < 128; ++k) {
        float w = wp[(size_t)k * D_];
#pragma unroll
        for (int b = 0; b < B_; ++b) acc[b] += xs[b][k] * w;
    }
#pragma unroll
    for (int b = 0; b < B_; ++b)
        part[(size_t)(((kz * 64 + n) * B_) + b) * D_ + col] = acc[b];
}

__global__ __launch_bounds__(512)
void ns_reduce(const float* __restrict__ part, const float* __restrict__ nb,
               float* __restrict__ out, int qmode) {
    const int n = blockIdx.x;
    const int col = threadIdx.x;
    const float bias = nb[n * D_ + col];
#pragma unroll
    for (int b = 0; b < B_; ++b) {
        float s = bias;
#pragma unroll
        for (int kz = 0; kz < 4; ++kz)
            s += part[(size_t)(((kz * 64 + n) * B_) + b) * D_ + col];
        int orow = qmode ? (b * LQPAD + LS_OUT + n) : (b * L_TOT + L_S_ + n);
        out[(size_t)orow * D_ + col] = s;
    }
}

// ---------------------------------------------------------------------------
// Flash attention, tf32 mma.sync. q-tile 128, 256 threads (8 warps), 3-stage
// cp.async K/V/pad rings. grid = (5 qtiles, 8 heads, 8 batch).
// ---------------------------------------------------------------------------
#define ATT_QS (128 * 68)     // Qs staging (fp32), aliased as Ps (tf32 bits)
#define ATT_KS (64 * 68)      // raw fp32 per stage
#define ATT_VS (64 * 72)
#define ATT_SMEM ((ATT_QS + 3 * ATT_KS + 3 * ATT_VS + 3 * 64) * 4)

__global__ __launch_bounds__(256)
void attn_mma(const float* __restrict__ Qg, const float* __restrict__ Kg,
              const float* __restrict__ Vg, const int* __restrict__ pad,
              float* __restrict__ Og) {
    extern __shared__ float sm[];
    float* Qs = sm;
    float* Ps = sm;
    float* Ks = sm + ATT_QS;
    float* Vs = Ks + 3 * ATT_KS;
    int*   padi = (int*)(Vs + 3 * ATT_VS);
    const uint32_t ks_u = smem_u32(Ks), vs_u = smem_u32(Vs), pd_u = smem_u32(padi);

    const int tid = threadIdx.x, lane = tid & 31, w = tid >> 5;
    const int g = lane >> 2, t4 = lane & 3;
    const int qt = blockIdx.x, h = blockIdx.y, b = blockIdx.z;
    const int qbase = qt * 128;
    const int nkt = min(2 * qt + 26, 33);
    const int rl0 = 16 * w + g, rl1 = rl0 + 8;

    auto issue = [&](int kt, int s) {
        if (kt >= nkt) return;
        const int kb = kt * 64;
        const float* Kb = Kg + (size_t)(b * L_TOT + kb) * D_ + h * HD_;
        const float* Vb = Vg + (size_t)(b * L_TOT + kb) * D_ + h * HD_;
#pragma unroll
        for (int p = 0; p < 4; ++p) {
            int idx = tid + p * 256;
            int j = idx >> 4, d4 = (idx & 15) * 4;
            cp16(ks_u + (uint32_t)(s * ATT_KS + j * 68 + d4) * 4, Kb + (size_t)j * D_ + d4);
            cp16(vs_u + (uint32_t)(s * ATT_VS + j * 72 + d4) * 4, Vb + (size_t)j * D_ + d4);
        }
        if (kt < 32 && tid < 16)
            cp16(pd_u + (uint32_t)(s * 64 + tid * 4) * 4, pad + b * L_S_ + kb + tid * 4);
    };

    issue(0, 0); CP_COMMIT();
    issue(1, 1); CP_COMMIT();

    // Stage Q (fp32)
#pragma unroll
    for (int p = 0; p < 8; ++p) {
        int idx = tid + p * 256;
        int row = idx >> 4, d4 = (idx & 15) * 4;
        *(float4*)&Qs[row * 68 + d4] =
            *(const float4*)(Qg + (size_t)(b * LQPAD + qbase + row) * D_ + h * HD_ + d4);
    }
    __syncthreads();

    // Extract Q fragments (scale 1/8 folded)
    uint32_t qa[8][4];
#pragma unroll
    for (int kc = 0; kc < 8; ++kc) {
        qa[kc][0] = cvt_tf32(Qs[rl0 * 68 + kc * 8 + t4] * 0.125f);
        qa[kc][1] = cvt_tf32(Qs[rl1 * 68 + kc * 8 + t4] * 0.125f);
        qa[kc][2] = cvt_tf32(Qs[rl0 * 68 + kc * 8 + t4 + 4] * 0.125f);
        qa[kc][3] = cvt_tf32(Qs[rl1 * 68 + kc * 8 + t4 + 4] * 0.125f);
    }

    float4 oacc[8];
#pragma unroll
    for (int i = 0; i < 8; ++i) oacc[i] = make_float4(0.f, 0.f, 0.f, 0.f);
    float m0v = -1e30f, m1v = -1e30f, l0 = 0.f, l1 = 0.f;

#pragma unroll 1
    for (int kt = 0; kt < nkt; ++kt) {
        const int s = kt % 3;
        CP_WAIT1();
        __syncthreads();           // stage s data visible to all; stage (kt+2)%3 free
        issue(kt + 2, (kt + 2) % 3);
        CP_COMMIT();

        const float* ks_ = Ks + s * ATT_KS;
        const float* vs_ = Vs + s * ATT_VS;
        const int*   pd_ = padi + s * 64;

        // S = Q K^T
        float4 sacc[8];
#pragma unroll
        for (int nt = 0; nt < 8; ++nt) sacc[nt] = make_float4(0.f, 0.f, 0.f, 0.f);
#pragma unroll
        for (int kc = 0; kc < 8; ++kc) {
#pragma unroll
            for (int nt = 0; nt < 8; ++nt) {
                uint32_t b0 = cvt_tf32(ks_[(nt * 8 + g) * 68 + kc * 8 + t4]);
                uint32_t b1 = cvt_tf32(ks_[(nt * 8 + g) * 68 + kc * 8 + t4 + 4]);
                mma8(sacc[nt], qa[kc], b0, b1);
            }
        }

        // Mask + online softmax
        const int moff = kt * 64 - qbase - 1536;
        const bool dopad = (kt < 32);
        float rmax0 = -1e30f, rmax1 = -1e30f;
#pragma unroll
        for (int nt = 0; nt < 8; ++nt) {
            int j0 = nt * 8 + 2 * t4, j1 = j0 + 1;
            float p0 = (dopad && pd_[j0] == 0) ? -1e30f : 0.f;
            float p1 = (dopad && pd_[j1] == 0) ? -1e30f : 0.f;
            sacc[nt].x += p0; sacc[nt].y += p1;
            sacc[nt].z += p0; sacc[nt].w += p1;
            if (moff > -64) {
                if (j0 + moff > rl0) sacc[nt].x = -1e30f;
                if (j1 + moff > rl0) sacc[nt].y = -1e30f;
                if (j0 + moff > rl1) sacc[nt].z = -1e30f;
                if (j1 + moff > rl1) sacc[nt].w = -1e30f;
            }
            rmax0 = fmaxf(rmax0, fmaxf(sacc[nt].x, sacc[nt].y));
            rmax1 = fmaxf(rmax1, fmaxf(sacc[nt].z, sacc[nt].w));
        }
        rmax0 = fmaxf(rmax0, __shfl_xor_sync(0xffffffffu, rmax0, 1));
        rmax0 = fmaxf(rmax0, __shfl_xor_sync(0xffffffffu, rmax0, 2));
        rmax1 = fmaxf(rmax1, __shfl_xor_sync(0xffffffffu, rmax1, 1));
        rmax1 = fmaxf(rmax1, __shfl_xor_sync(0xffffffffu, rmax1, 2));

        float mn0 = fmaxf(m0v, rmax0), mn1 = fmaxf(m1v, rmax1);
        float al0 = __expf(m0v - mn0), al1 = __expf(m1v - mn1);
        m0v = mn0; m1v = mn1;

        float rs0 = 0.f, rs1 = 0.f;
#pragma unroll
        for (int nt = 0; nt < 8; ++nt) {
            sacc[nt].x = __expf(sacc[nt].x - mn0); rs0 += sacc[nt].x;
            sacc[nt].y = __expf(sacc[nt].y - mn0); rs0 += sacc[nt].y;
            sacc[nt].z = __expf(sacc[nt].z - mn1); rs1 += sacc[nt].z;
            sacc[nt].w = __expf(sacc[nt].w - mn1); rs1 += sacc[nt].w;
        }
        rs0 += __shfl_xor_sync(0xffffffffu, rs0, 1);
        rs0 += __shfl_xor_sync(0xffffffffu, rs0, 2);
        rs1 += __shfl_xor_sync(0xffffffffu, rs1, 1);
        rs1 += __shfl_xor_sync(0xffffffffu, rs1, 2);
        l0 = l0 * al0 + rs0;
        l1 = l1 * al1 + rs1;
#pragma unroll
        for (int dt = 0; dt < 8; ++dt) {
            oacc[dt].x *= al0; oacc[dt].y *= al0;
            oacc[dt].z *= al1; oacc[dt].w *= al1;
        }

        // P -> smem (tf32 bits); intra-warp exchange only
#pragma unroll
        for (int nt = 0; nt < 8; ++nt) {
            int j0 = nt * 8 + 2 * t4;
            Ps[rl0 * 68 + j0]     = uf(cvt_tf32(sacc[nt].x));
            Ps[rl0 * 68 + j0 + 1] = uf(cvt_tf32(sacc[nt].y));
            Ps[rl1 * 68 + j0]     = uf(cvt_tf32(sacc[nt].z));
            Ps[rl1 * 68 + j0 + 1] = uf(cvt_tf32(sacc[nt].w));
        }
        __syncwarp();

        // O += P V
#pragma unroll
        for (int jc = 0; jc < 8; ++jc) {
            uint32_t pa[4];
            pa[0] = fu(Ps[rl0 * 68 + jc * 8 + t4]);
            pa[1] = fu(Ps[rl1 * 68 + jc * 8 + t4]);
            pa[2] = fu(Ps[rl0 * 68 + jc * 8 + t4 + 4]);
            pa[3] = fu(Ps[rl1 * 68 + jc * 8 + t4 + 4]);
#pragma unroll
            for (int dt = 0; dt < 8; ++dt) {
                uint32_t b0 = cvt_tf32(vs_[(jc * 8 + t4) * 72 + dt * 8 + g]);
                uint32_t b1 = cvt_tf32(vs_[(jc * 8 + t4 + 4) * 72 + dt * 8 + g]);
                mma8(oacc[dt], pa, b0, b1);
            }
        }
    }

    // Epilogue
    float il0 = 1.f / l0, il1 = 1.f / l1;
#pragma unroll
    for (int dt = 0; dt < 8; ++dt) {
        int col = h * HD_ + dt * 8 + 2 * t4;
        size_t r0 = (size_t)(b * LQPAD + qbase + rl0) * D_ + col;
        size_t r1 = (size_t)(b * LQPAD + qbase + rl1) * D_ + col;
        *(float2*)(Og + r0) = make_float2(oacc[dt].x * il0, oacc[dt].y * il0);
        *(float2*)(Og + r1) = make_float2(oacc[dt].z * il1, oacc[dt].w * il1);
    }
}

// ---------------------------------------------------------------------------
extern "C" void kernel_launch(void* const* d_in, const int* in_sizes, int n_in,
                              void* d_out, int out_size) {
    const float* x     = (const float*)d_in[0];
    const int*   pad   = (const int*)d_in[1];
    const float* wq_sw = (const float*)d_in[4];
    const float* wq_sb = (const float*)d_in[5];
    const float* wq_nw = (const float*)d_in[6];
    const float* wq_nb = (const float*)d_in[7];
    const float* wk_sw = (const float*)d_in[8];
    const float* wk_sb = (const float*)d_in[9];
    const float* wk_nw = (const float*)d_in[10];
    const float* wk_nb = (const float*)d_in[11];
    const float* wv_sw = (const float*)d_in[12];
    const float* wv_sb = (const float*)d_in[13];
    const float* wv_nw = (const float*)d_in[14];
    const float* wv_nb = (const float*)d_in[15];
    const float* out_w = (const float*)d_in[16];
    const float* out_b = (const float*)d_in[17];
    float* out = (float*)d_out;

    float *Kp, *Vp, *Qp, *Ap, *Pp;
    cudaGetSymbolAddress((void**)&Kp, g_K);
    cudaGetSymbolAddress((void**)&Vp, g_V);
    cudaGetSymbolAddress((void**)&Qp, g_Q);
    cudaGetSymbolAddress((void**)&Ap, g_A);
    cudaGetSymbolAddress((void**)&Pp, g_Part);

    cudaFuncSetAttribute(proj_mma<0>, cudaFuncAttributeMaxDynamicSharedMemorySize, PJ_SMEM);
    cudaFuncSetAttribute(proj_mma<1>, cudaFuncAttributeMaxDynamicSharedMemorySize, PJ_SMEM);
    cudaFuncSetAttribute(proj_mma<2>, cudaFuncAttributeMaxDynamicSharedMemorySize, PJ_SMEM);
    cudaFuncSetAttribute(attn_mma, cudaFuncAttributeMaxDynamicSharedMemorySize, ATT_SMEM);

    // K projection
    proj_mma<0><<<dim3(128, 4), 256, PJ_SMEM>>>(x, wk_sw, wk_sb, Kp);
    proj_ns<<<dim3(64, 4, 4), 128>>>(x, wk_nw, Pp);
    ns_reduce<<<64, 512>>>(Pp, wk_nb, Kp, 0);
    // V projection
    proj_mma<0><<<dim3(128, 4), 256, PJ_SMEM>>>(x, wv_sw, wv_sb, Vp);
    proj_ns<<<dim3(64, 4, 4), 128>>>(x, wv_nw, Pp);
    ns_reduce<<<64, 512>>>(Pp, wv_nb, Vp, 0);
    // Q projection
    proj_mma<1><<<dim3(32, 4), 256, PJ_SMEM>>>(x, wq_sw, wq_sb, Qp);
    proj_ns<<<dim3(64, 4, 4), 128>>>(x, wq_nw, Pp);
    ns_reduce<<<64, 512>>>(Pp, wq_nb, Qp, 1);

    // Attention (q-tiles of 128 over padded 640 rows)
    attn_mma<<<dim3(5, 8, 8), 256, ATT_SMEM>>>(Qp, Kp, Vp, pad, Ap);

    // Output projection
    proj_mma<2><<<dim3(36, 4), 256, PJ_SMEM>>>(Ap, out_w, out_b, out);
}

// round 6
// speedup vs baseline: 1.1447x; 1.1447x over previous
#include <cuda_runtime.h>
#include <cstdint>

// Problem constants
#define B_      8
#define D_      512
#define H_      8
#define HD_     64
#define L_NS_   64
#define L_S_    2048
#define L_TOT   2112
#define LS_OUT  512
#define LQ_     576
#define LQPAD   640    // padded q rows (5 tiles of 128); rows 576-639 stay zero

// Scratch (allocation-free device globals; zero-initialized at module load)
__device__ float g_K[B_ * L_TOT * D_];
__device__ float g_V[B_ * L_TOT * D_];
__device__ float g_Q[B_ * LQPAD * D_];
__device__ float g_A[B_ * LQPAD * D_];
__device__ float g_Part[8 * 64 * B_ * D_];
__device__ float g_Xr[B_ * L_TOT * D_];      // tf32-rounded x
__device__ float g_Wr[4 * D_ * D_];          // tf32-rounded wk_sw, wv_sw, wq_sw, out_w

// ---------------------------------------------------------------------------
// Helpers
// ---------------------------------------------------------------------------
__device__ __forceinline__ uint32_t smem_u32(const void* p) {
    uint32_t a;
    asm("{ .reg .u64 t; cvta.to.shared.u64 t, %1; cvt.u32.u64 %0, t; }" : "=r"(a) : "l"(p));
    return a;
}
__device__ __forceinline__ uint32_t cvt_tf32(float x) {
    uint32_t u; asm("cvt.rna.tf32.f32 %0, %1;" : "=r"(u) : "f"(x)); return u;
}
__device__ __forceinline__ float uf(uint32_t u) { return __uint_as_float(u); }
__device__ __forceinline__ uint32_t fu(float f) { return __float_as_uint(f); }
__device__ __forceinline__ float rtf(float x) { return uf(cvt_tf32(x)); }

__device__ __forceinline__ void mma8(float4& d, const uint32_t a[4], uint32_t b0, uint32_t b1) {
    asm volatile(
        "mma.sync.aligned.m16n8k8.row.col.f32.tf32.tf32.f32 "
        "{%0,%1,%2,%3}, {%4,%5,%6,%7}, {%8,%9}, {%0,%1,%2,%3};"
        : "+f"(d.x), "+f"(d.y), "+f"(d.z), "+f"(d.w)
        : "r"(a[0]), "r"(a[1]), "r"(a[2]), "r"(a[3]), "r"(b0), "r"(b1));
}
__device__ __forceinline__ void cp16(uint32_t dst, const void* src) {
    asm volatile("cp.async.cg.shared.global [%0], [%1], 16;" :: "r"(dst), "l"(src));
}
#define CP_COMMIT() asm volatile("cp.async.commit_group;" ::: "memory")
#define CP_WAIT1()  asm volatile("cp.async.wait_group 1;" ::: "memory")

// ---------------------------------------------------------------------------
// Pre-round a buffer to tf32 bit patterns (one-shot prep)
// ---------------------------------------------------------------------------
__global__ __launch_bounds__(256)
void round_buf(const float* __restrict__ in, float* __restrict__ out, int n4) {
    int i = (blockIdx.x * 256 + threadIdx.x);
    if (i < n4) {
        float4 v = ((const float4*)in)[i];
        v.x = rtf(v.x); v.y = rtf(v.y); v.z = rtf(v.z); v.w = rtf(v.w);
        ((float4*)out)[i] = v;
    }
}

// ---------------------------------------------------------------------------
// Dense projection GEMM, tf32 mma.sync, 3-stage cp.async pipeline.
// Inputs A and W are PRE-ROUNDED tf32 patterns; fragments are plain bit loads.
// RND: 0 = plain fp32 out; 1 = round out to tf32; 2 = round + scale 1/8 (Q).
// ---------------------------------------------------------------------------
template <int MODE> __device__ __forceinline__ int arow_of(int mi) {
    if (MODE == 0) return (mi >> 11) * L_TOT + (mi & 2047);
    if (MODE == 1) return (mi >> 9) * L_TOT + 1536 + (mi & 511);
    return ((unsigned)mi / 576) * LQPAD + ((unsigned)mi % 576);
}
template <int MODE> __device__ __forceinline__ int crow_of(int mi) {
    if (MODE == 0) return (mi >> 11) * L_TOT + (mi & 2047);
    if (MODE == 1) return (mi >> 9) * LQPAD + (mi & 511);
    return mi;
}

#define PJ_AS 2560            // floats per A stage: 128 rows x stride 20
#define PJ_WS 2176            // floats per W stage: 16 rows x stride 136 (k-major)
#define PJ_SMEM (3 * (PJ_AS + PJ_WS) * 4)

template <int MODE, int RND>
__global__ __launch_bounds__(256, 2)
void proj_mma(const float* __restrict__ A, const float* __restrict__ W,
              const float* __restrict__ bias, float* __restrict__ C) {
    extern __shared__ float sm[];
    float* As = sm;
    float* Ws = sm + 3 * PJ_AS;
    const uint32_t as_u = smem_u32(As), ws_u = smem_u32(Ws);

    const int tid = threadIdx.x, lane = tid & 31;
    const int warp = tid >> 5, wm = warp >> 2, wn = warp & 3;
    const int g = lane >> 2, t4 = lane & 3;
    const int m0 = blockIdx.x * 128, n0 = blockIdx.y * 128;

    const int lr = tid >> 2, lk = (tid & 3) * 4;
    const float* pA0 = A + (size_t)arow_of<MODE>(m0 + lr) * D_ + lk;
    const float* pA1 = A + (size_t)arow_of<MODE>(m0 + 64 + lr) * D_ + lk;
    const int kr0 = tid >> 5, kr1 = kr0 + 8;
    const int nn = (tid & 31) * 4;
    const float* pW = W + n0;

    auto issue = [&](int c, int s) {
        const int k0 = c * 16;
        uint32_t ad = as_u + (uint32_t)(s * PJ_AS) * 4;
        cp16(ad + (uint32_t)(lr * 20 + lk) * 4, pA0 + k0);
        cp16(ad + (uint32_t)((lr + 64) * 20 + lk) * 4, pA1 + k0);
        uint32_t wd = ws_u + (uint32_t)(s * PJ_WS) * 4;
        cp16(wd + (uint32_t)(kr0 * 136 + nn) * 4, pW + (size_t)(k0 + kr0) * D_ + nn);
        cp16(wd + (uint32_t)(kr1 * 136 + nn) * 4, pW + (size_t)(k0 + kr1) * D_ + nn);
    };

    float4 acc[4][4];
#pragma unroll
    for (int i = 0; i < 4; ++i)
#pragma unroll
        for (int j = 0; j < 4; ++j) acc[i][j] = make_float4(0.f, 0.f, 0.f, 0.f);

    issue(0, 0); CP_COMMIT();
    issue(1, 1); CP_COMMIT();

#pragma unroll 1
    for (int c = 0; c < 32; ++c) {
        const int s = c % 3;
        CP_WAIT1();
        __syncthreads();
        if (c + 2 < 32) issue(c + 2, (c + 2) % 3);
        CP_COMMIT();

        const float* as_ = As + s * PJ_AS;
        const float* ws_ = Ws + s * PJ_WS;
#pragma unroll
        for (int kc = 0; kc < 2; ++kc) {
            const int kb = kc * 8;
            uint32_t af[4][4], bf[4][2];
#pragma unroll
            for (int mi = 0; mi < 4; ++mi) {
                int row = wm * 64 + mi * 16 + g;
                af[mi][0] = fu(as_[row * 20 + kb + t4]);
                af[mi][1] = fu(as_[(row + 8) * 20 + kb + t4]);
                af[mi][2] = fu(as_[row * 20 + kb + t4 + 4]);
                af[mi][3] = fu(as_[(row + 8) * 20 + kb + t4 + 4]);
            }
#pragma unroll
            for (int ni = 0; ni < 4; ++ni) {
                int col = wn * 32 + ni * 8 + g;
                bf[ni][0] = fu(ws_[(kb + t4) * 136 + col]);
                bf[ni][1] = fu(ws_[(kb + t4 + 4) * 136 + col]);
            }
#pragma unroll
            for (int mi = 0; mi < 4; ++mi)
#pragma unroll
                for (int ni = 0; ni < 4; ++ni)
                    mma8(acc[mi][ni], af[mi], bf[ni][0], bf[ni][1]);
        }
    }

    // Epilogue
#pragma unroll
    for (int ni = 0; ni < 4; ++ni) {
        int col = n0 + wn * 32 + ni * 8 + 2 * t4;
        float2 bv = *(const float2*)(bias + col);
#pragma unroll
        for (int mi = 0; mi < 4; ++mi) {
            int r0 = crow_of<MODE>(m0 + wm * 64 + mi * 16 + g);
            int r1 = crow_of<MODE>(m0 + wm * 64 + mi * 16 + g + 8);
            float o[4] = {acc[mi][ni].x + bv.x, acc[mi][ni].y + bv.y,
                          acc[mi][ni].z + bv.x, acc[mi][ni].w + bv.y};
            if (RND >= 1) {
#pragma unroll
                for (int q = 0; q < 4; ++q) {
                    o[q] = rtf(o[q]);
                    if (RND == 2) o[q] *= 0.125f;   // exact on tf32 patterns
                }
            }
            *(float2*)(C + (size_t)r0 * D_ + col) = make_float2(o[0], o[1]);
            *(float2*)(C + (size_t)r1 * D_ + col) = make_float2(o[2], o[3]);
        }
    }
}

// ---------------------------------------------------------------------------
// ns projections: deterministic k-split x8 (float4 columns), then reduce.
// ---------------------------------------------------------------------------
__global__ __launch_bounds__(128)
void proj_ns(const float* __restrict__ x, const float* __restrict__ nw,
             float* __restrict__ part) {
    __shared__ float xs[B_][64];
    const int n = blockIdx.x, kz = blockIdx.y;
    const int tid = threadIdx.x;

    {
        int b = tid >> 4, k4 = (tid & 15) << 2;
        *(float4*)&xs[b][k4] =
            *(const float4*)(x + (size_t)(b * L_TOT + L_S_ + n) * D_ + kz * 64 + k4);
    }
    __syncthreads();

    const int col4 = tid * 4;
    float4 acc[B_];
#pragma unroll
    for (int b = 0; b < B_; ++b) acc[b] = make_float4(0.f, 0.f, 0.f, 0.f);

    const float* wp = nw + (size_t)n * D_ * D_ + (size_t)(kz * 64) * D_ + col4;
#pragma unroll 8
    for (int k = 0; k < 64; ++k) {
        float4 w = *(const float4*)(wp + (size_t)k * D_);
#pragma unroll
        for (int b = 0; b < B_; ++b) {
            float xv = xs[b][k];
            acc[b].x += xv * w.x; acc[b].y += xv * w.y;
            acc[b].z += xv * w.z; acc[b].w += xv * w.w;
        }
    }
#pragma unroll
    for (int b = 0; b < B_; ++b)
        *(float4*)&part[(size_t)(((kz * 64 + n) * B_) + b) * D_ + col4] = acc[b];
}

// qmode 0: K/V buffers (round tf32); qmode 1: Q buffer (round + scale 1/8)
__global__ __launch_bounds__(512)
void ns_reduce(const float* __restrict__ part, const float* __restrict__ nb,
               float* __restrict__ out, int qmode) {
    const int n = blockIdx.x;
    const int col = threadIdx.x;
    const float bias = nb[n * D_ + col];
#pragma unroll
    for (int b = 0; b < B_; ++b) {
        float s = bias;
#pragma unroll
        for (int kz = 0; kz < 8; ++kz)
            s += part[(size_t)(((kz * 64 + n) * B_) + b) * D_ + col];
        s = rtf(s);
        if (qmode) s *= 0.125f;
        int orow = qmode ? (b * LQPAD + LS_OUT + n) : (b * L_TOT + L_S_ + n);
        out[(size_t)orow * D_ + col] = s;
    }
}

// ---------------------------------------------------------------------------
// Flash attention, tf32 mma.sync. q-tile 128, 256 threads, 2-stage cp.async
// ring, K/V/Q pre-rounded tf32 patterns (no cvt in inner loops).
// grid = (5 qtiles, 8 heads, 8 batch).
// ---------------------------------------------------------------------------
#define ATT_PS (128 * 68)     // Q staging / P exchange
#define ATT_KS (64 * 68)
#define ATT_VS (64 * 72)
#define ATT_SMEM ((ATT_PS + 2 * ATT_KS + 2 * ATT_VS) * 4 + 2 * 64 * 4)

__global__ __launch_bounds__(256, 2)
void attn_mma(const float* __restrict__ Qg, const float* __restrict__ Kg,
              const float* __restrict__ Vg, const int* __restrict__ pad,
              float* __restrict__ Og) {
    extern __shared__ float sm[];
    float* Qs = sm;
    float* Ps = sm;
    float* Ks = sm + ATT_PS;
    float* Vs = Ks + 2 * ATT_KS;
    int*   padi = (int*)(Vs + 2 * ATT_VS);
    const uint32_t ks_u = smem_u32(Ks), vs_u = smem_u32(Vs), pd_u = smem_u32(padi);

    const int tid = threadIdx.x, lane = tid & 31, w = tid >> 5;
    const int g = lane >> 2, t4 = lane & 3;
    const int qt = blockIdx.x, h = blockIdx.y, b = blockIdx.z;
    const int qbase = qt * 128;
    const int nkt = min(2 * qt + 26, 33);
    const int rl0 = 16 * w + g, rl1 = rl0 + 8;

    auto issue = [&](int kt, int s) {
        if (kt >= nkt) return;
        const int kb = kt * 64;
        const float* Kb = Kg + (size_t)(b * L_TOT + kb) * D_ + h * HD_;
        const float* Vb = Vg + (size_t)(b * L_TOT + kb) * D_ + h * HD_;
#pragma unroll
        for (int p = 0; p < 4; ++p) {
            int idx = tid + p * 256;
            int j = idx >> 4, d4 = (idx & 15) * 4;
            cp16(ks_u + (uint32_t)(s * ATT_KS + j * 68 + d4) * 4, Kb + (size_t)j * D_ + d4);
            cp16(vs_u + (uint32_t)(s * ATT_VS + j * 72 + d4) * 4, Vb + (size_t)j * D_ + d4);
        }
        if (kt < 32 && tid < 16)
            cp16(pd_u + (uint32_t)(s * 64 + tid * 4) * 4, pad + b * L_S_ + kb + tid * 4);
    };

    issue(0, 0); CP_COMMIT();

    // Stage Q (pre-rounded, pre-scaled tf32 patterns)
#pragma unroll
    for (int p = 0; p < 8; ++p) {
        int idx = tid + p * 256;
        int row = idx >> 4, d4 = (idx & 15) * 4;
        *(float4*)&Qs[row * 68 + d4] =
            *(const float4*)(Qg + (size_t)(b * LQPAD + qbase + row) * D_ + h * HD_ + d4);
    }
    __syncthreads();

    uint32_t qa[8][4];
#pragma unroll
    for (int kc = 0; kc < 8; ++kc) {
        qa[kc][0] = fu(Qs[rl0 * 68 + kc * 8 + t4]);
        qa[kc][1] = fu(Qs[rl1 * 68 + kc * 8 + t4]);
        qa[kc][2] = fu(Qs[rl0 * 68 + kc * 8 + t4 + 4]);
        qa[kc][3] = fu(Qs[rl1 * 68 + kc * 8 + t4 + 4]);
    }

    float4 oacc[8];
#pragma unroll
    for (int i = 0; i < 8; ++i) oacc[i] = make_float4(0.f, 0.f, 0.f, 0.f);
    float m0v = -1e30f, m1v = -1e30f, l0 = 0.f, l1 = 0.f;

#pragma unroll 1
    for (int kt = 0; kt < nkt; ++kt) {
        const int s = kt & 1;
        __syncthreads();              // all warps done with buffer s^1 (iter kt-1)
        issue(kt + 1, s ^ 1);
        CP_COMMIT();
        CP_WAIT1();                   // stage s (group kt) complete
        __syncthreads();

        const float* ks_ = Ks + s * ATT_KS;
        const float* vs_ = Vs + s * ATT_VS;
        const int*   pd_ = padi + s * 64;

        // S = Q K^T
        float4 sacc[8];
#pragma unroll
        for (int nt = 0; nt < 8; ++nt) sacc[nt] = make_float4(0.f, 0.f, 0.f, 0.f);
#pragma unroll
        for (int kc = 0; kc < 8; ++kc) {
#pragma unroll
            for (int nt = 0; nt < 8; ++nt) {
                uint32_t b0 = fu(ks_[(nt * 8 + g) * 68 + kc * 8 + t4]);
                uint32_t b1 = fu(ks_[(nt * 8 + g) * 68 + kc * 8 + t4 + 4]);
                mma8(sacc[nt], qa[kc], b0, b1);
            }
        }

        // Mask + online softmax
        const int moff = kt * 64 - qbase - 1536;
        const bool dopad = (kt < 32);
        float rmax0 = -1e30f, rmax1 = -1e30f;
#pragma unroll
        for (int nt = 0; nt < 8; ++nt) {
            int j0 = nt * 8 + 2 * t4, j1 = j0 + 1;
            float p0 = (dopad && pd_[j0] == 0) ? -1e30f : 0.f;
            float p1 = (dopad && pd_[j1] == 0) ? -1e30f : 0.f;
            sacc[nt].x += p0; sacc[nt].y += p1;
            sacc[nt].z += p0; sacc[nt].w += p1;
            if (moff > -64) {
                if (j0 + moff > rl0) sacc[nt].x = -1e30f;
                if (j1 + moff > rl0) sacc[nt].y = -1e30f;
                if (j0 + moff > rl1) sacc[nt].z = -1e30f;
                if (j1 + moff > rl1) sacc[nt].w = -1e30f;
            }
            rmax0 = fmaxf(rmax0, fmaxf(sacc[nt].x, sacc[nt].y));
            rmax1 = fmaxf(rmax1, fmaxf(sacc[nt].z, sacc[nt].w));
        }
        rmax0 = fmaxf(rmax0, __shfl_xor_sync(0xffffffffu, rmax0, 1));
        rmax0 = fmaxf(rmax0, __shfl_xor_sync(0xffffffffu, rmax0, 2));
        rmax1 = fmaxf(rmax1, __shfl_xor_sync(0xffffffffu, rmax1, 1));
        rmax1 = fmaxf(rmax1, __shfl_xor_sync(0xffffffffu, rmax1, 2));

        float mn0 = fmaxf(m0v, rmax0), mn1 = fmaxf(m1v, rmax1);
        float al0 = __expf(m0v - mn0), al1 = __expf(m1v - mn1);
        m0v = mn0; m1v = mn1;

        float rs0 = 0.f, rs1 = 0.f;
#pragma unroll
        for (int nt = 0; nt < 8; ++nt) {
            sacc[nt].x = __expf(sacc[nt].x - mn0); rs0 += sacc[nt].x;
            sacc[nt].y = __expf(sacc[nt].y - mn0); rs0 += sacc[nt].y;
            sacc[nt].z = __expf(sacc[nt].z - mn1); rs1 += sacc[nt].z;
            sacc[nt].w = __expf(sacc[nt].w - mn1); rs1 += sacc[nt].w;
        }
        rs0 += __shfl_xor_sync(0xffffffffu, rs0, 1);
        rs0 += __shfl_xor_sync(0xffffffffu, rs0, 2);
        rs1 += __shfl_xor_sync(0xffffffffu, rs1, 1);
        rs1 += __shfl_xor_sync(0xffffffffu, rs1, 2);
        l0 = l0 * al0 + rs0;
        l1 = l1 * al1 + rs1;
#pragma unroll
        for (int dt = 0; dt < 8; ++dt) {
            oacc[dt].x *= al0; oacc[dt].y *= al0;
            oacc[dt].z *= al1; oacc[dt].w *= al1;
        }

        // P -> smem (tf32 bits); intra-warp exchange only
#pragma unroll
        for (int nt = 0; nt < 8; ++nt) {
            int j0 = nt * 8 + 2 * t4;
            Ps[rl0 * 68 + j0]     = uf(cvt_tf32(sacc[nt].x));
            Ps[rl0 * 68 + j0 + 1] = uf(cvt_tf32(sacc[nt].y));
            Ps[rl1 * 68 + j0]     = uf(cvt_tf32(sacc[nt].z));
            Ps[rl1 * 68 + j0 + 1] = uf(cvt_tf32(sacc[nt].w));
        }
        __syncwarp();

        // O += P V
#pragma unroll
        for (int jc = 0; jc < 8; ++jc) {
            uint32_t pa[4];
            pa[0] = fu(Ps[rl0 * 68 + jc * 8 + t4]);
            pa[1] = fu(Ps[rl1 * 68 + jc * 8 + t4]);
            pa[2] = fu(Ps[rl0 * 68 + jc * 8 + t4 + 4]);
            pa[3] = fu(Ps[rl1 * 68 + jc * 8 + t4 + 4]);
#pragma unroll
            for (int dt = 0; dt < 8; ++dt) {
                uint32_t b0 = fu(vs_[(jc * 8 + t4) * 72 + dt * 8 + g]);
                uint32_t b1 = fu(vs_[(jc * 8 + t4 + 4) * 72 + dt * 8 + g]);
                mma8(oacc[dt], pa, b0, b1);
            }
        }
    }

    // Epilogue: normalize, round to tf32 (feeds out-proj MMA), store
    float il0 = 1.f / l0, il1 = 1.f / l1;
#pragma unroll
    for (int dt = 0; dt < 8; ++dt) {
        int col = h * HD_ + dt * 8 + 2 * t4;
        size_t r0 = (size_t)(b * LQPAD + qbase + rl0) * D_ + col;
        size_t r1 = (size_t)(b * LQPAD + qbase + rl1) * D_ + col;
        *(float2*)(Og + r0) = make_float2(rtf(oacc[dt].x * il0), rtf(oacc[dt].y * il0));
        *(float2*)(Og + r1) = make_float2(rtf(oacc[dt].z * il1), rtf(oacc[dt].w * il1));
    }
}

// ---------------------------------------------------------------------------
extern "C" void kernel_launch(void* const* d_in, const int* in_sizes, int n_in,
                              void* d_out, int out_size) {
    const float* x     = (const float*)d_in[0];
    const int*   pad   = (const int*)d_in[1];
    const float* wq_sw = (const float*)d_in[4];
    const float* wq_sb = (const float*)d_in[5];
    const float* wq_nw = (const float*)d_in[6];
    const float* wq_nb = (const float*)d_in[7];
    const float* wk_sw = (const float*)d_in[8];
    const float* wk_sb = (const float*)d_in[9];
    const float* wk_nw = (const float*)d_in[10];
    const float* wk_nb = (const float*)d_in[11];
    const float* wv_sw = (const float*)d_in[12];
    const float* wv_sb = (const float*)d_in[13];
    const float* wv_nw = (const float*)d_in[14];
    const float* wv_nb = (const float*)d_in[15];
    const float* out_w = (const float*)d_in[16];
    const float* out_b = (const float*)d_in[17];
    float* out = (float*)d_out;

    float *Kp, *Vp, *Qp, *Ap, *Pp, *Xr, *Wr;
    cudaGetSymbolAddress((void**)&Kp, g_K);
    cudaGetSymbolAddress((void**)&Vp, g_V);
    cudaGetSymbolAddress((void**)&Qp, g_Q);
    cudaGetSymbolAddress((void**)&Ap, g_A);
    cudaGetSymbolAddress((void**)&Pp, g_Part);
    cudaGetSymbolAddress((void**)&Xr, g_Xr);
    cudaGetSymbolAddress((void**)&Wr, g_Wr);

    cudaFuncSetAttribute((const void*)proj_mma<0,1>, cudaFuncAttributeMaxDynamicSharedMemorySize, PJ_SMEM);
    cudaFuncSetAttribute((const void*)proj_mma<1,2>, cudaFuncAttributeMaxDynamicSharedMemorySize, PJ_SMEM);
    cudaFuncSetAttribute((const void*)proj_mma<2,0>, cudaFuncAttributeMaxDynamicSharedMemorySize, PJ_SMEM);
    cudaFuncSetAttribute((const void*)attn_mma, cudaFuncAttributeMaxDynamicSharedMemorySize, ATT_SMEM);

    const int WN4 = (D_ * D_) / 4;           // 65536 float4s per weight matrix
    const int XN4 = (B_ * L_TOT * D_) / 4;   // x element count / 4

    // Prep: round x and shared weights to tf32 patterns
    round_buf<<<(XN4 + 255) / 256, 256>>>(x, Xr, XN4);
    round_buf<<<(WN4 + 255) / 256, 256>>>(wk_sw, Wr + 0 * (size_t)D_ * D_, WN4);
    round_buf<<<(WN4 + 255) / 256, 256>>>(wv_sw, Wr + 1 * (size_t)D_ * D_, WN4);
    round_buf<<<(WN4 + 255) / 256, 256>>>(wq_sw, Wr + 2 * (size_t)D_ * D_, WN4);
    round_buf<<<(WN4 + 255) / 256, 256>>>(out_w, Wr + 3 * (size_t)D_ * D_, WN4);

    // K projection
    proj_mma<0,1><<<dim3(128, 4), 256, PJ_SMEM>>>(Xr, Wr + 0 * (size_t)D_ * D_, wk_sb, Kp);
    proj_ns<<<dim3(64, 8), 128>>>(x, wk_nw, Pp);
    ns_reduce<<<64, 512>>>(Pp, wk_nb, Kp, 0);
    // V projection
    proj_mma<0,1><<<dim3(128, 4), 256, PJ_SMEM>>>(Xr, Wr + 1 * (size_t)D_ * D_, wv_sb, Vp);
    proj_ns<<<dim3(64, 8), 128>>>(x, wv_nw, Pp);
    ns_reduce<<<64, 512>>>(Pp, wv_nb, Vp, 0);
    // Q projection (scaled by 1/8, rounded)
    proj_mma<1,2><<<dim3(32, 4), 256, PJ_SMEM>>>(Xr, Wr + 2 * (size_t)D_ * D_, wq_sb, Qp);
    proj_ns<<<dim3(64, 8), 128>>>(x, wq_nw, Pp);
    ns_reduce<<<64, 512>>>(Pp, wq_nb, Qp, 1);

    // Attention
    attn_mma<<<dim3(5, 8, 8), 256, ATT_SMEM>>>(Qp, Kp, Vp, pad, Ap);

    // Output projection
    proj_mma<2,0><<<dim3(36, 4), 256, PJ_SMEM>>>(Ap, Wr + 3 * (size_t)D_ * D_, out_b, out);
}

// round 7
// speedup vs baseline: 1.3421x; 1.1725x over previous
#include <cuda_runtime.h>
#include <cstdint>

// Problem constants
#define B_      8
#define D_      512
#define H_      8
#define HD_     64
#define L_NS_   64
#define L_S_    2048
#define L_TOT   2112
#define LS_OUT  512
#define LQ_     576
#define LQPAD   640

// Scratch (allocation-free device globals)
__device__ float g_K[B_ * L_TOT * D_];
__device__ float g_V[B_ * L_TOT * D_];
__device__ float g_Q[B_ * LQPAD * D_];
__device__ float g_A[B_ * LQPAD * D_];
__device__ float g_Part[3 * 8 * 64 * B_ * D_];   // per-projection k-split partials
__device__ float g_Xr[B_ * L_TOT * D_];          // tf32-rounded x
__device__ float g_Wr[4 * D_ * D_];              // rounded wk_sw, wv_sw, wq_sw, out_w

#define WSZ ((size_t)D_ * D_)
#define PARTSZ ((size_t)8 * 64 * B_ * D_)

// ---------------------------------------------------------------------------
// Helpers
// ---------------------------------------------------------------------------
__device__ __forceinline__ uint32_t smem_u32(const void* p) {
    uint32_t a;
    asm("{ .reg .u64 t; cvta.to.shared.u64 t, %1; cvt.u32.u64 %0, t; }" : "=r"(a) : "l"(p));
    return a;
}
__device__ __forceinline__ uint32_t cvt_tf32(float x) {
    uint32_t u; asm("cvt.rna.tf32.f32 %0, %1;" : "=r"(u) : "f"(x)); return u;
}
__device__ __forceinline__ float uf(uint32_t u) { return __uint_as_float(u); }
__device__ __forceinline__ uint32_t fu(float f) { return __float_as_uint(f); }
__device__ __forceinline__ float rtf(float x) { return uf(cvt_tf32(x)); }

__device__ __forceinline__ void mma8(float4& d, const uint32_t a[4], uint32_t b0, uint32_t b1) {
    asm volatile(
        "mma.sync.aligned.m16n8k8.row.col.f32.tf32.tf32.f32 "
        "{%0,%1,%2,%3}, {%4,%5,%6,%7}, {%8,%9}, {%0,%1,%2,%3};"
        : "+f"(d.x), "+f"(d.y), "+f"(d.z), "+f"(d.w)
        : "r"(a[0]), "r"(a[1]), "r"(a[2]), "r"(a[3]), "r"(b0), "r"(b1));
}
__device__ __forceinline__ void cp16(uint32_t dst, const void* src) {
    asm volatile("cp.async.cg.shared.global [%0], [%1], 16;" :: "r"(dst), "l"(src));
}
#define CP_COMMIT() asm volatile("cp.async.commit_group;" ::: "memory")
#define CP_WAIT1()  asm volatile("cp.async.wait_group 1;" ::: "memory")

// ---------------------------------------------------------------------------
// Rounding prep
// ---------------------------------------------------------------------------
__global__ __launch_bounds__(256)
void round_x(const float* __restrict__ in, float* __restrict__ out, int n4) {
    int i = blockIdx.x * 256 + threadIdx.x;
    if (i < n4) {
        float4 v = ((const float4*)in)[i];
        v.x = rtf(v.x); v.y = rtf(v.y); v.z = rtf(v.z); v.w = rtf(v.w);
        ((float4*)out)[i] = v;
    }
}
__global__ __launch_bounds__(256)
void round_w(const float* __restrict__ w0, const float* __restrict__ w1,
             const float* __restrict__ w2, const float* __restrict__ w3,
             float* __restrict__ out) {
    const float* src = (blockIdx.y == 0) ? w0 : (blockIdx.y == 1) ? w1
                     : (blockIdx.y == 2) ? w2 : w3;
    int i = blockIdx.x * 256 + threadIdx.x;   // gridDim.x*256 == WSZ/4
    float4 v = ((const float4*)src)[i];
    v.x = rtf(v.x); v.y = rtf(v.y); v.z = rtf(v.z); v.w = rtf(v.w);
    ((float4*)(out + blockIdx.y * WSZ))[i] = v;
}

// ---------------------------------------------------------------------------
// Dense projection body (tf32 mma.sync, 3-stage cp.async), shared by the mega
// kernel and the standalone output projection.
// ---------------------------------------------------------------------------
template <int MODE> __device__ __forceinline__ int arow_of(int mi) {
    if (MODE == 0) return (mi >> 11) * L_TOT + (mi & 2047);
    if (MODE == 1) return (mi >> 9) * L_TOT + 1536 + (mi & 511);
    return ((unsigned)mi / 576) * LQPAD + ((unsigned)mi % 576);
}
template <int MODE> __device__ __forceinline__ int crow_of(int mi) {
    if (MODE == 0) return (mi >> 11) * L_TOT + (mi & 2047);
    if (MODE == 1) return (mi >> 9) * LQPAD + (mi & 511);
    return mi;
}

#define PJ_AS 2560
#define PJ_WS 2176
#define PJ_SMEM (3 * (PJ_AS + PJ_WS) * 4)

template <int MODE, int RND>
__device__ __forceinline__
void proj_body(float* sm, int m0, int n0,
               const float* __restrict__ A, const float* __restrict__ W,
               const float* __restrict__ bias, float* __restrict__ C) {
    float* As = sm;
    float* Ws = sm + 3 * PJ_AS;
    const uint32_t as_u = smem_u32(As), ws_u = smem_u32(Ws);

    const int tid = threadIdx.x, lane = tid & 31;
    const int warp = tid >> 5, wm = warp >> 2, wn = warp & 3;
    const int g = lane >> 2, t4 = lane & 3;

    const int lr = tid >> 2, lk = (tid & 3) * 4;
    const float* pA0 = A + (size_t)arow_of<MODE>(m0 + lr) * D_ + lk;
    const float* pA1 = A + (size_t)arow_of<MODE>(m0 + 64 + lr) * D_ + lk;
    const int kr0 = tid >> 5, kr1 = kr0 + 8;
    const int nn = (tid & 31) * 4;
    const float* pW = W + n0;

    auto issue = [&](int c, int s) {
        const int k0 = c * 16;
        uint32_t ad = as_u + (uint32_t)(s * PJ_AS) * 4;
        cp16(ad + (uint32_t)(lr * 20 + lk) * 4, pA0 + k0);
        cp16(ad + (uint32_t)((lr + 64) * 20 + lk) * 4, pA1 + k0);
        uint32_t wd = ws_u + (uint32_t)(s * PJ_WS) * 4;
        cp16(wd + (uint32_t)(kr0 * 136 + nn) * 4, pW + (size_t)(k0 + kr0) * D_ + nn);
        cp16(wd + (uint32_t)(kr1 * 136 + nn) * 4, pW + (size_t)(k0 + kr1) * D_ + nn);
    };

    float4 acc[4][4];
#pragma unroll
    for (int i = 0; i < 4; ++i)
#pragma unroll
        for (int j = 0; j < 4; ++j) acc[i][j] = make_float4(0.f, 0.f, 0.f, 0.f);

    issue(0, 0); CP_COMMIT();
    issue(1, 1); CP_COMMIT();

#pragma unroll 1
    for (int c = 0; c < 32; ++c) {
        const int s = c % 3;
        CP_WAIT1();
        __syncthreads();
        if (c + 2 < 32) issue(c + 2, (c + 2) % 3);
        CP_COMMIT();

        const float* as_ = As + s * PJ_AS;
        const float* ws_ = Ws + s * PJ_WS;
#pragma unroll
        for (int kc = 0; kc < 2; ++kc) {
            const int kb = kc * 8;
            uint32_t af[4][4], bf[4][2];
#pragma unroll
            for (int mi = 0; mi < 4; ++mi) {
                int row = wm * 64 + mi * 16 + g;
                af[mi][0] = fu(as_[row * 20 + kb + t4]);
                af[mi][1] = fu(as_[(row + 8) * 20 + kb + t4]);
                af[mi][2] = fu(as_[row * 20 + kb + t4 + 4]);
                af[mi][3] = fu(as_[(row + 8) * 20 + kb + t4 + 4]);
            }
#pragma unroll
            for (int ni = 0; ni < 4; ++ni) {
                int col = wn * 32 + ni * 8 + g;
                bf[ni][0] = fu(ws_[(kb + t4) * 136 + col]);
                bf[ni][1] = fu(ws_[(kb + t4 + 4) * 136 + col]);
            }
#pragma unroll
            for (int mi = 0; mi < 4; ++mi)
#pragma unroll
                for (int ni = 0; ni < 4; ++ni)
                    mma8(acc[mi][ni], af[mi], bf[ni][0], bf[ni][1]);
        }
    }

#pragma unroll
    for (int ni = 0; ni < 4; ++ni) {
        int col = n0 + wn * 32 + ni * 8 + 2 * t4;
        float2 bv = *(const float2*)(bias + col);
#pragma unroll
        for (int mi = 0; mi < 4; ++mi) {
            int r0 = crow_of<MODE>(m0 + wm * 64 + mi * 16 + g);
            int r1 = crow_of<MODE>(m0 + wm * 64 + mi * 16 + g + 8);
            float o[4] = {acc[mi][ni].x + bv.x, acc[mi][ni].y + bv.y,
                          acc[mi][ni].z + bv.x, acc[mi][ni].w + bv.y};
            if (RND >= 1) {
#pragma unroll
                for (int q = 0; q < 4; ++q) {
                    o[q] = rtf(o[q]);
                    if (RND == 2) o[q] *= 0.125f;
                }
            }
            *(float2*)(C + (size_t)r0 * D_ + col) = make_float2(o[0], o[1]);
            *(float2*)(C + (size_t)r1 * D_ + col) = make_float2(o[2], o[3]);
        }
    }
}

// ---------------------------------------------------------------------------
// ns GEMV body (fp32 exact), 256 threads: two kz-chunks of 64 k per CTA.
// ---------------------------------------------------------------------------
__device__ __forceinline__
void ns_body(float* sm, int ns_idx, const float* __restrict__ x,
             const float* __restrict__ wk_nw, const float* __restrict__ wv_nw,
             const float* __restrict__ wq_nw, float* __restrict__ part) {
    const int p = ns_idx >> 8;              // 0..2 (k, v, q)
    const int rem = ns_idx & 255;
    const int n = rem >> 2;                 // 0..63
    const int kp = rem & 3;                 // kz pair
    const int tid = threadIdx.x;
    const int half = tid >> 7, t = tid & 127;
    const int kz = kp * 2 + half;

    float* xs = sm + half * (B_ * 64);      // xs[half][8][64]
    {
        int b = t >> 4, k4 = (t & 15) << 2;
        *(float4*)&xs[b * 64 + k4] =
            *(const float4*)(x + (size_t)(b * L_TOT + L_S_ + n) * D_ + kz * 64 + k4);
    }
    __syncthreads();

    const float* nw = (p == 0) ? wk_nw : (p == 1) ? wv_nw : wq_nw;
    const int col4 = t * 4;
    float4 acc[B_];
#pragma unroll
    for (int b = 0; b < B_; ++b) acc[b] = make_float4(0.f, 0.f, 0.f, 0.f);

    const float* wp = nw + (size_t)n * D_ * D_ + (size_t)(kz * 64) * D_ + col4;
#pragma unroll 8
    for (int k = 0; k < 64; ++k) {
        float4 w = *(const float4*)(wp + (size_t)k * D_);
#pragma unroll
        for (int b = 0; b < B_; ++b) {
            float xv = xs[b * 64 + k];
            acc[b].x += xv * w.x; acc[b].y += xv * w.y;
            acc[b].z += xv * w.z; acc[b].w += xv * w.w;
        }
    }
    float* pr = part + (size_t)p * PARTSZ;
#pragma unroll
    for (int b = 0; b < B_; ++b)
        *(float4*)&pr[(size_t)(((kz * 64 + n) * B_) + b) * D_ + col4] = acc[b];
}

// ---------------------------------------------------------------------------
// Mega projection kernel: 1920 blocks, 2:3 interleave of ns : mma blocks.
// ---------------------------------------------------------------------------
__global__ __launch_bounds__(256, 2)
void mega_proj(const float* __restrict__ Xr, const float* __restrict__ x,
               const float* __restrict__ Wr,
               const float* __restrict__ wk_sb, const float* __restrict__ wv_sb,
               const float* __restrict__ wq_sb,
               const float* __restrict__ wk_nw, const float* __restrict__ wv_nw,
               const float* __restrict__ wq_nw,
               float* __restrict__ Kp, float* __restrict__ Vp,
               float* __restrict__ Qp, float* __restrict__ part) {
    extern __shared__ float sm[];
    const int bid = blockIdx.x;
    const int group = bid / 5, r = bid - group * 5;

    if (r < 2) {
        ns_body(sm, group * 2 + r, x, wk_nw, wv_nw, wq_nw, part);
        return;
    }
    const int mi = group * 3 + (r - 2);     // 0..1151
    if (mi < 512) {
        proj_body<0, 1>(sm, (mi & 127) * 128, (mi >> 7) * 128, Xr, Wr, wk_sb, Kp);
    } else if (mi < 1024) {
        int i = mi - 512;
        proj_body<0, 1>(sm, (i & 127) * 128, (i >> 7) * 128, Xr, Wr + WSZ, wv_sb, Vp);
    } else {
        int i = mi - 1024;
        proj_body<1, 2>(sm, (i & 31) * 128, (i >> 5) * 128, Xr, Wr + 2 * WSZ, wq_sb, Qp);
    }
}

// Standalone output projection (after attention)
__global__ __launch_bounds__(256, 2)
void proj_out(const float* __restrict__ A, const float* __restrict__ W,
              const float* __restrict__ bias, float* __restrict__ C) {
    extern __shared__ float sm[];
    proj_body<2, 0>(sm, blockIdx.x * 128, blockIdx.y * 128, A, W, bias, C);
}

// ---------------------------------------------------------------------------
// Fused ns reduce: grid (64 tokens, 3 projections)
// ---------------------------------------------------------------------------
__global__ __launch_bounds__(512)
void ns_reduce_all(const float* __restrict__ part,
                   const float* __restrict__ nbk, const float* __restrict__ nbv,
                   const float* __restrict__ nbq,
                   float* __restrict__ Kp, float* __restrict__ Vp,
                   float* __restrict__ Qp) {
    const int n = blockIdx.x, p = blockIdx.y;
    const int col = threadIdx.x;
    const float* nb = (p == 0) ? nbk : (p == 1) ? nbv : nbq;
    float* out = (p == 0) ? Kp : (p == 1) ? Vp : Qp;
    const float* pr = part + (size_t)p * PARTSZ;
    const float bias = nb[n * D_ + col];
    const bool qm = (p == 2);
#pragma unroll
    for (int b = 0; b < B_; ++b) {
        float s = bias;
#pragma unroll
        for (int kz = 0; kz < 8; ++kz)
            s += pr[(size_t)(((kz * 64 + n) * B_) + b) * D_ + col];
        s = rtf(s);
        if (qm) s *= 0.125f;
        int orow = qm ? (b * LQPAD + LS_OUT + n) : (b * L_TOT + L_S_ + n);
        out[(size_t)orow * D_ + col] = s;
    }
}

// ---------------------------------------------------------------------------
// Flash attention (unchanged numerics from R5)
// ---------------------------------------------------------------------------
#define ATT_PS (128 * 68)
#define ATT_KS (64 * 68)
#define ATT_VS (64 * 72)
#define ATT_SMEM ((ATT_PS + 2 * ATT_KS + 2 * ATT_VS) * 4 + 2 * 64 * 4)

__global__ __launch_bounds__(256, 2)
void attn_mma(const float* __restrict__ Qg, const float* __restrict__ Kg,
              const float* __restrict__ Vg, const int* __restrict__ pad,
              float* __restrict__ Og) {
    extern __shared__ float sm[];
    float* Qs = sm;
    float* Ps = sm;
    float* Ks = sm + ATT_PS;
    float* Vs = Ks + 2 * ATT_KS;
    int*   padi = (int*)(Vs + 2 * ATT_VS);
    const uint32_t ks_u = smem_u32(Ks), vs_u = smem_u32(Vs), pd_u = smem_u32(padi);

    const int tid = threadIdx.x, lane = tid & 31, w = tid >> 5;
    const int g = lane >> 2, t4 = lane & 3;
    const int qt = blockIdx.x, h = blockIdx.y, b = blockIdx.z;
    const int qbase = qt * 128;
    const int nkt = min(2 * qt + 26, 33);
    const int rl0 = 16 * w + g, rl1 = rl0 + 8;

    auto issue = [&](int kt, int s) {
        if (kt >= nkt) return;
        const int kb = kt * 64;
        const float* Kb = Kg + (size_t)(b * L_TOT + kb) * D_ + h * HD_;
        const float* Vb = Vg + (size_t)(b * L_TOT + kb) * D_ + h * HD_;
#pragma unroll
        for (int p = 0; p < 4; ++p) {
            int idx = tid + p * 256;
            int j = idx >> 4, d4 = (idx & 15) * 4;
            cp16(ks_u + (uint32_t)(s * ATT_KS + j * 68 + d4) * 4, Kb + (size_t)j * D_ + d4);
            cp16(vs_u + (uint32_t)(s * ATT_VS + j * 72 + d4) * 4, Vb + (size_t)j * D_ + d4);
        }
        if (kt < 32 && tid < 16)
            cp16(pd_u + (uint32_t)(s * 64 + tid * 4) * 4, pad + b * L_S_ + kb + tid * 4);
    };

    issue(0, 0); CP_COMMIT();

#pragma unroll
    for (int p = 0; p < 8; ++p) {
        int idx = tid + p * 256;
        int row = idx >> 4, d4 = (idx & 15) * 4;
        *(float4*)&Qs[row * 68 + d4] =
            *(const float4*)(Qg + (size_t)(b * LQPAD + qbase + row) * D_ + h * HD_ + d4);
    }
    __syncthreads();

    uint32_t qa[8][4];
#pragma unroll
    for (int kc = 0; kc < 8; ++kc) {
        qa[kc][0] = fu(Qs[rl0 * 68 + kc * 8 + t4]);
        qa[kc][1] = fu(Qs[rl1 * 68 + kc * 8 + t4]);
        qa[kc][2] = fu(Qs[rl0 * 68 + kc * 8 + t4 + 4]);
        qa[kc][3] = fu(Qs[rl1 * 68 + kc * 8 + t4 + 4]);
    }

    float4 oacc[8];
#pragma unroll
    for (int i = 0; i < 8; ++i) oacc[i] = make_float4(0.f, 0.f, 0.f, 0.f);
    float m0v = -1e30f, m1v = -1e30f, l0 = 0.f, l1 = 0.f;

#pragma unroll 1
    for (int kt = 0; kt < nkt; ++kt) {
        const int s = kt & 1;
        __syncthreads();
        issue(kt + 1, s ^ 1);
        CP_COMMIT();
        CP_WAIT1();
        __syncthreads();

        const float* ks_ = Ks + s * ATT_KS;
        const float* vs_ = Vs + s * ATT_VS;
        const int*   pd_ = padi + s * 64;

        float4 sacc[8];
#pragma unroll
        for (int nt = 0; nt < 8; ++nt) sacc[nt] = make_float4(0.f, 0.f, 0.f, 0.f);
#pragma unroll
        for (int kc = 0; kc < 8; ++kc) {
#pragma unroll
            for (int nt = 0; nt < 8; ++nt) {
                uint32_t b0 = fu(ks_[(nt * 8 + g) * 68 + kc * 8 + t4]);
                uint32_t b1 = fu(ks_[(nt * 8 + g) * 68 + kc * 8 + t4 + 4]);
                mma8(sacc[nt], qa[kc], b0, b1);
            }
        }

        const int moff = kt * 64 - qbase - 1536;
        const bool dopad = (kt < 32);
        float rmax0 = -1e30f, rmax1 = -1e30f;
#pragma unroll
        for (int nt = 0; nt < 8; ++nt) {
            int j0 = nt * 8 + 2 * t4, j1 = j0 + 1;
            float p0 = (dopad && pd_[j0] == 0) ? -1e30f : 0.f;
            float p1 = (dopad && pd_[j1] == 0) ? -1e30f : 0.f;
            sacc[nt].x += p0; sacc[nt].y += p1;
            sacc[nt].z += p0; sacc[nt].w += p1;
            if (moff > -64) {
                if (j0 + moff > rl0) sacc[nt].x = -1e30f;
                if (j1 + moff > rl0) sacc[nt].y = -1e30f;
                if (j0 + moff > rl1) sacc[nt].z = -1e30f;
                if (j1 + moff > rl1) sacc[nt].w = -1e30f;
            }
            rmax0 = fmaxf(rmax0, fmaxf(sacc[nt].x, sacc[nt].y));
            rmax1 = fmaxf(rmax1, fmaxf(sacc[nt].z, sacc[nt].w));
        }
        rmax0 = fmaxf(rmax0, __shfl_xor_sync(0xffffffffu, rmax0, 1));
        rmax0 = fmaxf(rmax0, __shfl_xor_sync(0xffffffffu, rmax0, 2));
        rmax1 = fmaxf(rmax1, __shfl_xor_sync(0xffffffffu, rmax1, 1));
        rmax1 = fmaxf(rmax1, __shfl_xor_sync(0xffffffffu, rmax1, 2));

        float mn0 = fmaxf(m0v, rmax0), mn1 = fmaxf(m1v, rmax1);
        float al0 = __expf(m0v - mn0), al1 = __expf(m1v - mn1);
        m0v = mn0; m1v = mn1;

        float rs0 = 0.f, rs1 = 0.f;
#pragma unroll
        for (int nt = 0; nt < 8; ++nt) {
            sacc[nt].x = __expf(sacc[nt].x - mn0); rs0 += sacc[nt].x;
            sacc[nt].y = __expf(sacc[nt].y - mn0); rs0 += sacc[nt].y;
            sacc[nt].z = __expf(sacc[nt].z - mn1); rs1 += sacc[nt].z;
            sacc[nt].w = __expf(sacc[nt].w - mn1); rs1 += sacc[nt].w;
        }
        rs0 += __shfl_xor_sync(0xffffffffu, rs0, 1);
        rs0 += __shfl_xor_sync(0xffffffffu, rs0, 2);
        rs1 += __shfl_xor_sync(0xffffffffu, rs1, 1);
        rs1 += __shfl_xor_sync(0xffffffffu, rs1, 2);
        l0 = l0 * al0 + rs0;
        l1 = l1 * al1 + rs1;
#pragma unroll
        for (int dt = 0; dt < 8; ++dt) {
            oacc[dt].x *= al0; oacc[dt].y *= al0;
            oacc[dt].z *= al1; oacc[dt].w *= al1;
        }

#pragma unroll
        for (int nt = 0; nt < 8; ++nt) {
            int j0 = nt * 8 + 2 * t4;
            Ps[rl0 * 68 + j0]     = uf(cvt_tf32(sacc[nt].x));
            Ps[rl0 * 68 + j0 + 1] = uf(cvt_tf32(sacc[nt].y));
            Ps[rl1 * 68 + j0]     = uf(cvt_tf32(sacc[nt].z));
            Ps[rl1 * 68 + j0 + 1] = uf(cvt_tf32(sacc[nt].w));
        }
        __syncwarp();

#pragma unroll
        for (int jc = 0; jc < 8; ++jc) {
            uint32_t pa[4];
            pa[0] = fu(Ps[rl0 * 68 + jc * 8 + t4]);
            pa[1] = fu(Ps[rl1 * 68 + jc * 8 + t4]);
            pa[2] = fu(Ps[rl0 * 68 + jc * 8 + t4 + 4]);
            pa[3] = fu(Ps[rl1 * 68 + jc * 8 + t4 + 4]);
#pragma unroll
            for (int dt = 0; dt < 8; ++dt) {
                uint32_t b0 = fu(vs_[(jc * 8 + t4) * 72 + dt * 8 + g]);
                uint32_t b1 = fu(vs_[(jc * 8 + t4 + 4) * 72 + dt * 8 + g]);
                mma8(oacc[dt], pa, b0, b1);
            }
        }
    }

    float il0 = 1.f / l0, il1 = 1.f / l1;
#pragma unroll
    for (int dt = 0; dt < 8; ++dt) {
        int col = h * HD_ + dt * 8 + 2 * t4;
        size_t r0 = (size_t)(b * LQPAD + qbase + rl0) * D_ + col;
        size_t r1 = (size_t)(b * LQPAD + qbase + rl1) * D_ + col;
        *(float2*)(Og + r0) = make_float2(rtf(oacc[dt].x * il0), rtf(oacc[dt].y * il0));
        *(float2*)(Og + r1) = make_float2(rtf(oacc[dt].z * il1), rtf(oacc[dt].w * il1));
    }
}

// ---------------------------------------------------------------------------
extern "C" void kernel_launch(void* const* d_in, const int* in_sizes, int n_in,
                              void* d_out, int out_size) {
    const float* x     = (const float*)d_in[0];
    const int*   pad   = (const int*)d_in[1];
    const float* wq_sw = (const float*)d_in[4];
    const float* wq_sb = (const float*)d_in[5];
    const float* wq_nw = (const float*)d_in[6];
    const float* wq_nb = (const float*)d_in[7];
    const float* wk_sw = (const float*)d_in[8];
    const float* wk_sb = (const float*)d_in[9];
    const float* wk_nw = (const float*)d_in[10];
    const float* wk_nb = (const float*)d_in[11];
    const float* wv_sw = (const float*)d_in[12];
    const float* wv_sb = (const float*)d_in[13];
    const float* wv_nw = (const float*)d_in[14];
    const float* wv_nb = (const float*)d_in[15];
    const float* out_w = (const float*)d_in[16];
    const float* out_b = (const float*)d_in[17];
    float* out = (float*)d_out;

    float *Kp, *Vp, *Qp, *Ap, *Pp, *Xr, *Wr;
    cudaGetSymbolAddress((void**)&Kp, g_K);
    cudaGetSymbolAddress((void**)&Vp, g_V);
    cudaGetSymbolAddress((void**)&Qp, g_Q);
    cudaGetSymbolAddress((void**)&Ap, g_A);
    cudaGetSymbolAddress((void**)&Pp, g_Part);
    cudaGetSymbolAddress((void**)&Xr, g_Xr);
    cudaGetSymbolAddress((void**)&Wr, g_Wr);

    cudaFuncSetAttribute((const void*)mega_proj, cudaFuncAttributeMaxDynamicSharedMemorySize, PJ_SMEM);
    cudaFuncSetAttribute((const void*)proj_out, cudaFuncAttributeMaxDynamicSharedMemorySize, PJ_SMEM);
    cudaFuncSetAttribute((const void*)attn_mma, cudaFuncAttributeMaxDynamicSharedMemorySize, ATT_SMEM);

    const int XN4 = (B_ * L_TOT * D_) / 4;

    // Prep rounding (x + 4 weight matrices)
    round_x<<<(XN4 + 255) / 256, 256>>>(x, Xr, XN4);
    round_w<<<dim3((int)(WSZ / 4 / 256), 4), 256>>>(wk_sw, wv_sw, wq_sw, out_w, Wr);

    // Fused projection phase: interleaved ns + tensor blocks
    mega_proj<<<1920, 256, PJ_SMEM>>>(Xr, x, Wr, wk_sb, wv_sb, wq_sb,
                                      wk_nw, wv_nw, wq_nw, Kp, Vp, Qp, Pp);
    ns_reduce_all<<<dim3(64, 3), 512>>>(Pp, wk_nb, wv_nb, wq_nb, Kp, Vp, Qp);

    // Attention
    attn_mma<<<dim3(5, 8, 8), 256, ATT_SMEM>>>(Qp, Kp, Vp, pad, Ap);

    // Output projection
    proj_out<<<dim3(36, 4), 256, PJ_SMEM>>>(Ap, Wr + 3 * WSZ, out_b, out);
}

// round 8
// speedup vs baseline: 1.4580x; 1.0863x over previous
#include <cuda_runtime.h>
#include <cstdint>

// Problem constants
#define B_      8
#define D_      512
#define H_      8
#define HD_     64
#define L_NS_   64
#define L_S_    2048
#define L_TOT   2112
#define LS_OUT  512
#define LQ_     576
#define LQPAD   640

// Q scale: 1/sqrt(64) * log2(e)  (exp2 domain)
#define SCL 0.18033688011112042f

// Scratch (allocation-free device globals)
__device__ float g_K[B_ * L_TOT * D_];
__device__ float g_V[B_ * L_TOT * D_];
__device__ float g_Q[B_ * LQPAD * D_];
__device__ float g_A[B_ * LQPAD * D_];
__device__ float g_Part[3 * 4 * 64 * B_ * D_];   // per-projection k-split partials
__device__ float g_Xr[B_ * L_TOT * D_];          // tf32-rounded x
__device__ float g_Wr[4 * D_ * D_];              // rounded wk_sw, wv_sw, wq_sw, out_w

#define WSZ ((size_t)D_ * D_)
#define PARTSZ ((size_t)4 * 64 * B_ * D_)

// ---------------------------------------------------------------------------
// Helpers
// ---------------------------------------------------------------------------
__device__ __forceinline__ uint32_t smem_u32(const void* p) {
    uint32_t a;
    asm("{ .reg .u64 t; cvta.to.shared.u64 t, %1; cvt.u32.u64 %0, t; }" : "=r"(a) : "l"(p));
    return a;
}
__device__ __forceinline__ uint32_t cvt_tf32(float x) {
    uint32_t u; asm("cvt.rna.tf32.f32 %0, %1;" : "=r"(u) : "f"(x)); return u;
}
__device__ __forceinline__ float uf(uint32_t u) { return __uint_as_float(u); }
__device__ __forceinline__ uint32_t fu(float f) { return __float_as_uint(f); }
__device__ __forceinline__ float rtf(float x) { return uf(cvt_tf32(x)); }

__device__ __forceinline__ void mma8(float4& d, const uint32_t a[4], uint32_t b0, uint32_t b1) {
    asm volatile(
        "mma.sync.aligned.m16n8k8.row.col.f32.tf32.tf32.f32 "
        "{%0,%1,%2,%3}, {%4,%5,%6,%7}, {%8,%9}, {%0,%1,%2,%3};"
        : "+f"(d.x), "+f"(d.y), "+f"(d.z), "+f"(d.w)
        : "r"(a[0]), "r"(a[1]), "r"(a[2]), "r"(a[3]), "r"(b0), "r"(b1));
}
__device__ __forceinline__ void cp16(uint32_t dst, const void* src) {
    asm volatile("cp.async.cg.shared.global [%0], [%1], 16;" :: "r"(dst), "l"(src));
}
#define CP_COMMIT() asm volatile("cp.async.commit_group;" ::: "memory")
#define CP_WAIT1()  asm volatile("cp.async.wait_group 1;" ::: "memory")

// ---------------------------------------------------------------------------
// Fused rounding prep: x (8448 blocks) + 4 weight matrices (256 blocks each)
// ---------------------------------------------------------------------------
#define XN4L ((long)B_ * L_TOT * D_ / 4)

__global__ __launch_bounds__(256)
void round_all(const float* __restrict__ x,
               const float* __restrict__ w0, const float* __restrict__ w1,
               const float* __restrict__ w2, const float* __restrict__ w3,
               float* __restrict__ Xr, float* __restrict__ Wr) {
    long i = (long)blockIdx.x * 256 + threadIdx.x;
    const float4* src;
    float4* dst;
    if (i < XN4L) {
        src = (const float4*)x + i;
        dst = (float4*)Xr + i;
    } else {
        long j = i - XN4L;
        int which = (int)(j >> 16);          // WSZ/4 = 65536
        long off = j & 65535;
        const float* w = (which == 0) ? w0 : (which == 1) ? w1 : (which == 2) ? w2 : w3;
        src = (const float4*)w + off;
        dst = (float4*)(Wr + (size_t)which * WSZ) + off;
    }
    float4 v = *src;
    v.x = rtf(v.x); v.y = rtf(v.y); v.z = rtf(v.z); v.w = rtf(v.w);
    *dst = v;
}

// ---------------------------------------------------------------------------
// Dense projection body (tf32 mma.sync, 3-stage cp.async)
// ---------------------------------------------------------------------------
template <int MODE> __device__ __forceinline__ int arow_of(int mi) {
    if (MODE == 0) return (mi >> 11) * L_TOT + (mi & 2047);
    if (MODE == 1) return (mi >> 9) * L_TOT + 1536 + (mi & 511);
    return ((unsigned)mi / 576) * LQPAD + ((unsigned)mi % 576);
}
template <int MODE> __device__ __forceinline__ int crow_of(int mi) {
    if (MODE == 0) return (mi >> 11) * L_TOT + (mi & 2047);
    if (MODE == 1) return (mi >> 9) * LQPAD + (mi & 511);
    return mi;
}

#define PJ_AS 2560
#define PJ_WS 2176
#define PJ_SMEM (3 * (PJ_AS + PJ_WS) * 4)

template <int MODE, int RND>
__device__ __forceinline__
void proj_body(float* sm, int m0, int n0,
               const float* __restrict__ A, const float* __restrict__ W,
               const float* __restrict__ bias, float* __restrict__ C) {
    float* As = sm;
    float* Ws = sm + 3 * PJ_AS;
    const uint32_t as_u = smem_u32(As), ws_u = smem_u32(Ws);

    const int tid = threadIdx.x, lane = tid & 31;
    const int warp = tid >> 5, wm = warp >> 2, wn = warp & 3;
    const int g = lane >> 2, t4 = lane & 3;

    const int lr = tid >> 2, lk = (tid & 3) * 4;
    const float* pA0 = A + (size_t)arow_of<MODE>(m0 + lr) * D_ + lk;
    const float* pA1 = A + (size_t)arow_of<MODE>(m0 + 64 + lr) * D_ + lk;
    const int kr0 = tid >> 5, kr1 = kr0 + 8;
    const int nn = (tid & 31) * 4;
    const float* pW = W + n0;

    auto issue = [&](int c, int s) {
        const int k0 = c * 16;
        uint32_t ad = as_u + (uint32_t)(s * PJ_AS) * 4;
        cp16(ad + (uint32_t)(lr * 20 + lk) * 4, pA0 + k0);
        cp16(ad + (uint32_t)((lr + 64) * 20 + lk) * 4, pA1 + k0);
        uint32_t wd = ws_u + (uint32_t)(s * PJ_WS) * 4;
        cp16(wd + (uint32_t)(kr0 * 136 + nn) * 4, pW + (size_t)(k0 + kr0) * D_ + nn);
        cp16(wd + (uint32_t)(kr1 * 136 + nn) * 4, pW + (size_t)(k0 + kr1) * D_ + nn);
    };

    float4 acc[4][4];
#pragma unroll
    for (int i = 0; i < 4; ++i)
#pragma unroll
        for (int j = 0; j < 4; ++j) acc[i][j] = make_float4(0.f, 0.f, 0.f, 0.f);

    issue(0, 0); CP_COMMIT();
    issue(1, 1); CP_COMMIT();

#pragma unroll 1
    for (int c = 0; c < 32; ++c) {
        const int s = c % 3;
        CP_WAIT1();
        __syncthreads();
        if (c + 2 < 32) issue(c + 2, (c + 2) % 3);
        CP_COMMIT();

        const float* as_ = As + s * PJ_AS;
        const float* ws_ = Ws + s * PJ_WS;
#pragma unroll
        for (int kc = 0; kc < 2; ++kc) {
            const int kb = kc * 8;
            uint32_t af[4][4], bf[4][2];
#pragma unroll
            for (int mi = 0; mi < 4; ++mi) {
                int row = wm * 64 + mi * 16 + g;
                af[mi][0] = fu(as_[row * 20 + kb + t4]);
                af[mi][1] = fu(as_[(row + 8) * 20 + kb + t4]);
                af[mi][2] = fu(as_[row * 20 + kb + t4 + 4]);
                af[mi][3] = fu(as_[(row + 8) * 20 + kb + t4 + 4]);
            }
#pragma unroll
            for (int ni = 0; ni < 4; ++ni) {
                int col = wn * 32 + ni * 8 + g;
                bf[ni][0] = fu(ws_[(kb + t4) * 136 + col]);
                bf[ni][1] = fu(ws_[(kb + t4 + 4) * 136 + col]);
            }
#pragma unroll
            for (int mi = 0; mi < 4; ++mi)
#pragma unroll
                for (int ni = 0; ni < 4; ++ni)
                    mma8(acc[mi][ni], af[mi], bf[ni][0], bf[ni][1]);
        }
    }

#pragma unroll
    for (int ni = 0; ni < 4; ++ni) {
        int col = n0 + wn * 32 + ni * 8 + 2 * t4;
        float2 bv = *(const float2*)(bias + col);
#pragma unroll
        for (int mi = 0; mi < 4; ++mi) {
            int r0 = crow_of<MODE>(m0 + wm * 64 + mi * 16 + g);
            int r1 = crow_of<MODE>(m0 + wm * 64 + mi * 16 + g + 8);
            float o[4] = {acc[mi][ni].x + bv.x, acc[mi][ni].y + bv.y,
                          acc[mi][ni].z + bv.x, acc[mi][ni].w + bv.y};
            if (RND == 1) {
#pragma unroll
                for (int q = 0; q < 4; ++q) o[q] = rtf(o[q]);
            } else if (RND == 2) {
#pragma unroll
                for (int q = 0; q < 4; ++q) o[q] = rtf(o[q] * SCL);
            }
            *(float2*)(C + (size_t)r0 * D_ + col) = make_float2(o[0], o[1]);
            *(float2*)(C + (size_t)r1 * D_ + col) = make_float2(o[2], o[3]);
        }
    }
}

// ---------------------------------------------------------------------------
// ns GEMV body (fp32 exact): 256 threads, two kz-chunks of 128 k per CTA.
// ---------------------------------------------------------------------------
__device__ __forceinline__
void ns_body(float* sm, int ns_idx, const float* __restrict__ x,
             const float* __restrict__ wk_nw, const float* __restrict__ wv_nw,
             const float* __restrict__ wq_nw, float* __restrict__ part) {
    const int p = ns_idx >> 7;              // 0..2 (k, v, q)
    const int rem = ns_idx & 127;
    const int n = rem >> 1;                 // 0..63
    const int kp = rem & 1;                 // kz pair
    const int tid = threadIdx.x;
    const int half = tid >> 7, t = tid & 127;
    const int kz = kp * 2 + half;           // 0..3: k range [kz*128, +128)

    float* xs = sm + half * (B_ * 128);
#pragma unroll
    for (int it = 0; it < 2; ++it) {
        int idx = t + it * 128;
        int b = idx >> 5, k4 = (idx & 31) << 2;
        *(float4*)&xs[b * 128 + k4] =
            *(const float4*)(x + (size_t)(b * L_TOT + L_S_ + n) * D_ + kz * 128 + k4);
    }
    __syncthreads();

    const float* nw = (p == 0) ? wk_nw : (p == 1) ? wv_nw : wq_nw;
    const int col4 = t * 4;
    float4 acc[B_];
#pragma unroll
    for (int b = 0; b < B_; ++b) acc[b] = make_float4(0.f, 0.f, 0.f, 0.f);

    const float* wp = nw + (size_t)n * D_ * D_ + (size_t)(kz * 128) * D_ + col4;
#pragma unroll 8
    for (int k = 0; k < 128; ++k) {
        float4 w = *(const float4*)(wp + (size_t)k * D_);
#pragma unroll
        for (int b = 0; b < B_; ++b) {
            float xv = xs[b * 128 + k];
            acc[b].x += xv * w.x; acc[b].y += xv * w.y;
            acc[b].z += xv * w.z; acc[b].w += xv * w.w;
        }
    }
    float* pr = part + (size_t)p * PARTSZ;
#pragma unroll
    for (int b = 0; b < B_; ++b)
        *(float4*)&pr[(size_t)(((kz * 64 + n) * B_) + b) * D_ + col4] = acc[b];
}

// ---------------------------------------------------------------------------
// Mega projection kernel: 1536 blocks, 1:3 interleave of ns : mma blocks.
// ---------------------------------------------------------------------------
__global__ __launch_bounds__(256, 2)
void mega_proj(const float* __restrict__ Xr, const float* __restrict__ x,
               const float* __restrict__ Wr,
               const float* __restrict__ wk_sb, const float* __restrict__ wv_sb,
               const float* __restrict__ wq_sb,
               const float* __restrict__ wk_nw, const float* __restrict__ wv_nw,
               const float* __restrict__ wq_nw,
               float* __restrict__ Kp, float* __restrict__ Vp,
               float* __restrict__ Qp, float* __restrict__ part) {
    extern __shared__ float sm[];
    const int bid = blockIdx.x;
    const int group = bid >> 2, r = bid & 3;

    if (r == 0) {
        ns_body(sm, group, x, wk_nw, wv_nw, wq_nw, part);   // group 0..383
        return;
    }
    const int mi = group * 3 + (r - 1);     // 0..1151
    if (mi < 512) {
        proj_body<0, 1>(sm, (mi & 127) * 128, (mi >> 7) * 128, Xr, Wr, wk_sb, Kp);
    } else if (mi < 1024) {
        int i = mi - 512;
        proj_body<0, 1>(sm, (i & 127) * 128, (i >> 7) * 128, Xr, Wr + WSZ, wv_sb, Vp);
    } else {
        int i = mi - 1024;
        proj_body<1, 2>(sm, (i & 31) * 128, (i >> 5) * 128, Xr, Wr + 2 * WSZ, wq_sb, Qp);
    }
}

// Standalone output projection (after attention)
__global__ __launch_bounds__(256, 2)
void proj_out(const float* __restrict__ A, const float* __restrict__ W,
              const float* __restrict__ bias, float* __restrict__ C) {
    extern __shared__ float sm[];
    proj_body<2, 0>(sm, blockIdx.x * 128, blockIdx.y * 128, A, W, bias, C);
}

// ---------------------------------------------------------------------------
// Fused ns reduce: grid (64 tokens, 3 projections)
// ---------------------------------------------------------------------------
__global__ __launch_bounds__(512)
void ns_reduce_all(const float* __restrict__ part,
                   const float* __restrict__ nbk, const float* __restrict__ nbv,
                   const float* __restrict__ nbq,
                   float* __restrict__ Kp, float* __restrict__ Vp,
                   float* __restrict__ Qp) {
    const int n = blockIdx.x, p = blockIdx.y;
    const int col = threadIdx.x;
    const float* nb = (p == 0) ? nbk : (p == 1) ? nbv : nbq;
    float* out = (p == 0) ? Kp : (p == 1) ? Vp : Qp;
    const float* pr = part + (size_t)p * PARTSZ;
    const float bias = nb[n * D_ + col];
    const bool qm = (p == 2);
#pragma unroll
    for (int b = 0; b < B_; ++b) {
        float s = bias;
#pragma unroll
        for (int kz = 0; kz < 4; ++kz)
            s += pr[(size_t)(((kz * 64 + n) * B_) + b) * D_ + col];
        s = qm ? rtf(s * SCL) : rtf(s);
        int orow = qm ? (b * LQPAD + LS_OUT + n) : (b * L_TOT + L_S_ + n);
        out[(size_t)orow * D_ + col] = s;
    }
}

// ---------------------------------------------------------------------------
// Flash attention, tf32 mma.sync, exp2 softmax, load-balanced linear grid.
// ---------------------------------------------------------------------------
#define ATT_PS (128 * 68)
#define ATT_KS (64 * 68)
#define ATT_VS (64 * 72)
#define ATT_SMEM ((ATT_PS + 2 * ATT_KS + 2 * ATT_VS) * 4 + 2 * 64 * 4)

__global__ __launch_bounds__(256, 2)
void attn_mma(const float* __restrict__ Qg, const float* __restrict__ Kg,
              const float* __restrict__ Vg, const int* __restrict__ pad,
              float* __restrict__ Og) {
    extern __shared__ float sm[];
    float* Qs = sm;
    float* Ps = sm;
    float* Ks = sm + ATT_PS;
    float* Vs = Ks + 2 * ATT_KS;
    int*   padi = (int*)(Vs + 2 * ATT_VS);
    const uint32_t ks_u = smem_u32(Ks), vs_u = smem_u32(Vs), pd_u = smem_u32(padi);

    // Load-balanced mapping: heavy q-tiles first, mirrored second half-wave.
    const int l = blockIdx.x;
    const int s_ = (l < 148) ? l : ((l < 296) ? (443 - l) : l);
    const int qt = 4 - (s_ >> 6);
    const int rem = s_ & 63;
    const int h = rem >> 3, b = rem & 7;

    const int tid = threadIdx.x, lane = tid & 31, w = tid >> 5;
    const int g = lane >> 2, t4 = lane & 3;
    const int qbase = qt * 128;
    const int nkt = min(2 * qt + 26, 33);
    const int rl0 = 16 * w + g, rl1 = rl0 + 8;

    auto issue = [&](int kt, int s) {
        if (kt >= nkt) return;
        const int kb = kt * 64;
        const float* Kb = Kg + (size_t)(b * L_TOT + kb) * D_ + h * HD_;
        const float* Vb = Vg + (size_t)(b * L_TOT + kb) * D_ + h * HD_;
#pragma unroll
        for (int p = 0; p < 4; ++p) {
            int idx = tid + p * 256;
            int j = idx >> 4, d4 = (idx & 15) * 4;
            cp16(ks_u + (uint32_t)(s * ATT_KS + j * 68 + d4) * 4, Kb + (size_t)j * D_ + d4);
            cp16(vs_u + (uint32_t)(s * ATT_VS + j * 72 + d4) * 4, Vb + (size_t)j * D_ + d4);
        }
        if (kt < 32 && tid < 16)
            cp16(pd_u + (uint32_t)(s * 64 + tid * 4) * 4, pad + b * L_S_ + kb + tid * 4);
    };

    issue(0, 0); CP_COMMIT();

#pragma unroll
    for (int p = 0; p < 8; ++p) {
        int idx = tid + p * 256;
        int row = idx >> 4, d4 = (idx & 15) * 4;
        *(float4*)&Qs[row * 68 + d4] =
            *(const float4*)(Qg + (size_t)(b * LQPAD + qbase + row) * D_ + h * HD_ + d4);
    }
    __syncthreads();

    uint32_t qa[8][4];
#pragma unroll
    for (int kc = 0; kc < 8; ++kc) {
        qa[kc][0] = fu(Qs[rl0 * 68 + kc * 8 + t4]);
        qa[kc][1] = fu(Qs[rl1 * 68 + kc * 8 + t4]);
        qa[kc][2] = fu(Qs[rl0 * 68 + kc * 8 + t4 + 4]);
        qa[kc][3] = fu(Qs[rl1 * 68 + kc * 8 + t4 + 4]);
    }

    float4 oacc[8];
#pragma unroll
    for (int i = 0; i < 8; ++i) oacc[i] = make_float4(0.f, 0.f, 0.f, 0.f);
    float m0v = -1e30f, m1v = -1e30f, l0 = 0.f, l1 = 0.f;

#pragma unroll 1
    for (int kt = 0; kt < nkt; ++kt) {
        const int s = kt & 1;
        __syncthreads();
        issue(kt + 1, s ^ 1);
        CP_COMMIT();
        CP_WAIT1();
        __syncthreads();

        const float* ks_ = Ks + s * ATT_KS;
        const float* vs_ = Vs + s * ATT_VS;
        const int*   pd_ = padi + s * 64;

        float4 sacc[8];
#pragma unroll
        for (int nt = 0; nt < 8; ++nt) sacc[nt] = make_float4(0.f, 0.f, 0.f, 0.f);
#pragma unroll
        for (int kc = 0; kc < 8; ++kc) {
#pragma unroll
            for (int nt = 0; nt < 8; ++nt) {
                uint32_t b0 = fu(ks_[(nt * 8 + g) * 68 + kc * 8 + t4]);
                uint32_t b1 = fu(ks_[(nt * 8 + g) * 68 + kc * 8 + t4 + 4]);
                mma8(sacc[nt], qa[kc], b0, b1);
            }
        }

        const int moff = kt * 64 - qbase - 1536;
        const bool dopad = (kt < 32);
        float rmax0 = -1e30f, rmax1 = -1e30f;
#pragma unroll
        for (int nt = 0; nt < 8; ++nt) {
            int j0 = nt * 8 + 2 * t4, j1 = j0 + 1;
            float p0 = (dopad && pd_[j0] == 0) ? -1e30f : 0.f;
            float p1 = (dopad && pd_[j1] == 0) ? -1e30f : 0.f;
            sacc[nt].x += p0; sacc[nt].y += p1;
            sacc[nt].z += p0; sacc[nt].w += p1;
            if (moff > -64) {
                if (j0 + moff > rl0) sacc[nt].x = -1e30f;
                if (j1 + moff > rl0) sacc[nt].y = -1e30f;
                if (j0 + moff > rl1) sacc[nt].z = -1e30f;
                if (j1 + moff > rl1) sacc[nt].w = -1e30f;
            }
            rmax0 = fmaxf(rmax0, fmaxf(sacc[nt].x, sacc[nt].y));
            rmax1 = fmaxf(rmax1, fmaxf(sacc[nt].z, sacc[nt].w));
        }
        rmax0 = fmaxf(rmax0, __shfl_xor_sync(0xffffffffu, rmax0, 1));
        rmax0 = fmaxf(rmax0, __shfl_xor_sync(0xffffffffu, rmax0, 2));
        rmax1 = fmaxf(rmax1, __shfl_xor_sync(0xffffffffu, rmax1, 1));
        rmax1 = fmaxf(rmax1, __shfl_xor_sync(0xffffffffu, rmax1, 2));

        float mn0 = fmaxf(m0v, rmax0), mn1 = fmaxf(m1v, rmax1);
        float al0 = exp2f(m0v - mn0), al1 = exp2f(m1v - mn1);
        m0v = mn0; m1v = mn1;

        float rs0 = 0.f, rs1 = 0.f;
#pragma unroll
        for (int nt = 0; nt < 8; ++nt) {
            sacc[nt].x = exp2f(sacc[nt].x - mn0); rs0 += sacc[nt].x;
            sacc[nt].y = exp2f(sacc[nt].y - mn0); rs0 += sacc[nt].y;
            sacc[nt].z = exp2f(sacc[nt].z - mn1); rs1 += sacc[nt].z;
            sacc[nt].w = exp2f(sacc[nt].w - mn1); rs1 += sacc[nt].w;
        }
        rs0 += __shfl_xor_sync(0xffffffffu, rs0, 1);
        rs0 += __shfl_xor_sync(0xffffffffu, rs0, 2);
        rs1 += __shfl_xor_sync(0xffffffffu, rs1, 1);
        rs1 += __shfl_xor_sync(0xffffffffu, rs1, 2);
        l0 = l0 * al0 + rs0;
        l1 = l1 * al1 + rs1;
#pragma unroll
        for (int dt = 0; dt < 8; ++dt) {
            oacc[dt].x *= al0; oacc[dt].y *= al0;
            oacc[dt].z *= al1; oacc[dt].w *= al1;
        }

#pragma unroll
        for (int nt = 0; nt < 8; ++nt) {
            int j0 = nt * 8 + 2 * t4;
            Ps[rl0 * 68 + j0]     = uf(cvt_tf32(sacc[nt].x));
            Ps[rl0 * 68 + j0 + 1] = uf(cvt_tf32(sacc[nt].y));
            Ps[rl1 * 68 + j0]     = uf(cvt_tf32(sacc[nt].z));
            Ps[rl1 * 68 + j0 + 1] = uf(cvt_tf32(sacc[nt].w));
        }
        __syncwarp();

#pragma unroll
        for (int jc = 0; jc < 8; ++jc) {
            uint32_t pa[4];
            pa[0] = fu(Ps[rl0 * 68 + jc * 8 + t4]);
            pa[1] = fu(Ps[rl1 * 68 + jc * 8 + t4]);
            pa[2] = fu(Ps[rl0 * 68 + jc * 8 + t4 + 4]);
            pa[3] = fu(Ps[rl1 * 68 + jc * 8 + t4 + 4]);
#pragma unroll
            for (int dt = 0; dt < 8; ++dt) {
                uint32_t b0 = fu(vs_[(jc * 8 + t4) * 72 + dt * 8 + g]);
                uint32_t b1 = fu(vs_[(jc * 8 + t4 + 4) * 72 + dt * 8 + g]);
                mma8(oacc[dt], pa, b0, b1);
            }
        }
    }

    float il0 = 1.f / l0, il1 = 1.f / l1;
#pragma unroll
    for (int dt = 0; dt < 8; ++dt) {
        int col = h * HD_ + dt * 8 + 2 * t4;
        size_t r0 = (size_t)(b * LQPAD + qbase + rl0) * D_ + col;
        size_t r1 = (size_t)(b * LQPAD + qbase + rl1) * D_ + col;
        *(float2*)(Og + r0) = make_float2(rtf(oacc[dt].x * il0), rtf(oacc[dt].y * il0));
        *(float2*)(Og + r1) = make_float2(rtf(oacc[dt].z * il1), rtf(oacc[dt].w * il1));
    }
}

// ---------------------------------------------------------------------------
extern "C" void kernel_launch(void* const* d_in, const int* in_sizes, int n_in,
                              void* d_out, int out_size) {
    const float* x     = (const float*)d_in[0];
    const int*   pad   = (const int*)d_in[1];
    const float* wq_sw = (const float*)d_in[4];
    const float* wq_sb = (const float*)d_in[5];
    const float* wq_nw = (const float*)d_in[6];
    const float* wq_nb = (const float*)d_in[7];
    const float* wk_sw = (const float*)d_in[8];
    const float* wk_sb = (const float*)d_in[9];
    const float* wk_nw = (const float*)d_in[10];
    const float* wk_nb = (const float*)d_in[11];
    const float* wv_sw = (const float*)d_in[12];
    const float* wv_sb = (const float*)d_in[13];
    const float* wv_nw = (const float*)d_in[14];
    const float* wv_nb = (const float*)d_in[15];
    const float* out_w = (const float*)d_in[16];
    const float* out_b = (const float*)d_in[17];
    float* out = (float*)d_out;

    float *Kp, *Vp, *Qp, *Ap, *Pp, *Xr, *Wr;
    cudaGetSymbolAddress((void**)&Kp, g_K);
    cudaGetSymbolAddress((void**)&Vp, g_V);
    cudaGetSymbolAddress((void**)&Qp, g_Q);
    cudaGetSymbolAddress((void**)&Ap, g_A);
    cudaGetSymbolAddress((void**)&Pp, g_Part);
    cudaGetSymbolAddress((void**)&Xr, g_Xr);
    cudaGetSymbolAddress((void**)&Wr, g_Wr);

    cudaFuncSetAttribute((const void*)mega_proj, cudaFuncAttributeMaxDynamicSharedMemorySize, PJ_SMEM);
    cudaFuncSetAttribute((const void*)proj_out, cudaFuncAttributeMaxDynamicSharedMemorySize, PJ_SMEM);
    cudaFuncSetAttribute((const void*)attn_mma, cudaFuncAttributeMaxDynamicSharedMemorySize, ATT_SMEM);

    // Prep rounding: x (8448 blocks) + 4 weights (1024 blocks)
    round_all<<<8448 + 1024, 256>>>(x, wk_sw, wv_sw, wq_sw, out_w, Xr, Wr);

    // Fused projection phase: 1:3 interleave of ns GEMV and tensor GEMM blocks
    mega_proj<<<1536, 256, PJ_SMEM>>>(Xr, x, Wr, wk_sb, wv_sb, wq_sb,
                                      wk_nw, wv_nw, wq_nw, Kp, Vp, Qp, Pp);
    ns_reduce_all<<<dim3(64, 3), 512>>>(Pp, wk_nb, wv_nb, wq_nb, Kp, Vp, Qp);

    // Attention (load-balanced linear grid)
    attn_mma<<<320, 256, ATT_SMEM>>>(Qp, Kp, Vp, pad, Ap);

    // Output projection
    proj_out<<<dim3(36, 4), 256, PJ_SMEM>>>(Ap, Wr + 3 * WSZ, out_b, out);
}

// round 9
// speedup vs baseline: 1.9206x; 1.3173x over previous
#include <cuda_runtime.h>
#include <cuda_fp16.h>
#include <cstdint>

// Problem constants
#define B_      8
#define D_      512
#define H_      8
#define HD_     64
#define L_NS_   64
#define L_S_    2048
#define L_TOT   2112
#define LS_OUT  512
#define LQ_     576
#define LQPAD   640

// Q scale: 1/sqrt(64) * log2(e)  (exp2 domain)
#define SCL 0.18033688011112042f

// Scratch (allocation-free device globals)
__device__ __half g_K[B_ * L_TOT * D_];
__device__ __half g_V[B_ * L_TOT * D_];
__device__ __half g_Q[B_ * LQPAD * D_];          // rows 576-639 stay zero
__device__ float  g_A[B_ * LQPAD * D_];
__device__ float  g_Part[3 * 4 * 64 * B_ * D_];
__device__ float  g_Xr[B_ * L_TOT * D_];         // tf32-rounded x
__device__ float  g_Wr[4 * D_ * D_];             // rounded wk_sw, wv_sw, wq_sw, out_w

#define WSZ ((size_t)D_ * D_)
#define PARTSZ ((size_t)4 * 64 * B_ * D_)

// ---------------------------------------------------------------------------
// Helpers
// ---------------------------------------------------------------------------
__device__ __forceinline__ uint32_t smem_u32(const void* p) {
    uint32_t a;
    asm("{ .reg .u64 t; cvta.to.shared.u64 t, %1; cvt.u32.u64 %0, t; }" : "=r"(a) : "l"(p));
    return a;
}
__device__ __forceinline__ uint32_t cvt_tf32(float x) {
    uint32_t u; asm("cvt.rna.tf32.f32 %0, %1;" : "=r"(u) : "f"(x)); return u;
}
__device__ __forceinline__ float uf(uint32_t u) { return __uint_as_float(u); }
__device__ __forceinline__ uint32_t fu(float f) { return __float_as_uint(f); }
__device__ __forceinline__ float rtf(float x) { return uf(cvt_tf32(x)); }
__device__ __forceinline__ uint32_t packh2(float a, float b) {
    __half2 h = __floats2half2_rn(a, b);
    return *(uint32_t*)&h;
}

__device__ __forceinline__ void mma8(float4& d, const uint32_t a[4], uint32_t b0, uint32_t b1) {
    asm volatile(
        "mma.sync.aligned.m16n8k8.row.col.f32.tf32.tf32.f32 "
        "{%0,%1,%2,%3}, {%4,%5,%6,%7}, {%8,%9}, {%0,%1,%2,%3};"
        : "+f"(d.x), "+f"(d.y), "+f"(d.z), "+f"(d.w)
        : "r"(a[0]), "r"(a[1]), "r"(a[2]), "r"(a[3]), "r"(b0), "r"(b1));
}
__device__ __forceinline__ void mma16(float4& d, const uint32_t a[4], uint32_t b0, uint32_t b1) {
    asm volatile(
        "mma.sync.aligned.m16n8k16.row.col.f32.f16.f16.f32 "
        "{%0,%1,%2,%3}, {%4,%5,%6,%7}, {%8,%9}, {%0,%1,%2,%3};"
        : "+f"(d.x), "+f"(d.y), "+f"(d.z), "+f"(d.w)
        : "r"(a[0]), "r"(a[1]), "r"(a[2]), "r"(a[3]), "r"(b0), "r"(b1));
}
__device__ __forceinline__ void ldsm4(uint32_t& r0, uint32_t& r1, uint32_t& r2, uint32_t& r3,
                                      uint32_t addr) {
    asm volatile("ldmatrix.sync.aligned.m8n8.x4.shared.b16 {%0,%1,%2,%3}, [%4];"
                 : "=r"(r0), "=r"(r1), "=r"(r2), "=r"(r3) : "r"(addr));
}
__device__ __forceinline__ void ldsm4t(uint32_t& r0, uint32_t& r1, uint32_t& r2, uint32_t& r3,
                                       uint32_t addr) {
    asm volatile("ldmatrix.sync.aligned.m8n8.x4.trans.shared.b16 {%0,%1,%2,%3}, [%4];"
                 : "=r"(r0), "=r"(r1), "=r"(r2), "=r"(r3) : "r"(addr));
}
__device__ __forceinline__ void cp16(uint32_t dst, const void* src) {
    asm volatile("cp.async.cg.shared.global [%0], [%1], 16;" :: "r"(dst), "l"(src));
}
#define CP_COMMIT() asm volatile("cp.async.commit_group;" ::: "memory")
#define CP_WAIT1()  asm volatile("cp.async.wait_group 1;" ::: "memory")

// ---------------------------------------------------------------------------
// Fused rounding prep
// ---------------------------------------------------------------------------
#define XN4L ((long)B_ * L_TOT * D_ / 4)

__global__ __launch_bounds__(256)
void round_all(const float* __restrict__ x,
               const float* __restrict__ w0, const float* __restrict__ w1,
               const float* __restrict__ w2, const float* __restrict__ w3,
               float* __restrict__ Xr, float* __restrict__ Wr) {
    long i = (long)blockIdx.x * 256 + threadIdx.x;
    const float4* src;
    float4* dst;
    if (i < XN4L) {
        src = (const float4*)x + i;
        dst = (float4*)Xr + i;
    } else {
        long j = i - XN4L;
        int which = (int)(j >> 16);
        long off = j & 65535;
        const float* w = (which == 0) ? w0 : (which == 1) ? w1 : (which == 2) ? w2 : w3;
        src = (const float4*)w + off;
        dst = (float4*)(Wr + (size_t)which * WSZ) + off;
    }
    float4 v = *src;
    v.x = rtf(v.x); v.y = rtf(v.y); v.z = rtf(v.z); v.w = rtf(v.w);
    *dst = v;
}

// ---------------------------------------------------------------------------
// Dense projection body (tf32 mma.sync, 3-stage cp.async)
// RND: 0 = fp32 out (out proj); 1 = fp16 out (K/V); 2 = fp16 out * SCL (Q).
// ---------------------------------------------------------------------------
template <int MODE> __device__ __forceinline__ int arow_of(int mi) {
    if (MODE == 0) return (mi >> 11) * L_TOT + (mi & 2047);
    if (MODE == 1) return (mi >> 9) * L_TOT + 1536 + (mi & 511);
    return ((unsigned)mi / 576) * LQPAD + ((unsigned)mi % 576);
}
template <int MODE> __device__ __forceinline__ int crow_of(int mi) {
    if (MODE == 0) return (mi >> 11) * L_TOT + (mi & 2047);
    if (MODE == 1) return (mi >> 9) * LQPAD + (mi & 511);
    return mi;
}

#define PJ_AS 2560
#define PJ_WS 2176
#define PJ_SMEM (3 * (PJ_AS + PJ_WS) * 4)

template <int MODE, int RND>
__device__ __forceinline__
void proj_body(float* sm, int m0, int n0,
               const float* __restrict__ A, const float* __restrict__ W,
               const float* __restrict__ bias, void* __restrict__ C) {
    float* As = sm;
    float* Ws = sm + 3 * PJ_AS;
    const uint32_t as_u = smem_u32(As), ws_u = smem_u32(Ws);

    const int tid = threadIdx.x, lane = tid & 31;
    const int warp = tid >> 5, wm = warp >> 2, wn = warp & 3;
    const int g = lane >> 2, t4 = lane & 3;

    const int lr = tid >> 2, lk = (tid & 3) * 4;
    const float* pA0 = A + (size_t)arow_of<MODE>(m0 + lr) * D_ + lk;
    const float* pA1 = A + (size_t)arow_of<MODE>(m0 + 64 + lr) * D_ + lk;
    const int kr0 = tid >> 5, kr1 = kr0 + 8;
    const int nn = (tid & 31) * 4;
    const float* pW = W + n0;

    auto issue = [&](int c, int s) {
        const int k0 = c * 16;
        uint32_t ad = as_u + (uint32_t)(s * PJ_AS) * 4;
        cp16(ad + (uint32_t)(lr * 20 + lk) * 4, pA0 + k0);
        cp16(ad + (uint32_t)((lr + 64) * 20 + lk) * 4, pA1 + k0);
        uint32_t wd = ws_u + (uint32_t)(s * PJ_WS) * 4;
        cp16(wd + (uint32_t)(kr0 * 136 + nn) * 4, pW + (size_t)(k0 + kr0) * D_ + nn);
        cp16(wd + (uint32_t)(kr1 * 136 + nn) * 4, pW + (size_t)(k0 + kr1) * D_ + nn);
    };

    float4 acc[4][4];
#pragma unroll
    for (int i = 0; i < 4; ++i)
#pragma unroll
        for (int j = 0; j < 4; ++j) acc[i][j] = make_float4(0.f, 0.f, 0.f, 0.f);

    issue(0, 0); CP_COMMIT();
    issue(1, 1); CP_COMMIT();

#pragma unroll 1
    for (int c = 0; c < 32; ++c) {
        const int s = c % 3;
        CP_WAIT1();
        __syncthreads();
        if (c + 2 < 32) issue(c + 2, (c + 2) % 3);
        CP_COMMIT();

        const float* as_ = As + s * PJ_AS;
        const float* ws_ = Ws + s * PJ_WS;
#pragma unroll
        for (int kc = 0; kc < 2; ++kc) {
            const int kb = kc * 8;
            uint32_t af[4][4], bf[4][2];
#pragma unroll
            for (int mi = 0; mi < 4; ++mi) {
                int row = wm * 64 + mi * 16 + g;
                af[mi][0] = fu(as_[row * 20 + kb + t4]);
                af[mi][1] = fu(as_[(row + 8) * 20 + kb + t4]);
                af[mi][2] = fu(as_[row * 20 + kb + t4 + 4]);
                af[mi][3] = fu(as_[(row + 8) * 20 + kb + t4 + 4]);
            }
#pragma unroll
            for (int ni = 0; ni < 4; ++ni) {
                int col = wn * 32 + ni * 8 + g;
                bf[ni][0] = fu(ws_[(kb + t4) * 136 + col]);
                bf[ni][1] = fu(ws_[(kb + t4 + 4) * 136 + col]);
            }
#pragma unroll
            for (int mi = 0; mi < 4; ++mi)
#pragma unroll
                for (int ni = 0; ni < 4; ++ni)
                    mma8(acc[mi][ni], af[mi], bf[ni][0], bf[ni][1]);
        }
    }

#pragma unroll
    for (int ni = 0; ni < 4; ++ni) {
        int col = n0 + wn * 32 + ni * 8 + 2 * t4;
        float2 bv = *(const float2*)(bias + col);
#pragma unroll
        for (int mi = 0; mi < 4; ++mi) {
            int r0 = crow_of<MODE>(m0 + wm * 64 + mi * 16 + g);
            int r1 = crow_of<MODE>(m0 + wm * 64 + mi * 16 + g + 8);
            float o0 = acc[mi][ni].x + bv.x, o1 = acc[mi][ni].y + bv.y;
            float o2 = acc[mi][ni].z + bv.x, o3 = acc[mi][ni].w + bv.y;
            if (RND == 0) {
                *(float2*)((float*)C + (size_t)r0 * D_ + col) = make_float2(o0, o1);
                *(float2*)((float*)C + (size_t)r1 * D_ + col) = make_float2(o2, o3);
            } else {
                if (RND == 2) { o0 *= SCL; o1 *= SCL; o2 *= SCL; o3 *= SCL; }
                *(__half2*)((__half*)C + (size_t)r0 * D_ + col) = __floats2half2_rn(o0, o1);
                *(__half2*)((__half*)C + (size_t)r1 * D_ + col) = __floats2half2_rn(o2, o3);
            }
        }
    }
}

// ---------------------------------------------------------------------------
// ns GEMV body (fp32 exact)
// ---------------------------------------------------------------------------
__device__ __forceinline__
void ns_body(float* sm, int ns_idx, const float* __restrict__ x,
             const float* __restrict__ wk_nw, const float* __restrict__ wv_nw,
             const float* __restrict__ wq_nw, float* __restrict__ part) {
    const int p = ns_idx >> 7;
    const int rem = ns_idx & 127;
    const int n = rem >> 1;
    const int kp = rem & 1;
    const int tid = threadIdx.x;
    const int half = tid >> 7, t = tid & 127;
    const int kz = kp * 2 + half;

    float* xs = sm + half * (B_ * 128);
#pragma unroll
    for (int it = 0; it < 2; ++it) {
        int idx = t + it * 128;
        int b = idx >> 5, k4 = (idx & 31) << 2;
        *(float4*)&xs[b * 128 + k4] =
            *(const float4*)(x + (size_t)(b * L_TOT + L_S_ + n) * D_ + kz * 128 + k4);
    }
    __syncthreads();

    const float* nw = (p == 0) ? wk_nw : (p == 1) ? wv_nw : wq_nw;
    const int col4 = t * 4;
    float4 acc[B_];
#pragma unroll
    for (int b = 0; b < B_; ++b) acc[b] = make_float4(0.f, 0.f, 0.f, 0.f);

    const float* wp = nw + (size_t)n * D_ * D_ + (size_t)(kz * 128) * D_ + col4;
#pragma unroll 8
    for (int k = 0; k < 128; ++k) {
        float4 w = *(const float4*)(wp + (size_t)k * D_);
#pragma unroll
        for (int b = 0; b < B_; ++b) {
            float xv = xs[b * 128 + k];
            acc[b].x += xv * w.x; acc[b].y += xv * w.y;
            acc[b].z += xv * w.z; acc[b].w += xv * w.w;
        }
    }
    float* pr = part + (size_t)p * PARTSZ;
#pragma unroll
    for (int b = 0; b < B_; ++b)
        *(float4*)&pr[(size_t)(((kz * 64 + n) * B_) + b) * D_ + col4] = acc[b];
}

// ---------------------------------------------------------------------------
// Mega projection kernel: 1536 blocks, 1:3 interleave of ns : mma blocks.
// ---------------------------------------------------------------------------
__global__ __launch_bounds__(256, 2)
void mega_proj(const float* __restrict__ Xr, const float* __restrict__ x,
               const float* __restrict__ Wr,
               const float* __restrict__ wk_sb, const float* __restrict__ wv_sb,
               const float* __restrict__ wq_sb,
               const float* __restrict__ wk_nw, const float* __restrict__ wv_nw,
               const float* __restrict__ wq_nw,
               __half* __restrict__ Kp, __half* __restrict__ Vp,
               __half* __restrict__ Qp, float* __restrict__ part) {
    extern __shared__ float sm[];
    const int bid = blockIdx.x;
    const int group = bid >> 2, r = bid & 3;

    if (r == 0) {
        ns_body(sm, group, x, wk_nw, wv_nw, wq_nw, part);
        return;
    }
    const int mi = group * 3 + (r - 1);
    if (mi < 512) {
        proj_body<0, 1>(sm, (mi & 127) * 128, (mi >> 7) * 128, Xr, Wr, wk_sb, Kp);
    } else if (mi < 1024) {
        int i = mi - 512;
        proj_body<0, 1>(sm, (i & 127) * 128, (i >> 7) * 128, Xr, Wr + WSZ, wv_sb, Vp);
    } else {
        int i = mi - 1024;
        proj_body<1, 2>(sm, (i & 31) * 128, (i >> 5) * 128, Xr, Wr + 2 * WSZ, wq_sb, Qp);
    }
}

__global__ __launch_bounds__(256, 2)
void proj_out(const float* __restrict__ A, const float* __restrict__ W,
              const float* __restrict__ bias, float* __restrict__ C) {
    extern __shared__ float sm[];
    proj_body<2, 0>(sm, blockIdx.x * 128, blockIdx.y * 128, A, W, bias, C);
}

// ---------------------------------------------------------------------------
// Fused ns reduce: grid (64 tokens, 3 projections) -> fp16 outputs
// ---------------------------------------------------------------------------
__global__ __launch_bounds__(512)
void ns_reduce_all(const float* __restrict__ part,
                   const float* __restrict__ nbk, const float* __restrict__ nbv,
                   const float* __restrict__ nbq,
                   __half* __restrict__ Kp, __half* __restrict__ Vp,
                   __half* __restrict__ Qp) {
    const int n = blockIdx.x, p = blockIdx.y;
    const int col = threadIdx.x;
    const float* nb = (p == 0) ? nbk : (p == 1) ? nbv : nbq;
    __half* out = (p == 0) ? Kp : (p == 1) ? Vp : Qp;
    const float* pr = part + (size_t)p * PARTSZ;
    const float bias = nb[n * D_ + col];
    const bool qm = (p == 2);
#pragma unroll
    for (int b = 0; b < B_; ++b) {
        float s = bias;
#pragma unroll
        for (int kz = 0; kz < 4; ++kz)
            s += pr[(size_t)(((kz * 64 + n) * B_) + b) * D_ + col];
        if (qm) s *= SCL;
        int orow = qm ? (b * LQPAD + LS_OUT + n) : (b * L_TOT + L_S_ + n);
        out[(size_t)orow * D_ + col] = __float2half_rn(s);
    }
}

// ---------------------------------------------------------------------------
// Flash attention, fp16 mma m16n8k16 + ldmatrix, P register-resident.
// q-tile 128, 256 threads, 2-stage cp.async K/V rings, balanced linear grid.
// Smem: Qs[128][72]h | Ks 2x[64][72]h | Vs 2x[64][72]h | pad 2x64 int
// ---------------------------------------------------------------------------
#define KSB 9216                         // 64*72*2 bytes per stage
#define ATT_QB (128 * 72 * 2)
#define ATT_SMEM (ATT_QB + 4 * KSB + 2 * 64 * 4)

__global__ __launch_bounds__(256, 2)
void attn_mma(const __half* __restrict__ Qg, const __half* __restrict__ Kg,
              const __half* __restrict__ Vg, const int* __restrict__ pad,
              float* __restrict__ Og) {
    extern __shared__ char smc[];
    __half* Qs = (__half*)smc;
    int* padi = (int*)(smc + ATT_QB + 4 * KSB);
    const uint32_t base = smem_u32(smc);
    const uint32_t ks_u = base + ATT_QB;
    const uint32_t vs_u = base + ATT_QB + 2 * KSB;
    const uint32_t pd_u = base + ATT_QB + 4 * KSB;

    // Load-balanced mapping: heavy q-tiles first, mirrored second half-wave.
    const int l = blockIdx.x;
    const int s_ = (l < 148) ? l : ((l < 296) ? (443 - l) : l);
    const int qt = 4 - (s_ >> 6);
    const int rem = s_ & 63;
    const int h = rem >> 3, b = rem & 7;

    const int tid = threadIdx.x, lane = tid & 31, w = tid >> 5;
    const int g = lane >> 2, t4 = lane & 3;
    const int lt = lane >> 3, lr8 = lane & 7;        // ldmatrix lane split
    const int qbase = qt * 128;
    const int nkt = min(2 * qt + 26, 33);
    const int rl0 = 16 * w + g, rl1 = rl0 + 8;

    auto issue = [&](int kt, int s) {
        if (kt >= nkt) return;
        const int kb = kt * 64;
        const __half* Kb = Kg + (size_t)(b * L_TOT + kb) * D_ + h * HD_;
        const __half* Vb = Vg + (size_t)(b * L_TOT + kb) * D_ + h * HD_;
#pragma unroll
        for (int p = 0; p < 2; ++p) {
            int idx = tid + p * 256;
            int j = idx >> 3, c8 = (idx & 7) * 8;
            cp16(ks_u + (uint32_t)(s * KSB) + (uint32_t)(j * 72 + c8) * 2, Kb + (size_t)j * D_ + c8);
            cp16(vs_u + (uint32_t)(s * KSB) + (uint32_t)(j * 72 + c8) * 2, Vb + (size_t)j * D_ + c8);
        }
        if (kt < 32 && tid < 16)
            cp16(pd_u + (uint32_t)(s * 64 + tid * 4) * 4, pad + b * L_S_ + kb + tid * 4);
    };

    issue(0, 0); CP_COMMIT();

    // Stage Q (fp16, pre-scaled)
#pragma unroll
    for (int p = 0; p < 4; ++p) {
        int idx = tid + p * 256;
        int row = idx >> 3, c8 = (idx & 7) * 8;
        *(uint4*)&Qs[row * 72 + c8] =
            *(const uint4*)(Qg + (size_t)(b * LQPAD + qbase + row) * D_ + h * HD_ + c8);
    }
    __syncthreads();

    // Q A-fragments (m16n8k16): qa[kc][0..3]
    uint32_t qa[4][4];
#pragma unroll
    for (int kc = 0; kc < 4; ++kc) {
        qa[kc][0] = *(const uint32_t*)&Qs[rl0 * 72 + kc * 16 + 2 * t4];
        qa[kc][1] = *(const uint32_t*)&Qs[rl1 * 72 + kc * 16 + 2 * t4];
        qa[kc][2] = *(const uint32_t*)&Qs[rl0 * 72 + kc * 16 + 2 * t4 + 8];
        qa[kc][3] = *(const uint32_t*)&Qs[rl1 * 72 + kc * 16 + 2 * t4 + 8];
    }

    float4 oacc[8];
#pragma unroll
    for (int i = 0; i < 8; ++i) oacc[i] = make_float4(0.f, 0.f, 0.f, 0.f);
    float m0v = -1e30f, m1v = -1e30f, l0 = 0.f, l1 = 0.f;

#pragma unroll 1
    for (int kt = 0; kt < nkt; ++kt) {
        const int s = kt & 1;
        __syncthreads();
        issue(kt + 1, s ^ 1);
        CP_COMMIT();
        CP_WAIT1();
        __syncthreads();

        const uint32_t ksb = ks_u + (uint32_t)(s * KSB);
        const uint32_t vsb = vs_u + (uint32_t)(s * KSB);
        const int* pd_ = padi + s * 64;

        // S = Q K^T  (K B-frags via ldmatrix non-trans)
        float4 sacc[8];
#pragma unroll
        for (int nt = 0; nt < 8; ++nt) sacc[nt] = make_float4(0.f, 0.f, 0.f, 0.f);
#pragma unroll
        for (int kc = 0; kc < 4; ++kc) {
#pragma unroll
            for (int ntp = 0; ntp < 4; ++ntp) {
                uint32_t b0, b1, b2, b3;
                uint32_t addr = ksb +
                    (uint32_t)(((ntp * 16 + (lt >> 1) * 8 + lr8) * 72) + kc * 16 + (lt & 1) * 8) * 2;
                ldsm4(b0, b1, b2, b3, addr);
                mma16(sacc[2 * ntp], qa[kc], b0, b1);
                mma16(sacc[2 * ntp + 1], qa[kc], b2, b3);
            }
        }

        // Mask + online softmax (exp2 domain)
        const int moff = kt * 64 - qbase - 1536;
        const bool dopad = (kt < 32);
        float rmax0 = -1e30f, rmax1 = -1e30f;
#pragma unroll
        for (int nt = 0; nt < 8; ++nt) {
            int j0 = nt * 8 + 2 * t4, j1 = j0 + 1;
            float p0 = (dopad && pd_[j0] == 0) ? -1e30f : 0.f;
            float p1 = (dopad && pd_[j1] == 0) ? -1e30f : 0.f;
            sacc[nt].x += p0; sacc[nt].y += p1;
            sacc[nt].z += p0; sacc[nt].w += p1;
            if (moff > -64) {
                if (j0 + moff > rl0) sacc[nt].x = -1e30f;
                if (j1 + moff > rl0) sacc[nt].y = -1e30f;
                if (j0 + moff > rl1) sacc[nt].z = -1e30f;
                if (j1 + moff > rl1) sacc[nt].w = -1e30f;
            }
            rmax0 = fmaxf(rmax0, fmaxf(sacc[nt].x, sacc[nt].y));
            rmax1 = fmaxf(rmax1, fmaxf(sacc[nt].z, sacc[nt].w));
        }
        rmax0 = fmaxf(rmax0, __shfl_xor_sync(0xffffffffu, rmax0, 1));
        rmax0 = fmaxf(rmax0, __shfl_xor_sync(0xffffffffu, rmax0, 2));
        rmax1 = fmaxf(rmax1, __shfl_xor_sync(0xffffffffu, rmax1, 1));
        rmax1 = fmaxf(rmax1, __shfl_xor_sync(0xffffffffu, rmax1, 2));

        float mn0 = fmaxf(m0v, rmax0), mn1 = fmaxf(m1v, rmax1);
        float al0 = exp2f(m0v - mn0), al1 = exp2f(m1v - mn1);
        m0v = mn0; m1v = mn1;

        float rs0 = 0.f, rs1 = 0.f;
#pragma unroll
        for (int nt = 0; nt < 8; ++nt) {
            sacc[nt].x = exp2f(sacc[nt].x - mn0); rs0 += sacc[nt].x;
            sacc[nt].y = exp2f(sacc[nt].y - mn0); rs0 += sacc[nt].y;
            sacc[nt].z = exp2f(sacc[nt].z - mn1); rs1 += sacc[nt].z;
            sacc[nt].w = exp2f(sacc[nt].w - mn1); rs1 += sacc[nt].w;
        }
        rs0 += __shfl_xor_sync(0xffffffffu, rs0, 1);
        rs0 += __shfl_xor_sync(0xffffffffu, rs0, 2);
        rs1 += __shfl_xor_sync(0xffffffffu, rs1, 1);
        rs1 += __shfl_xor_sync(0xffffffffu, rs1, 2);
        l0 = l0 * al0 + rs0;
        l1 = l1 * al1 + rs1;
#pragma unroll
        for (int dt = 0; dt < 8; ++dt) {
            oacc[dt].x *= al0; oacc[dt].y *= al0;
            oacc[dt].z *= al1; oacc[dt].w *= al1;
        }

        // O += P V : P packed from sacc registers, V B-frags via ldmatrix.trans
#pragma unroll
        for (int jc = 0; jc < 4; ++jc) {
            uint32_t pa[4];
            pa[0] = packh2(sacc[2 * jc].x, sacc[2 * jc].y);
            pa[1] = packh2(sacc[2 * jc].z, sacc[2 * jc].w);
            pa[2] = packh2(sacc[2 * jc + 1].x, sacc[2 * jc + 1].y);
            pa[3] = packh2(sacc[2 * jc + 1].z, sacc[2 * jc + 1].w);
#pragma unroll
            for (int dtp = 0; dtp < 4; ++dtp) {
                uint32_t v0, v1, v2, v3;
                uint32_t addr = vsb +
                    (uint32_t)(((jc * 16 + (lt & 1) * 8 + lr8) * 72) + (dtp * 2 + (lt >> 1)) * 8) * 2;
                ldsm4t(v0, v1, v2, v3, addr);
                mma16(oacc[2 * dtp], pa, v0, v1);
                mma16(oacc[2 * dtp + 1], pa, v2, v3);
            }
        }
    }

    // Epilogue: normalize, round to tf32 (feeds out-proj), store fp32
    float il0 = 1.f / l0, il1 = 1.f / l1;
#pragma unroll
    for (int dt = 0; dt < 8; ++dt) {
        int col = h * HD_ + dt * 8 + 2 * t4;
        size_t r0 = (size_t)(b * LQPAD + qbase + rl0) * D_ + col;
        size_t r1 = (size_t)(b * LQPAD + qbase + rl1) * D_ + col;
        *(float2*)(Og + r0) = make_float2(rtf(oacc[dt].x * il0), rtf(oacc[dt].y * il0));
        *(float2*)(Og + r1) = make_float2(rtf(oacc[dt].z * il1), rtf(oacc[dt].w * il1));
    }
}

// ---------------------------------------------------------------------------
extern "C" void kernel_launch(void* const* d_in, const int* in_sizes, int n_in,
                              void* d_out, int out_size) {
    const float* x     = (const float*)d_in[0];
    const int*   pad   = (const int*)d_in[1];
    const float* wq_sw = (const float*)d_in[4];
    const float* wq_sb = (const float*)d_in[5];
    const float* wq_nw = (const float*)d_in[6];
    const float* wq_nb = (const float*)d_in[7];
    const float* wk_sw = (const float*)d_in[8];
    const float* wk_sb = (const float*)d_in[9];
    const float* wk_nw = (const float*)d_in[10];
    const float* wk_nb = (const float*)d_in[11];
    const float* wv_sw = (const float*)d_in[12];
    const float* wv_sb = (const float*)d_in[13];
    const float* wv_nw = (const float*)d_in[14];
    const float* wv_nb = (const float*)d_in[15];
    const float* out_w = (const float*)d_in[16];
    const float* out_b = (const float*)d_in[17];
    float* out = (float*)d_out;

    __half *Kp, *Vp, *Qp;
    float *Ap, *Pp, *Xr, *Wr;
    cudaGetSymbolAddress((void**)&Kp, g_K);
    cudaGetSymbolAddress((void**)&Vp, g_V);
    cudaGetSymbolAddress((void**)&Qp, g_Q);
    cudaGetSymbolAddress((void**)&Ap, g_A);
    cudaGetSymbolAddress((void**)&Pp, g_Part);
    cudaGetSymbolAddress((void**)&Xr, g_Xr);
    cudaGetSymbolAddress((void**)&Wr, g_Wr);

    cudaFuncSetAttribute((const void*)mega_proj, cudaFuncAttributeMaxDynamicSharedMemorySize, PJ_SMEM);
    cudaFuncSetAttribute((const void*)proj_out, cudaFuncAttributeMaxDynamicSharedMemorySize, PJ_SMEM);
    cudaFuncSetAttribute((const void*)attn_mma, cudaFuncAttributeMaxDynamicSharedMemorySize, ATT_SMEM);

    // Prep rounding: x (8448 blocks) + 4 weights (1024 blocks)
    round_all<<<8448 + 1024, 256>>>(x, wk_sw, wv_sw, wq_sw, out_w, Xr, Wr);

    // Fused projection phase
    mega_proj<<<1536, 256, PJ_SMEM>>>(Xr, x, Wr, wk_sb, wv_sb, wq_sb,
                                      wk_nw, wv_nw, wq_nw, Kp, Vp, Qp, Pp);
    ns_reduce_all<<<dim3(64, 3), 512>>>(Pp, wk_nb, wv_nb, wq_nb, Kp, Vp, Qp);

    // Attention (fp16 core)
    attn_mma<<<320, 256, ATT_SMEM>>>(Qp, Kp, Vp, pad, Ap);

    // Output projection (tf32)
    proj_out<<<dim3(36, 4), 256, PJ_SMEM>>>(Ap, Wr + 3 * WSZ, out_b, out);
}

// round 10
// speedup vs baseline: 2.0218x; 1.0527x over previous
#include <cuda_runtime.h>
#include <cuda_fp16.h>
#include <cstdint>

// Problem constants
#define B_      8
#define D_      512
#define H_      8
#define HD_     64
#define L_NS_   64
#define L_S_    2048
#define L_TOT   2112
#define LS_OUT  512
#define LQ_     576
#define LQPAD   640

// Q scale: 1/sqrt(64) * log2(e)  (exp2 domain)
#define SCL 0.18033688011112042f

// Scratch (allocation-free device globals)
__device__ __half g_K[B_ * L_TOT * D_];
__device__ __half g_V[B_ * L_TOT * D_];
__device__ __half g_Q[B_ * LQPAD * D_];          // rows 576-639 stay zero
__device__ float  g_A[B_ * LQPAD * D_];
__device__ float  g_Part[3 * 4 * 64 * B_ * D_];
__device__ float  g_Xr[B_ * L_TOT * D_];         // tf32-rounded x
__device__ float  g_Wr[4 * D_ * D_];             // rounded wk_sw, wv_sw, wq_sw, out_w

#define WSZ ((size_t)D_ * D_)
#define PARTSZ ((size_t)4 * 64 * B_ * D_)

// ---------------------------------------------------------------------------
// Helpers
// ---------------------------------------------------------------------------
__device__ __forceinline__ uint32_t smem_u32(const void* p) {
    uint32_t a;
    asm("{ .reg .u64 t; cvta.to.shared.u64 t, %1; cvt.u32.u64 %0, t; }" : "=r"(a) : "l"(p));
    return a;
}
__device__ __forceinline__ uint32_t cvt_tf32(float x) {
    uint32_t u; asm("cvt.rna.tf32.f32 %0, %1;" : "=r"(u) : "f"(x)); return u;
}
__device__ __forceinline__ float uf(uint32_t u) { return __uint_as_float(u); }
__device__ __forceinline__ uint32_t fu(float f) { return __float_as_uint(f); }
__device__ __forceinline__ float rtf(float x) { return uf(cvt_tf32(x)); }
__device__ __forceinline__ uint32_t packh2(float a, float b) {
    __half2 h = __floats2half2_rn(a, b);
    return *(uint32_t*)&h;
}
__device__ __forceinline__ uint32_t h2exp2(uint32_t h) {
    uint32_t r; asm("ex2.approx.f16x2 %0, %1;" : "=r"(r) : "r"(h)); return r;
}

__device__ __forceinline__ void mma8(float4& d, const uint32_t a[4], uint32_t b0, uint32_t b1) {
    asm volatile(
        "mma.sync.aligned.m16n8k8.row.col.f32.tf32.tf32.f32 "
        "{%0,%1,%2,%3}, {%4,%5,%6,%7}, {%8,%9}, {%0,%1,%2,%3};"
        : "+f"(d.x), "+f"(d.y), "+f"(d.z), "+f"(d.w)
        : "r"(a[0]), "r"(a[1]), "r"(a[2]), "r"(a[3]), "r"(b0), "r"(b1));
}
__device__ __forceinline__ void mma16(float4& d, const uint32_t a[4], uint32_t b0, uint32_t b1) {
    asm volatile(
        "mma.sync.aligned.m16n8k16.row.col.f32.f16.f16.f32 "
        "{%0,%1,%2,%3}, {%4,%5,%6,%7}, {%8,%9}, {%0,%1,%2,%3};"
        : "+f"(d.x), "+f"(d.y), "+f"(d.z), "+f"(d.w)
        : "r"(a[0]), "r"(a[1]), "r"(a[2]), "r"(a[3]), "r"(b0), "r"(b1));
}
__device__ __forceinline__ void ldsm4(uint32_t& r0, uint32_t& r1, uint32_t& r2, uint32_t& r3,
                                      uint32_t addr) {
    asm volatile("ldmatrix.sync.aligned.m8n8.x4.shared.b16 {%0,%1,%2,%3}, [%4];"
                 : "=r"(r0), "=r"(r1), "=r"(r2), "=r"(r3) : "r"(addr));
}
__device__ __forceinline__ void ldsm4t(uint32_t& r0, uint32_t& r1, uint32_t& r2, uint32_t& r3,
                                       uint32_t addr) {
    asm volatile("ldmatrix.sync.aligned.m8n8.x4.trans.shared.b16 {%0,%1,%2,%3}, [%4];"
                 : "=r"(r0), "=r"(r1), "=r"(r2), "=r"(r3) : "r"(addr));
}
__device__ __forceinline__ void cp16(uint32_t dst, const void* src) {
    asm volatile("cp.async.cg.shared.global [%0], [%1], 16;" :: "r"(dst), "l"(src));
}
#define CP_COMMIT() asm volatile("cp.async.commit_group;" ::: "memory")
#define CP_WAIT1()  asm volatile("cp.async.wait_group 1;" ::: "memory")

// ---------------------------------------------------------------------------
// Fused rounding prep
// ---------------------------------------------------------------------------
#define XN4L ((long)B_ * L_TOT * D_ / 4)

__global__ __launch_bounds__(256)
void round_all(const float* __restrict__ x,
               const float* __restrict__ w0, const float* __restrict__ w1,
               const float* __restrict__ w2, const float* __restrict__ w3,
               float* __restrict__ Xr, float* __restrict__ Wr) {
    long i = (long)blockIdx.x * 256 + threadIdx.x;
    const float4* src;
    float4* dst;
    if (i < XN4L) {
        src = (const float4*)x + i;
        dst = (float4*)Xr + i;
    } else {
        long j = i - XN4L;
        int which = (int)(j >> 16);
        long off = j & 65535;
        const float* w = (which == 0) ? w0 : (which == 1) ? w1 : (which == 2) ? w2 : w3;
        src = (const float4*)w + off;
        dst = (float4*)(Wr + (size_t)which * WSZ) + off;
    }
    float4 v = *src;
    v.x = rtf(v.x); v.y = rtf(v.y); v.z = rtf(v.z); v.w = rtf(v.w);
    *dst = v;
}

// ---------------------------------------------------------------------------
// Dense projection body (tf32 mma.sync, 3-stage cp.async)
// RND: 0 = fp32 out (out proj); 1 = fp16 out (K/V); 2 = fp16 out * SCL (Q).
// ---------------------------------------------------------------------------
template <int MODE> __device__ __forceinline__ int arow_of(int mi) {
    if (MODE == 0) return (mi >> 11) * L_TOT + (mi & 2047);
    if (MODE == 1) return (mi >> 9) * L_TOT + 1536 + (mi & 511);
    return ((unsigned)mi / 576) * LQPAD + ((unsigned)mi % 576);
}
template <int MODE> __device__ __forceinline__ int crow_of(int mi) {
    if (MODE == 0) return (mi >> 11) * L_TOT + (mi & 2047);
    if (MODE == 1) return (mi >> 9) * LQPAD + (mi & 511);
    return mi;
}

#define PJ_AS 2560
#define PJ_WS 2176
#define PJ_SMEM (3 * (PJ_AS + PJ_WS) * 4)

template <int MODE, int RND>
__device__ __forceinline__
void proj_body(float* sm, int m0, int n0,
               const float* __restrict__ A, const float* __restrict__ W,
               const float* __restrict__ bias, void* __restrict__ C) {
    float* As = sm;
    float* Ws = sm + 3 * PJ_AS;
    const uint32_t as_u = smem_u32(As), ws_u = smem_u32(Ws);

    const int tid = threadIdx.x, lane = tid & 31;
    const int warp = tid >> 5, wm = warp >> 2, wn = warp & 3;
    const int g = lane >> 2, t4 = lane & 3;

    const int lr = tid >> 2, lk = (tid & 3) * 4;
    const float* pA0 = A + (size_t)arow_of<MODE>(m0 + lr) * D_ + lk;
    const float* pA1 = A + (size_t)arow_of<MODE>(m0 + 64 + lr) * D_ + lk;
    const int kr0 = tid >> 5, kr1 = kr0 + 8;
    const int nn = (tid & 31) * 4;
    const float* pW = W + n0;

    auto issue = [&](int c, int s) {
        const int k0 = c * 16;
        uint32_t ad = as_u + (uint32_t)(s * PJ_AS) * 4;
        cp16(ad + (uint32_t)(lr * 20 + lk) * 4, pA0 + k0);
        cp16(ad + (uint32_t)((lr + 64) * 20 + lk) * 4, pA1 + k0);
        uint32_t wd = ws_u + (uint32_t)(s * PJ_WS) * 4;
        cp16(wd + (uint32_t)(kr0 * 136 + nn) * 4, pW + (size_t)(k0 + kr0) * D_ + nn);
        cp16(wd + (uint32_t)(kr1 * 136 + nn) * 4, pW + (size_t)(k0 + kr1) * D_ + nn);
    };

    float4 acc[4][4];
#pragma unroll
    for (int i = 0; i < 4; ++i)
#pragma unroll
        for (int j = 0; j < 4; ++j) acc[i][j] = make_float4(0.f, 0.f, 0.f, 0.f);

    issue(0, 0); CP_COMMIT();
    issue(1, 1); CP_COMMIT();

#pragma unroll 1
    for (int c = 0; c < 32; ++c) {
        const int s = c % 3;
        CP_WAIT1();
        __syncthreads();
        if (c + 2 < 32) issue(c + 2, (c + 2) % 3);
        CP_COMMIT();

        const float* as_ = As + s * PJ_AS;
        const float* ws_ = Ws + s * PJ_WS;
#pragma unroll
        for (int kc = 0; kc < 2; ++kc) {
            const int kb = kc * 8;
            uint32_t af[4][4], bf[4][2];
#pragma unroll
            for (int mi = 0; mi < 4; ++mi) {
                int row = wm * 64 + mi * 16 + g;
                af[mi][0] = fu(as_[row * 20 + kb + t4]);
                af[mi][1] = fu(as_[(row + 8) * 20 + kb + t4]);
                af[mi][2] = fu(as_[row * 20 + kb + t4 + 4]);
                af[mi][3] = fu(as_[(row + 8) * 20 + kb + t4 + 4]);
            }
#pragma unroll
            for (int ni = 0; ni < 4; ++ni) {
                int col = wn * 32 + ni * 8 + g;
                bf[ni][0] = fu(ws_[(kb + t4) * 136 + col]);
                bf[ni][1] = fu(ws_[(kb + t4 + 4) * 136 + col]);
            }
#pragma unroll
            for (int mi = 0; mi < 4; ++mi)
#pragma unroll
                for (int ni = 0; ni < 4; ++ni)
                    mma8(acc[mi][ni], af[mi], bf[ni][0], bf[ni][1]);
        }
    }

#pragma unroll
    for (int ni = 0; ni < 4; ++ni) {
        int col = n0 + wn * 32 + ni * 8 + 2 * t4;
        float2 bv = *(const float2*)(bias + col);
#pragma unroll
        for (int mi = 0; mi < 4; ++mi) {
            int r0 = crow_of<MODE>(m0 + wm * 64 + mi * 16 + g);
            int r1 = crow_of<MODE>(m0 + wm * 64 + mi * 16 + g + 8);
            float o0 = acc[mi][ni].x + bv.x, o1 = acc[mi][ni].y + bv.y;
            float o2 = acc[mi][ni].z + bv.x, o3 = acc[mi][ni].w + bv.y;
            if (RND == 0) {
                *(float2*)((float*)C + (size_t)r0 * D_ + col) = make_float2(o0, o1);
                *(float2*)((float*)C + (size_t)r1 * D_ + col) = make_float2(o2, o3);
            } else {
                if (RND == 2) { o0 *= SCL; o1 *= SCL; o2 *= SCL; o3 *= SCL; }
                *(__half2*)((__half*)C + (size_t)r0 * D_ + col) = __floats2half2_rn(o0, o1);
                *(__half2*)((__half*)C + (size_t)r1 * D_ + col) = __floats2half2_rn(o2, o3);
            }
        }
    }
}

// ---------------------------------------------------------------------------
// ns GEMV body (fp32 exact)
// ---------------------------------------------------------------------------
__device__ __forceinline__
void ns_body(float* sm, int ns_idx, const float* __restrict__ x,
             const float* __restrict__ wk_nw, const float* __restrict__ wv_nw,
             const float* __restrict__ wq_nw, float* __restrict__ part) {
    const int p = ns_idx >> 7;
    const int rem = ns_idx & 127;
    const int n = rem >> 1;
    const int kp = rem & 1;
    const int tid = threadIdx.x;
    const int half = tid >> 7, t = tid & 127;
    const int kz = kp * 2 + half;

    float* xs = sm + half * (B_ * 128);
#pragma unroll
    for (int it = 0; it < 2; ++it) {
        int idx = t + it * 128;
        int b = idx >> 5, k4 = (idx & 31) << 2;
        *(float4*)&xs[b * 128 + k4] =
            *(const float4*)(x + (size_t)(b * L_TOT + L_S_ + n) * D_ + kz * 128 + k4);
    }
    __syncthreads();

    const float* nw = (p == 0) ? wk_nw : (p == 1) ? wv_nw : wq_nw;
    const int col4 = t * 4;
    float4 acc[B_];
#pragma unroll
    for (int b = 0; b < B_; ++b) acc[b] = make_float4(0.f, 0.f, 0.f, 0.f);

    const float* wp = nw + (size_t)n * D_ * D_ + (size_t)(kz * 128) * D_ + col4;
#pragma unroll 8
    for (int k = 0; k < 128; ++k) {
        float4 w = *(const float4*)(wp + (size_t)k * D_);
#pragma unroll
        for (int b = 0; b < B_; ++b) {
            float xv = xs[b * 128 + k];
            acc[b].x += xv * w.x; acc[b].y += xv * w.y;
            acc[b].z += xv * w.z; acc[b].w += xv * w.w;
        }
    }
    float* pr = part + (size_t)p * PARTSZ;
#pragma unroll
    for (int b = 0; b < B_; ++b)
        *(float4*)&pr[(size_t)(((kz * 64 + n) * B_) + b) * D_ + col4] = acc[b];
}

// ---------------------------------------------------------------------------
// Mega projection kernel: 1536 blocks, 1:3 interleave of ns : mma blocks.
// ---------------------------------------------------------------------------
__global__ __launch_bounds__(256, 2)
void mega_proj(const float* __restrict__ Xr, const float* __restrict__ x,
               const float* __restrict__ Wr,
               const float* __restrict__ wk_sb, const float* __restrict__ wv_sb,
               const float* __restrict__ wq_sb,
               const float* __restrict__ wk_nw, const float* __restrict__ wv_nw,
               const float* __restrict__ wq_nw,
               __half* __restrict__ Kp, __half* __restrict__ Vp,
               __half* __restrict__ Qp, float* __restrict__ part) {
    extern __shared__ float sm[];
    const int bid = blockIdx.x;
    const int group = bid >> 2, r = bid & 3;

    if (r == 0) {
        ns_body(sm, group, x, wk_nw, wv_nw, wq_nw, part);
        return;
    }
    const int mi = group * 3 + (r - 1);
    if (mi < 512) {
        proj_body<0, 1>(sm, (mi & 127) * 128, (mi >> 7) * 128, Xr, Wr, wk_sb, Kp);
    } else if (mi < 1024) {
        int i = mi - 512;
        proj_body<0, 1>(sm, (i & 127) * 128, (i >> 7) * 128, Xr, Wr + WSZ, wv_sb, Vp);
    } else {
        int i = mi - 1024;
        proj_body<1, 2>(sm, (i & 31) * 128, (i >> 5) * 128, Xr, Wr + 2 * WSZ, wq_sb, Qp);
    }
}

__global__ __launch_bounds__(256, 2)
void proj_out(const float* __restrict__ A, const float* __restrict__ W,
              const float* __restrict__ bias, float* __restrict__ C) {
    extern __shared__ float sm[];
    proj_body<2, 0>(sm, blockIdx.x * 128, blockIdx.y * 128, A, W, bias, C);
}

// ---------------------------------------------------------------------------
// Fused ns reduce: grid (64 tokens, 3 projections) -> fp16 outputs
// ---------------------------------------------------------------------------
__global__ __launch_bounds__(512)
void ns_reduce_all(const float* __restrict__ part,
                   const float* __restrict__ nbk, const float* __restrict__ nbv,
                   const float* __restrict__ nbq,
                   __half* __restrict__ Kp, __half* __restrict__ Vp,
                   __half* __restrict__ Qp) {
    const int n = blockIdx.x, p = blockIdx.y;
    const int col = threadIdx.x;
    const float* nb = (p == 0) ? nbk : (p == 1) ? nbv : nbq;
    __half* out = (p == 0) ? Kp : (p == 1) ? Vp : Qp;
    const float* pr = part + (size_t)p * PARTSZ;
    const float bias = nb[n * D_ + col];
    const bool qm = (p == 2);
#pragma unroll
    for (int b = 0; b < B_; ++b) {
        float s = bias;
#pragma unroll
        for (int kz = 0; kz < 4; ++kz)
            s += pr[(size_t)(((kz * 64 + n) * B_) + b) * D_ + col];
        if (qm) s *= SCL;
        int orow = qm ? (b * LQPAD + LS_OUT + n) : (b * L_TOT + L_S_ + n);
        out[(size_t)orow * D_ + col] = __float2half_rn(s);
    }
}

// ---------------------------------------------------------------------------
// Flash attention, fp16 mma + ldmatrix; NO online max (scores bounded),
// f16x2 exp2, row-sum l via ones-column MMA. 2-stage cp.async rings.
// ---------------------------------------------------------------------------
#define KSB 9216                         // 64*72*2 bytes per stage
#define ATT_QB (128 * 72 * 2)
#define ATT_SMEM (ATT_QB + 4 * KSB + 2 * 64 * 4)

__global__ __launch_bounds__(256, 2)
void attn_mma(const __half* __restrict__ Qg, const __half* __restrict__ Kg,
              const __half* __restrict__ Vg, const int* __restrict__ pad,
              float* __restrict__ Og) {
    extern __shared__ char smc[];
    __half* Qs = (__half*)smc;
    int* padi = (int*)(smc + ATT_QB + 4 * KSB);
    const uint32_t base = smem_u32(smc);
    const uint32_t ks_u = base + ATT_QB;
    const uint32_t vs_u = base + ATT_QB + 2 * KSB;
    const uint32_t pd_u = base + ATT_QB + 4 * KSB;

    // Load-balanced mapping: heavy q-tiles first, mirrored second half-wave.
    const int l = blockIdx.x;
    const int s_ = (l < 148) ? l : ((l < 296) ? (443 - l) : l);
    const int qt = 4 - (s_ >> 6);
    const int rem = s_ & 63;
    const int h = rem >> 3, b = rem & 7;

    const int tid = threadIdx.x, lane = tid & 31, w = tid >> 5;
    const int g = lane >> 2, t4 = lane & 3;
    const int lt = lane >> 3, lr8 = lane & 7;
    const int qbase = qt * 128;
    const int nkt = min(2 * qt + 26, 33);
    const int rl0 = 16 * w + g, rl1 = rl0 + 8;

    // ones B-fragment (col 0 of B = 1): held by lanes 0-3 (g==0)
    const uint32_t ones = (lane < 4) ? 0x3C003C00u : 0u;

    auto issue = [&](int kt, int s) {
        if (kt >= nkt) return;
        const int kb = kt * 64;
        const __half* Kb = Kg + (size_t)(b * L_TOT + kb) * D_ + h * HD_;
        const __half* Vb = Vg + (size_t)(b * L_TOT + kb) * D_ + h * HD_;
#pragma unroll
        for (int p = 0; p < 2; ++p) {
            int idx = tid + p * 256;
            int j = idx >> 3, c8 = (idx & 7) * 8;
            cp16(ks_u + (uint32_t)(s * KSB) + (uint32_t)(j * 72 + c8) * 2, Kb + (size_t)j * D_ + c8);
            cp16(vs_u + (uint32_t)(s * KSB) + (uint32_t)(j * 72 + c8) * 2, Vb + (size_t)j * D_ + c8);
        }
        if (kt < 32 && tid < 16)
            cp16(pd_u + (uint32_t)(s * 64 + tid * 4) * 4, pad + b * L_S_ + kb + tid * 4);
    };

    issue(0, 0); CP_COMMIT();

    // Stage Q (fp16, pre-scaled)
#pragma unroll
    for (int p = 0; p < 4; ++p) {
        int idx = tid + p * 256;
        int row = idx >> 3, c8 = (idx & 7) * 8;
        *(uint4*)&Qs[row * 72 + c8] =
            *(const uint4*)(Qg + (size_t)(b * LQPAD + qbase + row) * D_ + h * HD_ + c8);
    }
    __syncthreads();

    uint32_t qa[4][4];
#pragma unroll
    for (int kc = 0; kc < 4; ++kc) {
        qa[kc][0] = *(const uint32_t*)&Qs[rl0 * 72 + kc * 16 + 2 * t4];
        qa[kc][1] = *(const uint32_t*)&Qs[rl1 * 72 + kc * 16 + 2 * t4];
        qa[kc][2] = *(const uint32_t*)&Qs[rl0 * 72 + kc * 16 + 2 * t4 + 8];
        qa[kc][3] = *(const uint32_t*)&Qs[rl1 * 72 + kc * 16 + 2 * t4 + 8];
    }

    float4 oacc[8];
#pragma unroll
    for (int i = 0; i < 8; ++i) oacc[i] = make_float4(0.f, 0.f, 0.f, 0.f);
    float4 lacc = make_float4(0.f, 0.f, 0.f, 0.f);   // col0 holds row sums of P

#pragma unroll 1
    for (int kt = 0; kt < nkt; ++kt) {
        const int s = kt & 1;
        __syncthreads();
        issue(kt + 1, s ^ 1);
        CP_COMMIT();
        CP_WAIT1();
        __syncthreads();

        const uint32_t ksb = ks_u + (uint32_t)(s * KSB);
        const uint32_t vsb = vs_u + (uint32_t)(s * KSB);
        const int* pd_ = padi + s * 64;

        // S = Q K^T
        float4 sacc[8];
#pragma unroll
        for (int nt = 0; nt < 8; ++nt) sacc[nt] = make_float4(0.f, 0.f, 0.f, 0.f);
#pragma unroll
        for (int kc = 0; kc < 4; ++kc) {
#pragma unroll
            for (int ntp = 0; ntp < 4; ++ntp) {
                uint32_t b0, b1, b2, b3;
                uint32_t addr = ksb +
                    (uint32_t)(((ntp * 16 + (lt >> 1) * 8 + lr8) * 72) + kc * 16 + (lt & 1) * 8) * 2;
                ldsm4(b0, b1, b2, b3, addr);
                mma16(sacc[2 * ntp], qa[kc], b0, b1);
                mma16(sacc[2 * ntp + 1], qa[kc], b2, b3);
            }
        }

        // Mask (pad + causal); scores bounded, so NO max subtraction needed
        const int moff = kt * 64 - qbase - 1536;
        const bool dopad = (kt < 32);
#pragma unroll
        for (int nt = 0; nt < 8; ++nt) {
            int j0 = nt * 8 + 2 * t4, j1 = j0 + 1;
            float p0 = (dopad && pd_[j0] == 0) ? -1e30f : 0.f;
            float p1 = (dopad && pd_[j1] == 0) ? -1e30f : 0.f;
            sacc[nt].x += p0; sacc[nt].y += p1;
            sacc[nt].z += p0; sacc[nt].w += p1;
            if (moff > -64) {
                if (j0 + moff > rl0) sacc[nt].x = -1e30f;
                if (j1 + moff > rl0) sacc[nt].y = -1e30f;
                if (j0 + moff > rl1) sacc[nt].z = -1e30f;
                if (j1 + moff > rl1) sacc[nt].w = -1e30f;
            }
        }

        // P = exp2(S) in f16x2 (masked -> -inf -> 0), then O += P V and
        // l += P @ ones (col-0 ones B fragment).
#pragma unroll
        for (int jc = 0; jc < 4; ++jc) {
            uint32_t pa[4];
            pa[0] = h2exp2(packh2(sacc[2 * jc].x, sacc[2 * jc].y));
            pa[1] = h2exp2(packh2(sacc[2 * jc].z, sacc[2 * jc].w));
            pa[2] = h2exp2(packh2(sacc[2 * jc + 1].x, sacc[2 * jc + 1].y));
            pa[3] = h2exp2(packh2(sacc[2 * jc + 1].z, sacc[2 * jc + 1].w));
            mma16(lacc, pa, ones, ones);
#pragma unroll
            for (int dtp = 0; dtp < 4; ++dtp) {
                uint32_t v0, v1, v2, v3;
                uint32_t addr = vsb +
                    (uint32_t)(((jc * 16 + (lt & 1) * 8 + lr8) * 72) + (dtp * 2 + (lt >> 1)) * 8) * 2;
                ldsm4t(v0, v1, v2, v3, addr);
                mma16(oacc[2 * dtp], pa, v0, v1);
                mma16(oacc[2 * dtp + 1], pa, v2, v3);
            }
        }
    }

    // Recover row sums from col 0 of lacc (held by t4==0 lane of each quad)
    float l0 = __shfl_sync(0xffffffffu, lacc.x, lane & 28);
    float l1 = __shfl_sync(0xffffffffu, lacc.z, lane & 28);

    // Epilogue: normalize, round to tf32 (feeds out-proj), store fp32
    float il0 = 1.f / l0, il1 = 1.f / l1;
#pragma unroll
    for (int dt = 0; dt < 8; ++dt) {
        int col = h * HD_ + dt * 8 + 2 * t4;
        size_t r0 = (size_t)(b * LQPAD + qbase + rl0) * D_ + col;
        size_t r1 = (size_t)(b * LQPAD + qbase + rl1) * D_ + col;
        *(float2*)(Og + r0) = make_float2(rtf(oacc[dt].x * il0), rtf(oacc[dt].y * il0));
        *(float2*)(Og + r1) = make_float2(rtf(oacc[dt].z * il1), rtf(oacc[dt].w * il1));
    }
}

// ---------------------------------------------------------------------------
extern "C" void kernel_launch(void* const* d_in, const int* in_sizes, int n_in,
                              void* d_out, int out_size) {
    const float* x     = (const float*)d_in[0];
    const int*   pad   = (const int*)d_in[1];
    const float* wq_sw = (const float*)d_in[4];
    const float* wq_sb = (const float*)d_in[5];
    const float* wq_nw = (const float*)d_in[6];
    const float* wq_nb = (const float*)d_in[7];
    const float* wk_sw = (const float*)d_in[8];
    const float* wk_sb = (const float*)d_in[9];
    const float* wk_nw = (const float*)d_in[10];
    const float* wk_nb = (const float*)d_in[11];
    const float* wv_sw = (const float*)d_in[12];
    const float* wv_sb = (const float*)d_in[13];
    const float* wv_nw = (const float*)d_in[14];
    const float* wv_nb = (const float*)d_in[15];
    const float* out_w = (const float*)d_in[16];
    const float* out_b = (const float*)d_in[17];
    float* out = (float*)d_out;

    __half *Kp, *Vp, *Qp;
    float *Ap, *Pp, *Xr, *Wr;
    cudaGetSymbolAddress((void**)&Kp, g_K);
    cudaGetSymbolAddress((void**)&Vp, g_V);
    cudaGetSymbolAddress((void**)&Qp, g_Q);
    cudaGetSymbolAddress((void**)&Ap, g_A);
    cudaGetSymbolAddress((void**)&Pp, g_Part);
    cudaGetSymbolAddress((void**)&Xr, g_Xr);
    cudaGetSymbolAddress((void**)&Wr, g_Wr);

    cudaFuncSetAttribute((const void*)mega_proj, cudaFuncAttributeMaxDynamicSharedMemorySize, PJ_SMEM);
    cudaFuncSetAttribute((const void*)proj_out, cudaFuncAttributeMaxDynamicSharedMemorySize, PJ_SMEM);
    cudaFuncSetAttribute((const void*)attn_mma, cudaFuncAttributeMaxDynamicSharedMemorySize, ATT_SMEM);

    // Prep rounding: x (8448 blocks) + 4 weights (1024 blocks)
    round_all<<<8448 + 1024, 256>>>(x, wk_sw, wv_sw, wq_sw, out_w, Xr, Wr);

    // Fused projection phase
    mega_proj<<<1536, 256, PJ_SMEM>>>(Xr, x, Wr, wk_sb, wv_sb, wq_sb,
                                      wk_nw, wv_nw, wq_nw, Kp, Vp, Qp, Pp);
    ns_reduce_all<<<dim3(64, 3), 512>>>(Pp, wk_nb, wv_nb, wq_nb, Kp, Vp, Qp);

    // Attention (fp16 core, no-max softmax)
    attn_mma<<<320, 256, ATT_SMEM>>>(Qp, Kp, Vp, pad, Ap);

    // Output projection (tf32)
    proj_out<<<dim3(36, 4), 256, PJ_SMEM>>>(Ap, Wr + 3 * WSZ, out_b, out);
}

// round 11
// speedup vs baseline: 2.1139x; 1.0455x over previous
#include <cuda_runtime.h>
#include <cuda_fp16.h>
#include <cstdint>

// Problem constants
#define B_      8
#define D_      512
#define H_      8
#define HD_     64
#define L_NS_   64
#define L_S_    2048
#define L_TOT   2112
#define LS_OUT  512
#define LQ_     576
#define LQPAD   640

// Q scale: 1/sqrt(64) * log2(e)  (exp2 domain)
#define SCL 0.18033688011112042f

// Scratch (allocation-free device globals)
__device__ __half g_K[B_ * L_TOT * D_];
__device__ __half g_V[B_ * L_TOT * D_];
__device__ __half g_Q[B_ * LQPAD * D_];          // rows 576-639 stay zero
__device__ float  g_A[B_ * LQPAD * D_];
__device__ float  g_Part[3 * 4 * 64 * B_ * D_];
__device__ float  g_Xr[B_ * L_TOT * D_];         // tf32-rounded x
__device__ float  g_Wr[4 * D_ * D_];             // rounded wk_sw, wv_sw, wq_sw, out_w
__device__ __half g_PadH[B_ * L_S_];             // fp16 0/1 pad mask

#define WSZ ((size_t)D_ * D_)
#define PARTSZ ((size_t)4 * 64 * B_ * D_)

// ---------------------------------------------------------------------------
// Helpers
// ---------------------------------------------------------------------------
__device__ __forceinline__ uint32_t smem_u32(const void* p) {
    uint32_t a;
    asm("{ .reg .u64 t; cvta.to.shared.u64 t, %1; cvt.u32.u64 %0, t; }" : "=r"(a) : "l"(p));
    return a;
}
__device__ __forceinline__ uint32_t cvt_tf32(float x) {
    uint32_t u; asm("cvt.rna.tf32.f32 %0, %1;" : "=r"(u) : "f"(x)); return u;
}
__device__ __forceinline__ float uf(uint32_t u) { return __uint_as_float(u); }
__device__ __forceinline__ uint32_t fu(float f) { return __float_as_uint(f); }
__device__ __forceinline__ float rtf(float x) { return uf(cvt_tf32(x)); }
__device__ __forceinline__ uint32_t packh2(float a, float b) {
    __half2 h = __floats2half2_rn(a, b);
    return *(uint32_t*)&h;
}
__device__ __forceinline__ uint32_t h2exp2(uint32_t h) {
    uint32_t r; asm("ex2.approx.f16x2 %0, %1;" : "=r"(r) : "r"(h)); return r;
}

__device__ __forceinline__ void mma8(float4& d, const uint32_t a[4], uint32_t b0, uint32_t b1) {
    asm volatile(
        "mma.sync.aligned.m16n8k8.row.col.f32.tf32.tf32.f32 "
        "{%0,%1,%2,%3}, {%4,%5,%6,%7}, {%8,%9}, {%0,%1,%2,%3};"
        : "+f"(d.x), "+f"(d.y), "+f"(d.z), "+f"(d.w)
        : "r"(a[0]), "r"(a[1]), "r"(a[2]), "r"(a[3]), "r"(b0), "r"(b1));
}
__device__ __forceinline__ void mma16(float4& d, const uint32_t a[4], uint32_t b0, uint32_t b1) {
    asm volatile(
        "mma.sync.aligned.m16n8k16.row.col.f32.f16.f16.f32 "
        "{%0,%1,%2,%3}, {%4,%5,%6,%7}, {%8,%9}, {%0,%1,%2,%3};"
        : "+f"(d.x), "+f"(d.y), "+f"(d.z), "+f"(d.w)
        : "r"(a[0]), "r"(a[1]), "r"(a[2]), "r"(a[3]), "r"(b0), "r"(b1));
}
__device__ __forceinline__ void ldsm4(uint32_t& r0, uint32_t& r1, uint32_t& r2, uint32_t& r3,
                                      uint32_t addr) {
    asm volatile("ldmatrix.sync.aligned.m8n8.x4.shared.b16 {%0,%1,%2,%3}, [%4];"
                 : "=r"(r0), "=r"(r1), "=r"(r2), "=r"(r3) : "r"(addr));
}
__device__ __forceinline__ void ldsm4t(uint32_t& r0, uint32_t& r1, uint32_t& r2, uint32_t& r3,
                                       uint32_t addr) {
    asm volatile("ldmatrix.sync.aligned.m8n8.x4.trans.shared.b16 {%0,%1,%2,%3}, [%4];"
                 : "=r"(r0), "=r"(r1), "=r"(r2), "=r"(r3) : "r"(addr));
}
__device__ __forceinline__ void cp16(uint32_t dst, const void* src) {
    asm volatile("cp.async.cg.shared.global [%0], [%1], 16;" :: "r"(dst), "l"(src));
}
#define CP_COMMIT() asm volatile("cp.async.commit_group;" ::: "memory")
#define CP_WAIT1()  asm volatile("cp.async.wait_group 1;" ::: "memory")

// ---------------------------------------------------------------------------
// Fused rounding prep: x, 4 weight matrices, pad->fp16
// ---------------------------------------------------------------------------
#define XN4L ((long)B_ * L_TOT * D_ / 4)

__global__ __launch_bounds__(256)
void round_all(const float* __restrict__ x,
               const float* __restrict__ w0, const float* __restrict__ w1,
               const float* __restrict__ w2, const float* __restrict__ w3,
               const int* __restrict__ pad,
               float* __restrict__ Xr, float* __restrict__ Wr,
               __half* __restrict__ PadH) {
    long i = (long)blockIdx.x * 256 + threadIdx.x;
    if (i < XN4L) {
        float4 v = ((const float4*)x)[i];
        v.x = rtf(v.x); v.y = rtf(v.y); v.z = rtf(v.z); v.w = rtf(v.w);
        ((float4*)Xr)[i] = v;
        return;
    }
    long j = i - XN4L;
    if (j < 262144) {
        int which = (int)(j >> 16);
        long off = j & 65535;
        const float* w = (which == 0) ? w0 : (which == 1) ? w1 : (which == 2) ? w2 : w3;
        float4 v = ((const float4*)w)[off];
        v.x = rtf(v.x); v.y = rtf(v.y); v.z = rtf(v.z); v.w = rtf(v.w);
        ((float4*)(Wr + (size_t)which * WSZ))[off] = v;
        return;
    }
    long k = j - 262144;     // 0..2047, each converts 8 pad ints
    if (k < (long)(B_ * L_S_ / 8)) {
        long base = k * 8;
#pragma unroll
        for (int q = 0; q < 8; ++q)
            PadH[base + q] = __int2half_rn(pad[base + q] ? 1 : 0);
    }
}

// ---------------------------------------------------------------------------
// Dense projection body (tf32 mma.sync, 3-stage cp.async)
// RND: 0 = fp32 out; 1 = fp16 out (K/V); 2 = fp16 out * SCL (Q).
// PADV: multiply output rows by pad mask (V projection; zeroes padded tokens).
// ---------------------------------------------------------------------------
template <int MODE> __device__ __forceinline__ int arow_of(int mi) {
    if (MODE == 0) return (mi >> 11) * L_TOT + (mi & 2047);
    if (MODE == 1) return (mi >> 9) * L_TOT + 1536 + (mi & 511);
    return ((unsigned)mi / 576) * LQPAD + ((unsigned)mi % 576);
}
template <int MODE> __device__ __forceinline__ int crow_of(int mi) {
    if (MODE == 0) return (mi >> 11) * L_TOT + (mi & 2047);
    if (MODE == 1) return (mi >> 9) * LQPAD + (mi & 511);
    return mi;
}

#define PJ_AS 2560
#define PJ_WS 2176
#define PJ_SMEM (3 * (PJ_AS + PJ_WS) * 4)

template <int MODE, int RND, int PADV>
__device__ __forceinline__
void proj_body(float* sm, int m0, int n0,
               const float* __restrict__ A, const float* __restrict__ W,
               const float* __restrict__ bias, void* __restrict__ C,
               const int* __restrict__ pad) {
    float* As = sm;
    float* Ws = sm + 3 * PJ_AS;
    const uint32_t as_u = smem_u32(As), ws_u = smem_u32(Ws);

    const int tid = threadIdx.x, lane = tid & 31;
    const int warp = tid >> 5, wm = warp >> 2, wn = warp & 3;
    const int g = lane >> 2, t4 = lane & 3;

    const int lr = tid >> 2, lk = (tid & 3) * 4;
    const float* pA0 = A + (size_t)arow_of<MODE>(m0 + lr) * D_ + lk;
    const float* pA1 = A + (size_t)arow_of<MODE>(m0 + 64 + lr) * D_ + lk;
    const int kr0 = tid >> 5, kr1 = kr0 + 8;
    const int nn = (tid & 31) * 4;
    const float* pW = W + n0;

    auto issue = [&](int c, int s) {
        const int k0 = c * 16;
        uint32_t ad = as_u + (uint32_t)(s * PJ_AS) * 4;
        cp16(ad + (uint32_t)(lr * 20 + lk) * 4, pA0 + k0);
        cp16(ad + (uint32_t)((lr + 64) * 20 + lk) * 4, pA1 + k0);
        uint32_t wd = ws_u + (uint32_t)(s * PJ_WS) * 4;
        cp16(wd + (uint32_t)(kr0 * 136 + nn) * 4, pW + (size_t)(k0 + kr0) * D_ + nn);
        cp16(wd + (uint32_t)(kr1 * 136 + nn) * 4, pW + (size_t)(k0 + kr1) * D_ + nn);
    };

    float4 acc[4][4];
#pragma unroll
    for (int i = 0; i < 4; ++i)
#pragma unroll
        for (int j = 0; j < 4; ++j) acc[i][j] = make_float4(0.f, 0.f, 0.f, 0.f);

    issue(0, 0); CP_COMMIT();
    issue(1, 1); CP_COMMIT();

#pragma unroll 1
    for (int c = 0; c < 32; ++c) {
        const int s = c % 3;
        CP_WAIT1();
        __syncthreads();
        if (c + 2 < 32) issue(c + 2, (c + 2) % 3);
        CP_COMMIT();

        const float* as_ = As + s * PJ_AS;
        const float* ws_ = Ws + s * PJ_WS;
#pragma unroll
        for (int kc = 0; kc < 2; ++kc) {
            const int kb = kc * 8;
            uint32_t af[4][4], bf[4][2];
#pragma unroll
            for (int mi = 0; mi < 4; ++mi) {
                int row = wm * 64 + mi * 16 + g;
                af[mi][0] = fu(as_[row * 20 + kb + t4]);
                af[mi][1] = fu(as_[(row + 8) * 20 + kb + t4]);
                af[mi][2] = fu(as_[row * 20 + kb + t4 + 4]);
                af[mi][3] = fu(as_[(row + 8) * 20 + kb + t4 + 4]);
            }
#pragma unroll
            for (int ni = 0; ni < 4; ++ni) {
                int col = wn * 32 + ni * 8 + g;
                bf[ni][0] = fu(ws_[(kb + t4) * 136 + col]);
                bf[ni][1] = fu(ws_[(kb + t4 + 4) * 136 + col]);
            }
#pragma unroll
            for (int mi = 0; mi < 4; ++mi)
#pragma unroll
                for (int ni = 0; ni < 4; ++ni)
                    mma8(acc[mi][ni], af[mi], bf[ni][0], bf[ni][1]);
        }
    }

    // Pad multipliers for V projection (one per owned row)
    float pm[4][2];
    if (PADV) {
#pragma unroll
        for (int mi = 0; mi < 4; ++mi) {
            int mr0 = m0 + wm * 64 + mi * 16 + g;
            int mr1 = mr0 + 8;
            pm[mi][0] = pad[(mr0 >> 11) * L_S_ + (mr0 & 2047)] ? 1.f : 0.f;
            pm[mi][1] = pad[(mr1 >> 11) * L_S_ + (mr1 & 2047)] ? 1.f : 0.f;
        }
    }

#pragma unroll
    for (int ni = 0; ni < 4; ++ni) {
        int col = n0 + wn * 32 + ni * 8 + 2 * t4;
        float2 bv = *(const float2*)(bias + col);
#pragma unroll
        for (int mi = 0; mi < 4; ++mi) {
            int r0 = crow_of<MODE>(m0 + wm * 64 + mi * 16 + g);
            int r1 = crow_of<MODE>(m0 + wm * 64 + mi * 16 + g + 8);
            float o0 = acc[mi][ni].x + bv.x, o1 = acc[mi][ni].y + bv.y;
            float o2 = acc[mi][ni].z + bv.x, o3 = acc[mi][ni].w + bv.y;
            if (PADV) { o0 *= pm[mi][0]; o1 *= pm[mi][0]; o2 *= pm[mi][1]; o3 *= pm[mi][1]; }
            if (RND == 0) {
                *(float2*)((float*)C + (size_t)r0 * D_ + col) = make_float2(o0, o1);
                *(float2*)((float*)C + (size_t)r1 * D_ + col) = make_float2(o2, o3);
            } else {
                if (RND == 2) { o0 *= SCL; o1 *= SCL; o2 *= SCL; o3 *= SCL; }
                *(__half2*)((__half*)C + (size_t)r0 * D_ + col) = __floats2half2_rn(o0, o1);
                *(__half2*)((__half*)C + (size_t)r1 * D_ + col) = __floats2half2_rn(o2, o3);
            }
        }
    }
}

// ---------------------------------------------------------------------------
// ns GEMV body (fp32 exact)
// ---------------------------------------------------------------------------
__device__ __forceinline__
void ns_body(float* sm, int ns_idx, const float* __restrict__ x,
             const float* __restrict__ wk_nw, const float* __restrict__ wv_nw,
             const float* __restrict__ wq_nw, float* __restrict__ part) {
    const int p = ns_idx >> 7;
    const int rem = ns_idx & 127;
    const int n = rem >> 1;
    const int kp = rem & 1;
    const int tid = threadIdx.x;
    const int half = tid >> 7, t = tid & 127;
    const int kz = kp * 2 + half;

    float* xs = sm + half * (B_ * 128);
#pragma unroll
    for (int it = 0; it < 2; ++it) {
        int idx = t + it * 128;
        int b = idx >> 5, k4 = (idx & 31) << 2;
        *(float4*)&xs[b * 128 + k4] =
            *(const float4*)(x + (size_t)(b * L_TOT + L_S_ + n) * D_ + kz * 128 + k4);
    }
    __syncthreads();

    const float* nw = (p == 0) ? wk_nw : (p == 1) ? wv_nw : wq_nw;
    const int col4 = t * 4;
    float4 acc[B_];
#pragma unroll
    for (int b = 0; b < B_; ++b) acc[b] = make_float4(0.f, 0.f, 0.f, 0.f);

    const float* wp = nw + (size_t)n * D_ * D_ + (size_t)(kz * 128) * D_ + col4;
#pragma unroll 8
    for (int k = 0; k < 128; ++k) {
        float4 w = *(const float4*)(wp + (size_t)k * D_);
#pragma unroll
        for (int b = 0; b < B_; ++b) {
            float xv = xs[b * 128 + k];
            acc[b].x += xv * w.x; acc[b].y += xv * w.y;
            acc[b].z += xv * w.z; acc[b].w += xv * w.w;
        }
    }
    float* pr = part + (size_t)p * PARTSZ;
#pragma unroll
    for (int b = 0; b < B_; ++b)
        *(float4*)&pr[(size_t)(((kz * 64 + n) * B_) + b) * D_ + col4] = acc[b];
}

// ---------------------------------------------------------------------------
// Mega projection kernel: 1536 blocks, 1:3 interleave of ns : mma blocks.
// ---------------------------------------------------------------------------
__global__ __launch_bounds__(256, 2)
void mega_proj(const float* __restrict__ Xr, const float* __restrict__ x,
               const float* __restrict__ Wr,
               const float* __restrict__ wk_sb, const float* __restrict__ wv_sb,
               const float* __restrict__ wq_sb,
               const float* __restrict__ wk_nw, const float* __restrict__ wv_nw,
               const float* __restrict__ wq_nw,
               const int* __restrict__ pad,
               __half* __restrict__ Kp, __half* __restrict__ Vp,
               __half* __restrict__ Qp, float* __restrict__ part) {
    extern __shared__ float sm[];
    const int bid = blockIdx.x;
    const int group = bid >> 2, r = bid & 3;

    if (r == 0) {
        ns_body(sm, group, x, wk_nw, wv_nw, wq_nw, part);
        return;
    }
    const int mi = group * 3 + (r - 1);
    if (mi < 512) {
        proj_body<0, 1, 0>(sm, (mi & 127) * 128, (mi >> 7) * 128, Xr, Wr, wk_sb, Kp, pad);
    } else if (mi < 1024) {
        int i = mi - 512;
        proj_body<0, 1, 1>(sm, (i & 127) * 128, (i >> 7) * 128, Xr, Wr + WSZ, wv_sb, Vp, pad);
    } else {
        int i = mi - 1024;
        proj_body<1, 2, 0>(sm, (i & 31) * 128, (i >> 5) * 128, Xr, Wr + 2 * WSZ, wq_sb, Qp, pad);
    }
}

__global__ __launch_bounds__(256, 2)
void proj_out(const float* __restrict__ A, const float* __restrict__ W,
              const float* __restrict__ bias, float* __restrict__ C) {
    extern __shared__ float sm[];
    proj_body<2, 0, 0>(sm, blockIdx.x * 128, blockIdx.y * 128, A, W, bias, C, nullptr);
}

// ---------------------------------------------------------------------------
// Fused ns reduce: grid (64 tokens, 3 projections) -> fp16 outputs
// ---------------------------------------------------------------------------
__global__ __launch_bounds__(512)
void ns_reduce_all(const float* __restrict__ part,
                   const float* __restrict__ nbk, const float* __restrict__ nbv,
                   const float* __restrict__ nbq,
                   __half* __restrict__ Kp, __half* __restrict__ Vp,
                   __half* __restrict__ Qp) {
    const int n = blockIdx.x, p = blockIdx.y;
    const int col = threadIdx.x;
    const float* nb = (p == 0) ? nbk : (p == 1) ? nbv : nbq;
    __half* out = (p == 0) ? Kp : (p == 1) ? Vp : Qp;
    const float* pr = part + (size_t)p * PARTSZ;
    const float bias = nb[n * D_ + col];
    const bool qm = (p == 2);
#pragma unroll
    for (int b = 0; b < B_; ++b) {
        float s = bias;
#pragma unroll
        for (int kz = 0; kz < 4; ++kz)
            s += pr[(size_t)(((kz * 64 + n) * B_) + b) * D_ + col];
        if (qm) s *= SCL;
        int orow = qm ? (b * LQPAD + LS_OUT + n) : (b * L_TOT + L_S_ + n);
        out[(size_t)orow * D_ + col] = __float2half_rn(s);
    }
}

// ---------------------------------------------------------------------------
// Flash attention, fp16 mma + ldmatrix; no-max softmax; pad via V-zero +
// mask-column l MMA; one __syncthreads per tile; 2-stage cp.async rings.
// ---------------------------------------------------------------------------
#define KSB 9216                         // 64*72*2 bytes per stage
#define ATT_QB (128 * 72 * 2)
#define PDH_OFF (ATT_QB + 4 * KSB)       // 2 stages x 128 B
#define ATT_SMEM (PDH_OFF + 2 * 128)

__global__ __launch_bounds__(256, 2)
void attn_mma(const __half* __restrict__ Qg, const __half* __restrict__ Kg,
              const __half* __restrict__ Vg, const __half* __restrict__ padh,
              float* __restrict__ Og) {
    extern __shared__ char smc[];
    __half* Qs = (__half*)smc;
    const uint32_t base = smem_u32(smc);
    const uint32_t ks_u = base + ATT_QB;
    const uint32_t vs_u = base + ATT_QB + 2 * KSB;
    const uint32_t pd_u = base + PDH_OFF;

    // Load-balanced mapping: heavy q-tiles first, mirrored second half-wave.
    const int l = blockIdx.x;
    const int s_ = (l < 148) ? l : ((l < 296) ? (443 - l) : l);
    const int qt = 4 - (s_ >> 6);
    const int rem = s_ & 63;
    const int h = rem >> 3, b = rem & 7;

    const int tid = threadIdx.x, lane = tid & 31, w = tid >> 5;
    const int g = lane >> 2, t4 = lane & 3;
    const int lt = lane >> 3, lr8 = lane & 7;
    const int qbase = qt * 128;
    const int nkt = min(2 * qt + 26, 33);
    const int rl0 = 16 * w + g, rl1 = rl0 + 8;

    auto issue = [&](int kt, int s) {
        if (kt >= nkt) return;
        const int kb = kt * 64;
        const __half* Kb = Kg + (size_t)(b * L_TOT + kb) * D_ + h * HD_;
        const __half* Vb = Vg + (size_t)(b * L_TOT + kb) * D_ + h * HD_;
#pragma unroll
        for (int p = 0; p < 2; ++p) {
            int idx = tid + p * 256;
            int j = idx >> 3, c8 = (idx & 7) * 8;
            cp16(ks_u + (uint32_t)(s * KSB) + (uint32_t)(j * 72 + c8) * 2, Kb + (size_t)j * D_ + c8);
            cp16(vs_u + (uint32_t)(s * KSB) + (uint32_t)(j * 72 + c8) * 2, Vb + (size_t)j * D_ + c8);
        }
        if (kt < 32 && tid < 8)
            cp16(pd_u + (uint32_t)(s * 128 + tid * 16), padh + b * L_S_ + kb + tid * 8);
    };

    issue(0, 0); CP_COMMIT();

    // Stage Q (fp16, pre-scaled)
#pragma unroll
    for (int p = 0; p < 4; ++p) {
        int idx = tid + p * 256;
        int row = idx >> 3, c8 = (idx & 7) * 8;
        *(uint4*)&Qs[row * 72 + c8] =
            *(const uint4*)(Qg + (size_t)(b * LQPAD + qbase + row) * D_ + h * HD_ + c8);
    }
    __syncthreads();

    uint32_t qa[4][4];
#pragma unroll
    for (int kc = 0; kc < 4; ++kc) {
        qa[kc][0] = *(const uint32_t*)&Qs[rl0 * 72 + kc * 16 + 2 * t4];
        qa[kc][1] = *(const uint32_t*)&Qs[rl1 * 72 + kc * 16 + 2 * t4];
        qa[kc][2] = *(const uint32_t*)&Qs[rl0 * 72 + kc * 16 + 2 * t4 + 8];
        qa[kc][3] = *(const uint32_t*)&Qs[rl1 * 72 + kc * 16 + 2 * t4 + 8];
    }

    float4 oacc[8];
#pragma unroll
    for (int i = 0; i < 8; ++i) oacc[i] = make_float4(0.f, 0.f, 0.f, 0.f);
    float4 lacc = make_float4(0.f, 0.f, 0.f, 0.f);   // col0 holds row sums of P

#pragma unroll 1
    for (int kt = 0; kt < nkt; ++kt) {
        const int s = kt & 1;
        __syncthreads();              // all threads done reading buffer s^1
        issue(kt + 1, s ^ 1);
        CP_COMMIT();
        CP_WAIT1();                   // group kt (buffer s) complete

        const uint32_t ksb = ks_u + (uint32_t)(s * KSB);
        const uint32_t vsb = vs_u + (uint32_t)(s * KSB);
        const __half* ph = (const __half*)(smc + PDH_OFF + s * 128);

        // S = Q K^T
        float4 sacc[8];
#pragma unroll
        for (int nt = 0; nt < 8; ++nt) sacc[nt] = make_float4(0.f, 0.f, 0.f, 0.f);
#pragma unroll
        for (int kc = 0; kc < 4; ++kc) {
#pragma unroll
            for (int ntp = 0; ntp < 4; ++ntp) {
                uint32_t b0, b1, b2, b3;
                uint32_t addr = ksb +
                    (uint32_t)(((ntp * 16 + (lt >> 1) * 8 + lr8) * 72) + kc * 16 + (lt & 1) * 8) * 2;
                ldsm4(b0, b1, b2, b3, addr);
                mma16(sacc[2 * ntp], qa[kc], b0, b1);
                mma16(sacc[2 * ntp + 1], qa[kc], b2, b3);
            }
        }

        // Causal mask only (last 2 tiles); pad handled via V-zero + mask column
        const int moff = kt * 64 - qbase - 1536;
        if (moff > -64) {
#pragma unroll
            for (int nt = 0; nt < 8; ++nt) {
                int j0 = nt * 8 + 2 * t4, j1 = j0 + 1;
                if (j0 + moff > rl0) sacc[nt].x = -1e30f;
                if (j1 + moff > rl0) sacc[nt].y = -1e30f;
                if (j0 + moff > rl1) sacc[nt].z = -1e30f;
                if (j1 + moff > rl1) sacc[nt].w = -1e30f;
            }
        }

        // P = exp2(S) f16x2; O += P V; l += P @ maskcol
        const bool dopad = (kt < 32);
#pragma unroll
        for (int jc = 0; jc < 4; ++jc) {
            uint32_t pa[4];
            pa[0] = h2exp2(packh2(sacc[2 * jc].x, sacc[2 * jc].y));
            pa[1] = h2exp2(packh2(sacc[2 * jc].z, sacc[2 * jc].w));
            pa[2] = h2exp2(packh2(sacc[2 * jc + 1].x, sacc[2 * jc + 1].y));
            pa[3] = h2exp2(packh2(sacc[2 * jc + 1].z, sacc[2 * jc + 1].w));
            uint32_t m0c = 0, m1c = 0;
            if (lane < 4) {
                if (dopad) {
                    m0c = *(const uint32_t*)&ph[jc * 16 + 2 * lane];
                    m1c = *(const uint32_t*)&ph[jc * 16 + 2 * lane + 8];
                } else {
                    m0c = 0x3C003C00u; m1c = 0x3C003C00u;
                }
            }
            mma16(lacc, pa, m0c, m1c);
#pragma unroll
            for (int dtp = 0; dtp < 4; ++dtp) {
                uint32_t v0, v1, v2, v3;
                uint32_t addr = vsb +
                    (uint32_t)(((jc * 16 + (lt & 1) * 8 + lr8) * 72) + (dtp * 2 + (lt >> 1)) * 8) * 2;
                ldsm4t(v0, v1, v2, v3, addr);
                mma16(oacc[2 * dtp], pa, v0, v1);
                mma16(oacc[2 * dtp + 1], pa, v2, v3);
            }
        }
    }

    // Recover row sums from col 0 of lacc
    float l0 = __shfl_sync(0xffffffffu, lacc.x, lane & 28);
    float l1 = __shfl_sync(0xffffffffu, lacc.z, lane & 28);

    // Epilogue: normalize, round to tf32 (feeds out-proj), store fp32
    float il0 = 1.f / l0, il1 = 1.f / l1;
#pragma unroll
    for (int dt = 0; dt < 8; ++dt) {
        int col = h * HD_ + dt * 8 + 2 * t4;
        size_t r0 = (size_t)(b * LQPAD + qbase + rl0) * D_ + col;
        size_t r1 = (size_t)(b * LQPAD + qbase + rl1) * D_ + col;
        *(float2*)(Og + r0) = make_float2(rtf(oacc[dt].x * il0), rtf(oacc[dt].y * il0));
        *(float2*)(Og + r1) = make_float2(rtf(oacc[dt].z * il1), rtf(oacc[dt].w * il1));
    }
}

// ---------------------------------------------------------------------------
extern "C" void kernel_launch(void* const* d_in, const int* in_sizes, int n_in,
                              void* d_out, int out_size) {
    const float* x     = (const float*)d_in[0];
    const int*   pad   = (const int*)d_in[1];
    const float* wq_sw = (const float*)d_in[4];
    const float* wq_sb = (const float*)d_in[5];
    const float* wq_nw = (const float*)d_in[6];
    const float* wq_nb = (const float*)d_in[7];
    const float* wk_sw = (const float*)d_in[8];
    const float* wk_sb = (const float*)d_in[9];
    const float* wk_nw = (const float*)d_in[10];
    const float* wk_nb = (const float*)d_in[11];
    const float* wv_sw = (const float*)d_in[12];
    const float* wv_sb = (const float*)d_in[13];
    const float* wv_nw = (const float*)d_in[14];
    const float* wv_nb = (const float*)d_in[15];
    const float* out_w = (const float*)d_in[16];
    const float* out_b = (const float*)d_in[17];
    float* out = (float*)d_out;

    __half *Kp, *Vp, *Qp, *Ph;
    float *Ap, *Pp, *Xr, *Wr;
    cudaGetSymbolAddress((void**)&Kp, g_K);
    cudaGetSymbolAddress((void**)&Vp, g_V);
    cudaGetSymbolAddress((void**)&Qp, g_Q);
    cudaGetSymbolAddress((void**)&Ap, g_A);
    cudaGetSymbolAddress((void**)&Pp, g_Part);
    cudaGetSymbolAddress((void**)&Xr, g_Xr);
    cudaGetSymbolAddress((void**)&Wr, g_Wr);
    cudaGetSymbolAddress((void**)&Ph, g_PadH);

    cudaFuncSetAttribute((const void*)mega_proj, cudaFuncAttributeMaxDynamicSharedMemorySize, PJ_SMEM);
    cudaFuncSetAttribute((const void*)proj_out, cudaFuncAttributeMaxDynamicSharedMemorySize, PJ_SMEM);
    cudaFuncSetAttribute((const void*)attn_mma, cudaFuncAttributeMaxDynamicSharedMemorySize, ATT_SMEM);

    // Prep: round x + 4 weights, convert pad to fp16 (8448 + 1024 + 8 blocks)
    round_all<<<8448 + 1024 + 8, 256>>>(x, wk_sw, wv_sw, wq_sw, out_w, pad, Xr, Wr, Ph);

    // Fused projection phase (V rows zeroed where padded)
    mega_proj<<<1536, 256, PJ_SMEM>>>(Xr, x, Wr, wk_sb, wv_sb, wq_sb,
                                      wk_nw, wv_nw, wq_nw, pad, Kp, Vp, Qp, Pp);
    ns_reduce_all<<<dim3(64, 3), 512>>>(Pp, wk_nb, wv_nb, wq_nb, Kp, Vp, Qp);

    // Attention
    attn_mma<<<320, 256, ATT_SMEM>>>(Qp, Kp, Vp, Ph, Ap);

    // Output projection (tf32)
    proj_out<<<dim3(36, 4), 256, PJ_SMEM>>>(Ap, Wr + 3 * WSZ, out_b, out);
}

// round 12
// speedup vs baseline: 2.8543x; 1.3503x over previous
#include <cuda_runtime.h>
#include <cuda_fp16.h>
#include <cstdint>

// Problem constants
#define B_      8
#define D_      512
#define H_      8
#define HD_     64
#define L_NS_   64
#define L_S_    2048
#define L_TOT   2112
#define LS_OUT  512
#define LQ_     576
#define LQPAD   640

// Q scale: 1/sqrt(64) * log2(e)  (exp2 domain)
#define SCL 0.18033688011112042f

// Scratch (allocation-free device globals)
__device__ __half g_K[B_ * L_TOT * D_];
__device__ __half g_V[B_ * L_TOT * D_];
__device__ __half g_Q[B_ * LQPAD * D_];          // rows 576-639 stay zero
__device__ __half g_A[B_ * LQPAD * D_];          // attention out (fp16)
__device__ float  g_Part[3 * 4 * 64 * B_ * D_];
__device__ __half g_Xh[B_ * L_TOT * D_];         // fp16 x
__device__ __half g_Wh[4 * D_ * D_];             // fp16 wk_sw, wv_sw, wq_sw, out_w
__device__ __half g_PadH[B_ * L_S_];             // fp16 0/1 pad mask

#define WSZ ((size_t)D_ * D_)
#define PARTSZ ((size_t)4 * 64 * B_ * D_)

// ---------------------------------------------------------------------------
// Helpers
// ---------------------------------------------------------------------------
__device__ __forceinline__ uint32_t smem_u32(const void* p) {
    uint32_t a;
    asm("{ .reg .u64 t; cvta.to.shared.u64 t, %1; cvt.u32.u64 %0, t; }" : "=r"(a) : "l"(p));
    return a;
}
__device__ __forceinline__ uint32_t packh2(float a, float b) {
    __half2 h = __floats2half2_rn(a, b);
    return *(uint32_t*)&h;
}
__device__ __forceinline__ uint32_t h2exp2(uint32_t h) {
    uint32_t r; asm("ex2.approx.f16x2 %0, %1;" : "=r"(r) : "r"(h)); return r;
}
__device__ __forceinline__ void mma16(float4& d, const uint32_t a[4], uint32_t b0, uint32_t b1) {
    asm volatile(
        "mma.sync.aligned.m16n8k16.row.col.f32.f16.f16.f32 "
        "{%0,%1,%2,%3}, {%4,%5,%6,%7}, {%8,%9}, {%0,%1,%2,%3};"
        : "+f"(d.x), "+f"(d.y), "+f"(d.z), "+f"(d.w)
        : "r"(a[0]), "r"(a[1]), "r"(a[2]), "r"(a[3]), "r"(b0), "r"(b1));
}
__device__ __forceinline__ void ldsm4(uint32_t& r0, uint32_t& r1, uint32_t& r2, uint32_t& r3,
                                      uint32_t addr) {
    asm volatile("ldmatrix.sync.aligned.m8n8.x4.shared.b16 {%0,%1,%2,%3}, [%4];"
                 : "=r"(r0), "=r"(r1), "=r"(r2), "=r"(r3) : "r"(addr));
}
__device__ __forceinline__ void ldsm4t(uint32_t& r0, uint32_t& r1, uint32_t& r2, uint32_t& r3,
                                       uint32_t addr) {
    asm volatile("ldmatrix.sync.aligned.m8n8.x4.trans.shared.b16 {%0,%1,%2,%3}, [%4];"
                 : "=r"(r0), "=r"(r1), "=r"(r2), "=r"(r3) : "r"(addr));
}
__device__ __forceinline__ void cp16(uint32_t dst, const void* src) {
    asm volatile("cp.async.cg.shared.global [%0], [%1], 16;" :: "r"(dst), "l"(src));
}
#define CP_COMMIT() asm volatile("cp.async.commit_group;" ::: "memory")
#define CP_WAIT1()  asm volatile("cp.async.wait_group 1;" ::: "memory")

// ---------------------------------------------------------------------------
// Fused prep: x->fp16, 4 weights->fp16, pad->fp16
// ---------------------------------------------------------------------------
#define XN4L ((long)B_ * L_TOT * D_ / 4)

__global__ __launch_bounds__(256)
void prep_all(const float* __restrict__ x,
              const float* __restrict__ w0, const float* __restrict__ w1,
              const float* __restrict__ w2, const float* __restrict__ w3,
              const int* __restrict__ pad,
              __half* __restrict__ Xh, __half* __restrict__ Wh,
              __half* __restrict__ PadH) {
    long i = (long)blockIdx.x * 256 + threadIdx.x;
    if (i < XN4L) {
        float4 v = ((const float4*)x)[i];
        __half2 h0 = __floats2half2_rn(v.x, v.y);
        __half2 h1 = __floats2half2_rn(v.z, v.w);
        ((__half2*)Xh)[2 * i] = h0;
        ((__half2*)Xh)[2 * i + 1] = h1;
        return;
    }
    long j = i - XN4L;
    if (j < 262144) {
        int which = (int)(j >> 16);
        long off = j & 65535;
        const float* w = (which == 0) ? w0 : (which == 1) ? w1 : (which == 2) ? w2 : w3;
        float4 v = ((const float4*)w)[off];
        __half2* dst = (__half2*)(Wh + (size_t)which * WSZ);
        dst[2 * off] = __floats2half2_rn(v.x, v.y);
        dst[2 * off + 1] = __floats2half2_rn(v.z, v.w);
        return;
    }
    long k = j - 262144;     // 0..2047, each converts 8 pad ints
    if (k < (long)(B_ * L_S_ / 8)) {
        long base = k * 8;
#pragma unroll
        for (int q = 0; q < 8; ++q)
            PadH[base + q] = __int2half_rn(pad[base + q] ? 1 : 0);
    }
}

// ---------------------------------------------------------------------------
// Dense projection body, fp16 mma m16n8k16 + ldmatrix, 3-stage cp.async.
// BK=32, 16 k-iterations. CTA 128x128, 8 warps (2m x 4n), warp tile 64x32.
// RND: 0 = fp32 out; 1 = fp16 out (K/V); 2 = fp16 out * SCL (Q).
// PADV: multiply output rows by pad mask (V projection).
// ---------------------------------------------------------------------------
template <int MODE> __device__ __forceinline__ int arow_of(int mi) {
    if (MODE == 0) return (mi >> 11) * L_TOT + (mi & 2047);
    if (MODE == 1) return (mi >> 9) * L_TOT + 1536 + (mi & 511);
    return ((unsigned)mi / 576) * LQPAD + ((unsigned)mi % 576);
}
template <int MODE> __device__ __forceinline__ int crow_of(int mi) {
    if (MODE == 0) return (mi >> 11) * L_TOT + (mi & 2047);
    if (MODE == 1) return (mi >> 9) * LQPAD + (mi & 511);
    return mi;
}

#define PH_AS (128 * 40)     // halves per A stage (32 data + 8 pad per row)
#define PH_WS (32 * 136)     // halves per W stage (128 data + 8 pad per row)
#define PJ_SMEM (3 * (PH_AS + PH_WS) * 2)

template <int MODE, int RND, int PADV>
__device__ __forceinline__
void proj_body(char* smc, int m0, int n0,
               const __half* __restrict__ A, const __half* __restrict__ W,
               const float* __restrict__ bias, void* __restrict__ C,
               const int* __restrict__ pad) {
    const uint32_t as_u = smem_u32(smc);
    const uint32_t ws_u = as_u + 3 * PH_AS * 2;

    const int tid = threadIdx.x, lane = tid & 31;
    const int warp = tid >> 5, wm = warp >> 2, wn = warp & 3;
    const int g = lane >> 2, t4 = lane & 3;
    const int lt = lane >> 3, lr8 = lane & 7;

    // Loader indices
    const int ar = tid >> 2, aseg = (tid & 3) * 8;       // A: rows ar, ar+64
    const __half* pA0 = A + (size_t)arow_of<MODE>(m0 + ar) * D_ + aseg;
    const __half* pA1 = A + (size_t)arow_of<MODE>(m0 + 64 + ar) * D_ + aseg;
    const int wr = tid >> 4, wseg = (tid & 15) * 8;      // W: rows wr, wr+16
    const __half* pW = W + n0 + wseg;

    auto issue = [&](int c, int s) {
        const int k0 = c * 32;
        uint32_t ad = as_u + (uint32_t)(s * PH_AS) * 2;
        cp16(ad + (uint32_t)(ar * 40 + aseg) * 2, pA0 + k0);
        cp16(ad + (uint32_t)((ar + 64) * 40 + aseg) * 2, pA1 + k0);
        uint32_t wd = ws_u + (uint32_t)(s * PH_WS) * 2;
        cp16(wd + (uint32_t)(wr * 136 + wseg) * 2, pW + (size_t)(k0 + wr) * D_);
        cp16(wd + (uint32_t)((wr + 16) * 136 + wseg) * 2, pW + (size_t)(k0 + wr + 16) * D_);
    };

    float4 acc[4][4];
#pragma unroll
    for (int i = 0; i < 4; ++i)
#pragma unroll
        for (int j = 0; j < 4; ++j) acc[i][j] = make_float4(0.f, 0.f, 0.f, 0.f);

    issue(0, 0); CP_COMMIT();
    issue(1, 1); CP_COMMIT();

#pragma unroll 1
    for (int c = 0; c < 16; ++c) {
        const int s = c % 3;
        CP_WAIT1();
        __syncthreads();
        if (c + 2 < 16) issue(c + 2, (c + 2) % 3);
        CP_COMMIT();

        const uint32_t as_ = as_u + (uint32_t)(s * PH_AS) * 2;
        const uint32_t ws_ = ws_u + (uint32_t)(s * PH_WS) * 2;
#pragma unroll
        for (int kc = 0; kc < 2; ++kc) {
            uint32_t af[4][4], bf[4][2];
#pragma unroll
            for (int mi = 0; mi < 4; ++mi) {
                uint32_t addr = as_ +
                    (uint32_t)(((wm * 64 + mi * 16 + (lane & 15)) * 40) + kc * 16 + (lane >> 4) * 8) * 2;
                ldsm4(af[mi][0], af[mi][1], af[mi][2], af[mi][3], addr);
            }
#pragma unroll
            for (int pr = 0; pr < 2; ++pr) {
                uint32_t addr = ws_ +
                    (uint32_t)(((kc * 16 + (lt & 1) * 8 + lr8) * 136) + wn * 32 + (pr * 2 + (lt >> 1)) * 8) * 2;
                ldsm4t(bf[2 * pr][0], bf[2 * pr][1], bf[2 * pr + 1][0], bf[2 * pr + 1][1], addr);
            }
#pragma unroll
            for (int mi = 0; mi < 4; ++mi)
#pragma unroll
                for (int ni = 0; ni < 4; ++ni)
                    mma16(acc[mi][ni], af[mi], bf[ni][0], bf[ni][1]);
        }
    }

    // Pad multipliers for V projection
    float pm[4][2];
    if (PADV) {
#pragma unroll
        for (int mi = 0; mi < 4; ++mi) {
            int mr0 = m0 + wm * 64 + mi * 16 + g;
            int mr1 = mr0 + 8;
            pm[mi][0] = pad[(mr0 >> 11) * L_S_ + (mr0 & 2047)] ? 1.f : 0.f;
            pm[mi][1] = pad[(mr1 >> 11) * L_S_ + (mr1 & 2047)] ? 1.f : 0.f;
        }
    }

#pragma unroll
    for (int ni = 0; ni < 4; ++ni) {
        int col = n0 + wn * 32 + ni * 8 + 2 * t4;
        float2 bv = *(const float2*)(bias + col);
#pragma unroll
        for (int mi = 0; mi < 4; ++mi) {
            int r0 = crow_of<MODE>(m0 + wm * 64 + mi * 16 + g);
            int r1 = crow_of<MODE>(m0 + wm * 64 + mi * 16 + g + 8);
            float o0 = acc[mi][ni].x + bv.x, o1 = acc[mi][ni].y + bv.y;
            float o2 = acc[mi][ni].z + bv.x, o3 = acc[mi][ni].w + bv.y;
            if (PADV) { o0 *= pm[mi][0]; o1 *= pm[mi][0]; o2 *= pm[mi][1]; o3 *= pm[mi][1]; }
            if (RND == 0) {
                *(float2*)((float*)C + (size_t)r0 * D_ + col) = make_float2(o0, o1);
                *(float2*)((float*)C + (size_t)r1 * D_ + col) = make_float2(o2, o3);
            } else {
                if (RND == 2) { o0 *= SCL; o1 *= SCL; o2 *= SCL; o3 *= SCL; }
                *(__half2*)((__half*)C + (size_t)r0 * D_ + col) = __floats2half2_rn(o0, o1);
                *(__half2*)((__half*)C + (size_t)r1 * D_ + col) = __floats2half2_rn(o2, o3);
            }
        }
    }
}

// ---------------------------------------------------------------------------
// ns GEMV body (fp32 exact)
// ---------------------------------------------------------------------------
__device__ __forceinline__
void ns_body(float* sm, int ns_idx, const float* __restrict__ x,
             const float* __restrict__ wk_nw, const float* __restrict__ wv_nw,
             const float* __restrict__ wq_nw, float* __restrict__ part) {
    const int p = ns_idx >> 7;
    const int rem = ns_idx & 127;
    const int n = rem >> 1;
    const int kp = rem & 1;
    const int tid = threadIdx.x;
    const int half = tid >> 7, t = tid & 127;
    const int kz = kp * 2 + half;

    float* xs = sm + half * (B_ * 128);
#pragma unroll
    for (int it = 0; it < 2; ++it) {
        int idx = t + it * 128;
        int b = idx >> 5, k4 = (idx & 31) << 2;
        *(float4*)&xs[b * 128 + k4] =
            *(const float4*)(x + (size_t)(b * L_TOT + L_S_ + n) * D_ + kz * 128 + k4);
    }
    __syncthreads();

    const float* nw = (p == 0) ? wk_nw : (p == 1) ? wv_nw : wq_nw;
    const int col4 = t * 4;
    float4 acc[B_];
#pragma unroll
    for (int b = 0; b < B_; ++b) acc[b] = make_float4(0.f, 0.f, 0.f, 0.f);

    const float* wp = nw + (size_t)n * D_ * D_ + (size_t)(kz * 128) * D_ + col4;
#pragma unroll 8
    for (int k = 0; k < 128; ++k) {
        float4 w = *(const float4*)(wp + (size_t)k * D_);
#pragma unroll
        for (int b = 0; b < B_; ++b) {
            float xv = xs[b * 128 + k];
            acc[b].x += xv * w.x; acc[b].y += xv * w.y;
            acc[b].z += xv * w.z; acc[b].w += xv * w.w;
        }
    }
    float* pr = part + (size_t)p * PARTSZ;
#pragma unroll
    for (int b = 0; b < B_; ++b)
        *(float4*)&pr[(size_t)(((kz * 64 + n) * B_) + b) * D_ + col4] = acc[b];
}

// ---------------------------------------------------------------------------
// Mega projection kernel: 1536 blocks, 1:3 interleave of ns : mma blocks.
// ---------------------------------------------------------------------------
__global__ __launch_bounds__(256, 2)
void mega_proj(const __half* __restrict__ Xh, const float* __restrict__ x,
               const __half* __restrict__ Wh,
               const float* __restrict__ wk_sb, const float* __restrict__ wv_sb,
               const float* __restrict__ wq_sb,
               const float* __restrict__ wk_nw, const float* __restrict__ wv_nw,
               const float* __restrict__ wq_nw,
               const int* __restrict__ pad,
               __half* __restrict__ Kp, __half* __restrict__ Vp,
               __half* __restrict__ Qp, float* __restrict__ part) {
    extern __shared__ char smc[];
    const int bid = blockIdx.x;
    const int group = bid >> 2, r = bid & 3;

    if (r == 0) {
        ns_body((float*)smc, group, x, wk_nw, wv_nw, wq_nw, part);
        return;
    }
    const int mi = group * 3 + (r - 1);
    if (mi < 512) {
        proj_body<0, 1, 0>(smc, (mi & 127) * 128, (mi >> 7) * 128, Xh, Wh, wk_sb, Kp, pad);
    } else if (mi < 1024) {
        int i = mi - 512;
        proj_body<0, 1, 1>(smc, (i & 127) * 128, (i >> 7) * 128, Xh, Wh + WSZ, wv_sb, Vp, pad);
    } else {
        int i = mi - 1024;
        proj_body<1, 2, 0>(smc, (i & 31) * 128, (i >> 5) * 128, Xh, Wh + 2 * WSZ, wq_sb, Qp, pad);
    }
}

__global__ __launch_bounds__(256, 2)
void proj_out(const __half* __restrict__ A, const __half* __restrict__ W,
              const float* __restrict__ bias, float* __restrict__ C) {
    extern __shared__ char smc[];
    proj_body<2, 0, 0>(smc, blockIdx.x * 128, blockIdx.y * 128, A, W, bias, C, nullptr);
}

// ---------------------------------------------------------------------------
// Fused ns reduce: grid (64 tokens, 3 projections) -> fp16 outputs
// ---------------------------------------------------------------------------
__global__ __launch_bounds__(512)
void ns_reduce_all(const float* __restrict__ part,
                   const float* __restrict__ nbk, const float* __restrict__ nbv,
                   const float* __restrict__ nbq,
                   __half* __restrict__ Kp, __half* __restrict__ Vp,
                   __half* __restrict__ Qp) {
    const int n = blockIdx.x, p = blockIdx.y;
    const int col = threadIdx.x;
    const float* nb = (p == 0) ? nbk : (p == 1) ? nbv : nbq;
    __half* out = (p == 0) ? Kp : (p == 1) ? Vp : Qp;
    const float* pr = part + (size_t)p * PARTSZ;
    const float bias = nb[n * D_ + col];
    const bool qm = (p == 2);
#pragma unroll
    for (int b = 0; b < B_; ++b) {
        float s = bias;
#pragma unroll
        for (int kz = 0; kz < 4; ++kz)
            s += pr[(size_t)(((kz * 64 + n) * B_) + b) * D_ + col];
        if (qm) s *= SCL;
        int orow = qm ? (b * LQPAD + LS_OUT + n) : (b * L_TOT + L_S_ + n);
        out[(size_t)orow * D_ + col] = __float2half_rn(s);
    }
}

// ---------------------------------------------------------------------------
// Flash attention (fp16 mma, no-max softmax, pad via V-zero + mask-col l MMA)
// ---------------------------------------------------------------------------
#define KSB 9216                         // 64*72*2 bytes per stage
#define ATT_QB (128 * 72 * 2)
#define PDH_OFF (ATT_QB + 4 * KSB)       // 2 stages x 128 B
#define ATT_SMEM (PDH_OFF + 2 * 128)

__global__ __launch_bounds__(256, 2)
void attn_mma(const __half* __restrict__ Qg, const __half* __restrict__ Kg,
              const __half* __restrict__ Vg, const __half* __restrict__ padh,
              __half* __restrict__ Og) {
    extern __shared__ char smc[];
    __half* Qs = (__half*)smc;
    const uint32_t base = smem_u32(smc);
    const uint32_t ks_u = base + ATT_QB;
    const uint32_t vs_u = base + ATT_QB + 2 * KSB;
    const uint32_t pd_u = base + PDH_OFF;

    const int l = blockIdx.x;
    const int s_ = (l < 148) ? l : ((l < 296) ? (443 - l) : l);
    const int qt = 4 - (s_ >> 6);
    const int rem = s_ & 63;
    const int h = rem >> 3, b = rem & 7;

    const int tid = threadIdx.x, lane = tid & 31, w = tid >> 5;
    const int g = lane >> 2, t4 = lane & 3;
    const int lt = lane >> 3, lr8 = lane & 7;
    const int qbase = qt * 128;
    const int nkt = min(2 * qt + 26, 33);
    const int rl0 = 16 * w + g, rl1 = rl0 + 8;

    auto issue = [&](int kt, int s) {
        if (kt >= nkt) return;
        const int kb = kt * 64;
        const __half* Kb = Kg + (size_t)(b * L_TOT + kb) * D_ + h * HD_;
        const __half* Vb = Vg + (size_t)(b * L_TOT + kb) * D_ + h * HD_;
#pragma unroll
        for (int p = 0; p < 2; ++p) {
            int idx = tid + p * 256;
            int j = idx >> 3, c8 = (idx & 7) * 8;
            cp16(ks_u + (uint32_t)(s * KSB) + (uint32_t)(j * 72 + c8) * 2, Kb + (size_t)j * D_ + c8);
            cp16(vs_u + (uint32_t)(s * KSB) + (uint32_t)(j * 72 + c8) * 2, Vb + (size_t)j * D_ + c8);
        }
        if (kt < 32 && tid < 8)
            cp16(pd_u + (uint32_t)(s * 128 + tid * 16), padh + b * L_S_ + kb + tid * 8);
    };

    issue(0, 0); CP_COMMIT();

#pragma unroll
    for (int p = 0; p < 4; ++p) {
        int idx = tid + p * 256;
        int row = idx >> 3, c8 = (idx & 7) * 8;
        *(uint4*)&Qs[row * 72 + c8] =
            *(const uint4*)(Qg + (size_t)(b * LQPAD + qbase + row) * D_ + h * HD_ + c8);
    }
    __syncthreads();

    uint32_t qa[4][4];
#pragma unroll
    for (int kc = 0; kc < 4; ++kc) {
        qa[kc][0] = *(const uint32_t*)&Qs[rl0 * 72 + kc * 16 + 2 * t4];
        qa[kc][1] = *(const uint32_t*)&Qs[rl1 * 72 + kc * 16 + 2 * t4];
        qa[kc][2] = *(const uint32_t*)&Qs[rl0 * 72 + kc * 16 + 2 * t4 + 8];
        qa[kc][3] = *(const uint32_t*)&Qs[rl1 * 72 + kc * 16 + 2 * t4 + 8];
    }

    float4 oacc[8];
#pragma unroll
    for (int i = 0; i < 8; ++i) oacc[i] = make_float4(0.f, 0.f, 0.f, 0.f);
    float4 lacc = make_float4(0.f, 0.f, 0.f, 0.f);

#pragma unroll 1
    for (int kt = 0; kt < nkt; ++kt) {
        const int s = kt & 1;
        __syncthreads();
        issue(kt + 1, s ^ 1);
        CP_COMMIT();
        CP_WAIT1();

        const uint32_t ksb = ks_u + (uint32_t)(s * KSB);
        const uint32_t vsb = vs_u + (uint32_t)(s * KSB);
        const __half* ph = (const __half*)(smc + PDH_OFF + s * 128);

        float4 sacc[8];
#pragma unroll
        for (int nt = 0; nt < 8; ++nt) sacc[nt] = make_float4(0.f, 0.f, 0.f, 0.f);
#pragma unroll
        for (int kc = 0; kc < 4; ++kc) {
#pragma unroll
            for (int ntp = 0; ntp < 4; ++ntp) {
                uint32_t b0, b1, b2, b3;
                uint32_t addr = ksb +
                    (uint32_t)(((ntp * 16 + (lt >> 1) * 8 + lr8) * 72) + kc * 16 + (lt & 1) * 8) * 2;
                ldsm4(b0, b1, b2, b3, addr);
                mma16(sacc[2 * ntp], qa[kc], b0, b1);
                mma16(sacc[2 * ntp + 1], qa[kc], b2, b3);
            }
        }

        const int moff = kt * 64 - qbase - 1536;
        if (moff > -64) {
#pragma unroll
            for (int nt = 0; nt < 8; ++nt) {
                int j0 = nt * 8 + 2 * t4, j1 = j0 + 1;
                if (j0 + moff > rl0) sacc[nt].x = -1e30f;
                if (j1 + moff > rl0) sacc[nt].y = -1e30f;
                if (j0 + moff > rl1) sacc[nt].z = -1e30f;
                if (j1 + moff > rl1) sacc[nt].w = -1e30f;
            }
        }

        const bool dopad = (kt < 32);
#pragma unroll
        for (int jc = 0; jc < 4; ++jc) {
            uint32_t pa[4];
            pa[0] = h2exp2(packh2(sacc[2 * jc].x, sacc[2 * jc].y));
            pa[1] = h2exp2(packh2(sacc[2 * jc].z, sacc[2 * jc].w));
            pa[2] = h2exp2(packh2(sacc[2 * jc + 1].x, sacc[2 * jc + 1].y));
            pa[3] = h2exp2(packh2(sacc[2 * jc + 1].z, sacc[2 * jc + 1].w));
            uint32_t m0c = 0, m1c = 0;
            if (lane < 4) {
                if (dopad) {
                    m0c = *(const uint32_t*)&ph[jc * 16 + 2 * lane];
                    m1c = *(const uint32_t*)&ph[jc * 16 + 2 * lane + 8];
                } else {
                    m0c = 0x3C003C00u; m1c = 0x3C003C00u;
                }
            }
            mma16(lacc, pa, m0c, m1c);
#pragma unroll
            for (int dtp = 0; dtp < 4; ++dtp) {
                uint32_t v0, v1, v2, v3;
                uint32_t addr = vsb +
                    (uint32_t)(((jc * 16 + (lt & 1) * 8 + lr8) * 72) + (dtp * 2 + (lt >> 1)) * 8) * 2;
                ldsm4t(v0, v1, v2, v3, addr);
                mma16(oacc[2 * dtp], pa, v0, v1);
                mma16(oacc[2 * dtp + 1], pa, v2, v3);
            }
        }
    }

    float l0 = __shfl_sync(0xffffffffu, lacc.x, lane & 28);
    float l1 = __shfl_sync(0xffffffffu, lacc.z, lane & 28);

    // Epilogue: normalize, store fp16 (feeds fp16 out-proj)
    float il0 = 1.f / l0, il1 = 1.f / l1;
#pragma unroll
    for (int dt = 0; dt < 8; ++dt) {
        int col = h * HD_ + dt * 8 + 2 * t4;
        size_t r0 = (size_t)(b * LQPAD + qbase + rl0) * D_ + col;
        size_t r1 = (size_t)(b * LQPAD + qbase + rl1) * D_ + col;
        *(__half2*)(Og + r0) = __floats2half2_rn(oacc[dt].x * il0, oacc[dt].y * il0);
        *(__half2*)(Og + r1) = __floats2half2_rn(oacc[dt].z * il1, oacc[dt].w * il1);
    }
}

// ---------------------------------------------------------------------------
extern "C" void kernel_launch(void* const* d_in, const int* in_sizes, int n_in,
                              void* d_out, int out_size) {
    const float* x     = (const float*)d_in[0];
    const int*   pad   = (const int*)d_in[1];
    const float* wq_sw = (const float*)d_in[4];
    const float* wq_sb = (const float*)d_in[5];
    const float* wq_nw = (const float*)d_in[6];
    const float* wq_nb = (const float*)d_in[7];
    const float* wk_sw = (const float*)d_in[8];
    const float* wk_sb = (const float*)d_in[9];
    const float* wk_nw = (const float*)d_in[10];
    const float* wk_nb = (const float*)d_in[11];
    const float* wv_sw = (const float*)d_in[12];
    const float* wv_sb = (const float*)d_in[13];
    const float* wv_nw = (const float*)d_in[14];
    const float* wv_nb = (const float*)d_in[15];
    const float* out_w = (const float*)d_in[16];
    const float* out_b = (const float*)d_in[17];
    float* out = (float*)d_out;

    __half *Kp, *Vp, *Qp, *Ap, *Xh, *Wh, *Ph;
    float *Pp;
    cudaGetSymbolAddress((void**)&Kp, g_K);
    cudaGetSymbolAddress((void**)&Vp, g_V);
    cudaGetSymbolAddress((void**)&Qp, g_Q);
    cudaGetSymbolAddress((void**)&Ap, g_A);
    cudaGetSymbolAddress((void**)&Pp, g_Part);
    cudaGetSymbolAddress((void**)&Xh, g_Xh);
    cudaGetSymbolAddress((void**)&Wh, g_Wh);
    cudaGetSymbolAddress((void**)&Ph, g_PadH);

    cudaFuncSetAttribute((const void*)mega_proj, cudaFuncAttributeMaxDynamicSharedMemorySize, PJ_SMEM);
    cudaFuncSetAttribute((const void*)proj_out, cudaFuncAttributeMaxDynamicSharedMemorySize, PJ_SMEM);
    cudaFuncSetAttribute((const void*)attn_mma, cudaFuncAttributeMaxDynamicSharedMemorySize, ATT_SMEM);

    // Prep: x + 4 weights -> fp16, pad -> fp16
    prep_all<<<8448 + 1024 + 8, 256>>>(x, wk_sw, wv_sw, wq_sw, out_w, pad, Xh, Wh, Ph);

    // Fused projection phase (fp16 GEMMs + fp32 ns GEMV)
    mega_proj<<<1536, 256, PJ_SMEM>>>(Xh, x, Wh, wk_sb, wv_sb, wq_sb,
                                      wk_nw, wv_nw, wq_nw, pad, Kp, Vp, Qp, Pp);
    ns_reduce_all<<<dim3(64, 3), 512>>>(Pp, wk_nb, wv_nb, wq_nb, Kp, Vp, Qp);

    // Attention
    attn_mma<<<320, 256, ATT_SMEM>>>(Qp, Kp, Vp, Ph, Ap);

    // Output projection (fp16)
    proj_out<<<dim3(36, 4), 256, PJ_SMEM>>>(Ap, Wh + 3 * WSZ, out_b, out);
}